// round 11
// baseline (speedup 1.0000x reference)
#include <cuda_runtime.h>
#include <cuda_bf16.h>
#include <cuda_fp16.h>
#include <cstdint>

#define Bz 8
#define Cc 512
#define Nn 1024

// ---------------- device scratch (no allocations allowed) --------------------
__device__ float g_yf[Bz*Cc*Nn];               // conv output [B,C,N]
// bf16 operand buffers
__device__ __nv_bfloat16 g_xbf [Bz*Nn*Cc];     // x^T  [b,n,512]
__device__ __nv_bfloat16 g_ynbf[Bz*Nn*Cc];     // yn^T [b,n,512]
__device__ __nv_bfloat16 g_qwb [Cc*Cc];        // 0.125*q_w  [co,512]
__device__ __nv_bfloat16 g_kvwb[2*Cc*Cc];      // kv_w [co,512]
__device__ __nv_bfloat16 g_pwb [Cc*Cc];        // proj_w [co,512]
__device__ __nv_bfloat16 g_qbf [Bz*Nn*Cc];     // q  [b,n,512]
__device__ __nv_bfloat16 g_kbf [Bz*Nn*Cc];     // k  [b,n,512]
__device__ __nv_bfloat16 g_vbf [Bz*Nn*Cc];     // v  [b,n,512]
__device__ __nv_bfloat16 g_obf [Bz*Nn*Cc];     // attn out [b,n,512]
__device__ __nv_bfloat16 g_vthi[(size_t)64*64*1024];   // v^T [z,d,m]
__device__ __nv_bfloat16 g_chi [(size_t)64*1024*1024]; // coeff [z,n,m]

// =================== warp-MMA helpers (plain sm_103-safe PTX) ================
__device__ __forceinline__ uint32_t smem_u32(const void* p) {
    uint32_t a;
    asm("{ .reg .u64 t; cvta.to.shared.u64 t, %1; cvt.u32.u64 %0, t; }"
        : "=r"(a) : "l"(p));
    return a;
}
__device__ __forceinline__ void ldsm_x4(uint32_t& r0, uint32_t& r1, uint32_t& r2,
                                        uint32_t& r3, uint32_t addr) {
    asm volatile("ldmatrix.sync.aligned.m8n8.x4.shared.b16 {%0,%1,%2,%3}, [%4];"
                 : "=r"(r0), "=r"(r1), "=r"(r2), "=r"(r3) : "r"(addr));
}
__device__ __forceinline__ void ldsm_x2(uint32_t& r0, uint32_t& r1, uint32_t addr) {
    asm volatile("ldmatrix.sync.aligned.m8n8.x2.shared.b16 {%0,%1}, [%2];"
                 : "=r"(r0), "=r"(r1) : "r"(addr));
}
__device__ __forceinline__ void mma_bf16(float* c, const uint32_t* a, const uint32_t* b) {
    asm volatile("mma.sync.aligned.m16n8k16.row.col.f32.bf16.bf16.f32 "
                 "{%0,%1,%2,%3}, {%4,%5,%6,%7}, {%8,%9}, {%0,%1,%2,%3};"
                 : "+f"(c[0]), "+f"(c[1]), "+f"(c[2]), "+f"(c[3])
                 : "r"(a[0]), "r"(a[1]), "r"(a[2]), "r"(a[3]), "r"(b[0]), "r"(b[1]));
}
#define CP_ASYNC16(dst, src) \
    asm volatile("cp.async.cg.shared.global [%0], [%1], 16;" :: "r"(dst), "l"(src))
#define CP_COMMIT() asm volatile("cp.async.commit_group;" ::: "memory")
#define CP_WAIT(n)  asm volatile("cp.async.wait_group %0;" :: "n"(n) : "memory")
#define PADB 144   // padded row stride (72 bf16): conflict-free ldmatrix, 16B-mult

// ================= K1: fused conv | weight-convert | x transpose =============
#define K1_SMEM (38*40*4 + 64*4)

__device__ void conv_body(int bc, int t,
                          const float* __restrict__ y,
                          const float* __restrict__ w3, const float* __restrict__ b3,
                          const float* __restrict__ w5, const float* __restrict__ b5,
                          const float* __restrict__ w7, const float* __restrict__ b7)
{
    extern __shared__ __align__(16) char k1sm[];
    float* tile  = (float*)k1sm;            // [38][40]
    float* wsum  = tile + 38*40;            // [49]
    float* biasp = wsum + 49;

    int c = bc & (Cc-1);
    if (t < 49) {
        int dy = t / 7, dx = t % 7;
        float w = w7[c*49 + t];
        if (dy >= 1 && dy <= 5 && dx >= 1 && dx <= 5) w += w5[c*25 + (dy-1)*5 + (dx-1)];
        if (dy >= 2 && dy <= 4 && dx >= 2 && dx <= 4) w += w3[c*9  + (dy-2)*3 + (dx-2)];
        wsum[t] = w;
    }
    if (t == 64) *biasp = b3[c] + b5[c] + b7[c];

    const float* yp = y + (size_t)bc * Nn;
    for (int i = t; i < 38*38; i += 256) {
        int rr = i / 38, cc = i % 38;
        int r = rr - 3, cl = cc - 3;
        float v = 0.f;
        if (r >= 0 && r < 32 && cl >= 0 && cl < 32) v = yp[r*32 + cl];
        tile[rr*40 + cc] = v;
    }
    __syncthreads();

    int r  = t >> 3;
    int cq = (t & 7) * 4;
    float bias = *biasp;
    float a0 = bias, a1 = bias, a2 = bias, a3 = bias;
    #pragma unroll
    for (int dy = 0; dy < 7; dy++) {
        float rv[12];
        const float* rp = &tile[(r+dy)*40 + cq];
        *(float4*)&rv[0] = *(const float4*)rp;
        *(float4*)&rv[4] = *(const float4*)(rp + 4);
        *(float4*)&rv[8] = *(const float4*)(rp + 8);
        #pragma unroll
        for (int dx = 0; dx < 7; dx++) {
            float w = wsum[dy*7 + dx];
            a0 += w*rv[dx];   a1 += w*rv[dx+1];
            a2 += w*rv[dx+2]; a3 += w*rv[dx+3];
        }
    }
    *(float4*)&g_yf[(size_t)bc*Nn + r*32 + cq] = make_float4(a0, a1, a2, a3);
}

__device__ void wcvt_body(int b2, int t,
                          const float* __restrict__ q_w,
                          const float* __restrict__ kv_w,
                          const float* __restrict__ proj_w)
{
    const float* S; __nv_bfloat16* D; float scale; int off;
    if (b2 < 256)      { S = q_w;    D = g_qwb;  scale = 0.125f; off = b2; }
    else if (b2 < 768) { S = kv_w;   D = g_kvwb; scale = 1.f;    off = b2 - 256; }
    else               { S = proj_w; D = g_pwb;  scale = 1.f;    off = b2 - 768; }
    int i4 = off * 256 + t;
    float4 v = *(const float4*)&S[(size_t)i4 * 4];
    __nv_bfloat16 o[4] = {__float2bfloat16(v.x*scale), __float2bfloat16(v.y*scale),
                          __float2bfloat16(v.z*scale), __float2bfloat16(v.w*scale)};
    *(uint2*)&D[(size_t)i4 * 4] = *(uint2*)o;
}

__device__ void tcvt_body(int idx, int t, const float* __restrict__ S,
                          __nv_bfloat16* __restrict__ D)
{
    extern __shared__ __align__(16) char k1sm[];
    float* tile = (float*)k1sm;             // [32][33]
    int n0 = (idx & 31) * 32;
    int c0 = ((idx >> 5) & 15) * 32;
    int b  = idx >> 9;
    int tx = t & 31, ty = t >> 5;
    #pragma unroll
    for (int i = ty; i < 32; i += 8)
        tile[i*33 + tx] = S[((size_t)b*Cc + c0 + i)*Nn + n0 + tx];
    __syncthreads();
    #pragma unroll
    for (int i = ty; i < 32; i += 8)
        D[((size_t)b*Nn + n0 + i)*Cc + c0 + tx] = __float2bfloat16(tile[tx*33 + i]);
}

__global__ void __launch_bounds__(256)
k1_kernel(const float* __restrict__ y,
          const float* __restrict__ w3, const float* __restrict__ b3,
          const float* __restrict__ w5, const float* __restrict__ b5,
          const float* __restrict__ w7, const float* __restrict__ b7,
          const float* __restrict__ x,
          const float* __restrict__ q_w, const float* __restrict__ kv_w,
          const float* __restrict__ proj_w)
{
    int blk = blockIdx.x, t = threadIdx.x;
    if (blk < 4096)       conv_body(blk, t, y, w3, b3, w5, b5, w7, b7);
    else if (blk < 5120)  wcvt_body(blk - 4096, t, q_w, kv_w, proj_w);
    else                  tcvt_body(blk - 5120, t, x, g_xbf);
}

// ------ kernel 2: layernorm over C per (b,n), writes yn^T bf16 directly ------
__global__ void __launch_bounds__(256) ln_kernel(const float* __restrict__ lnw,
                                                 const float* __restrict__ lnb)
{
    __shared__ __nv_bfloat16 tile[32*516];   // [n 32][c 512+4 pad]
    __shared__ float sh[2][8][32];

    int b    = blockIdx.x >> 5;
    int n0   = (blockIdx.x & 31) * 32;
    int t    = threadIdx.x;
    int lane = t & 31;
    int g    = t >> 5;
    int n    = n0 + lane;

    const float* base = g_yf + (size_t)b*Cc*Nn + n;
    float s = 0.f, s2 = 0.f;
    for (int c = g; c < Cc; c += 8) {
        float v = base[(size_t)c*Nn];
        s += v; s2 += v*v;
    }
    sh[0][g][lane] = s; sh[1][g][lane] = s2;
    __syncthreads();
    if (g == 0) {
        float a = 0.f, a2 = 0.f;
        #pragma unroll
        for (int i = 0; i < 8; i++) { a += sh[0][i][lane]; a2 += sh[1][i][lane]; }
        float mu  = a * (1.f/512.f);
        float var = a2 * (1.f/512.f) - mu*mu;
        sh[0][0][lane] = mu;
        sh[1][0][lane] = rsqrtf(var + 1e-5f);
    }
    __syncthreads();
    float mu = sh[0][0][lane], rs = sh[1][0][lane];
    for (int c = g; c < Cc; c += 8) {
        float v = base[(size_t)c*Nn];
        tile[lane*516 + c] = __float2bfloat16((v - mu) * rs * lnw[c] + lnb[c]);
    }
    __syncthreads();
    // coalesced write-out: 32 rows x 512 bf16 (256 words each)
    for (int i = t; i < 32*256; i += 256) {
        int row = i >> 8, w = i & 255;
        uint32_t val = *(const uint32_t*)&tile[row*516 + w*2];
        *(uint32_t*)&g_ynbf[((size_t)(b*Nn + n0 + row))*Cc + w*2] = val;
    }
}

// ------- kernels 3/4: bf16 mma projection GEMM, double-buffered cp.async -----
#define GM_SMEM (4*128*PADB)
__global__ void __launch_bounds__(256, 2)
gemm_mma_kernel(const __nv_bfloat16* __restrict__ A, const __nv_bfloat16* __restrict__ W,
                __nv_bfloat16* __restrict__ D0, __nv_bfloat16* __restrict__ D1)
{
    extern __shared__ __align__(16) char sm[];
    uint32_t sb = smem_u32(sm);

    int t = threadIdx.x, warp = t >> 5, lane = t & 31;
    int co0 = blockIdx.x * 128, n0 = blockIdx.y * 128, b = blockIdx.z;
    int wn = warp >> 2, wm = warp & 3;

    const char* asrc = (const char*)(A + ((size_t)(b*Nn + n0))*Cc);
    const char* wsrc = (const char*)(W + (size_t)co0*Cc);

    auto issue = [&](int kc, int bi) {
        uint32_t base = sb + bi*(2*128*PADB);
        for (int i = t; i < 1024; i += 256) {
            int row = i >> 3, cb = (i & 7) * 16;
            CP_ASYNC16(base + row*PADB + cb, asrc + (size_t)row*1024 + kc*2 + cb);
            CP_ASYNC16(base + 128*PADB + row*PADB + cb, wsrc + (size_t)row*1024 + kc*2 + cb);
        }
        CP_COMMIT();
    };
    issue(0, 0);

    float acc[4][4][4] = {};
    int lr16 = lane & 15, lh = lane >> 4;
    int l8 = lane & 7,  lq = (lane & 15) >> 3;

    for (int c8 = 0; c8 < 8; c8++) {
        if (c8 < 7) { issue((c8+1)*64, (c8+1)&1); CP_WAIT(1); }
        else        { CP_WAIT(0); }
        __syncthreads();
        uint32_t base = sb + (c8&1)*(2*128*PADB);
        uint32_t aAddr = base + (wn*64 + lr16)*PADB + lh*16;
        uint32_t bAddr = base + 128*PADB + (wm*32 + l8)*PADB + lq*16;
        #pragma unroll
        for (int k0 = 0; k0 < 64; k0 += 16) {
            uint32_t a[4][4], bb[4][2];
            #pragma unroll
            for (int mi = 0; mi < 4; mi++)
                ldsm_x4(a[mi][0], a[mi][1], a[mi][2], a[mi][3],
                        aAddr + mi*16*PADB + k0*2);
            #pragma unroll
            for (int ni = 0; ni < 4; ni++)
                ldsm_x2(bb[ni][0], bb[ni][1], bAddr + ni*8*PADB + k0*2);
            #pragma unroll
            for (int mi = 0; mi < 4; mi++)
                #pragma unroll
                for (int ni = 0; ni < 4; ni++)
                    mma_bf16(acc[mi][ni], a[mi], bb[ni]);
        }
        __syncthreads();
    }

    __nv_bfloat16* D = (co0 < Cc) ? D0 : D1;
    int cadj = (co0 < Cc) ? 0 : Cc;
    int rbase = n0 + wn*64 + (lane >> 2);
    int cbase = co0 - cadj + wm*32 + (lane & 3)*2;
    #pragma unroll
    for (int mi = 0; mi < 4; mi++)
        #pragma unroll
        for (int ni = 0; ni < 4; ni++) {
            float* c = acc[mi][ni];
            size_t r0i = ((size_t)(b*Nn) + rbase + mi*16)*Cc + cbase + ni*8;
            __nv_bfloat162 p0, p1;
            p0.x = __float2bfloat16(c[0]); p0.y = __float2bfloat16(c[1]);
            p1.x = __float2bfloat16(c[2]); p1.y = __float2bfloat16(c[3]);
            *(__nv_bfloat162*)&D[r0i]        = p0;
            *(__nv_bfloat162*)&D[r0i + 8*Cc] = p1;
        }
}

// ---------- v (bf16) -> transposed bf16 [z][d][m], flat grid 4096 -------------
__global__ void __launch_bounds__(256) vt_kernel()
{
    __shared__ __nv_bfloat16 tile[32*33];
    int f = blockIdx.x;
    int d0 = (f & 1) * 32, m0 = ((f >> 1) & 31) * 32, z = f >> 6;
    int b = z >> 3, h = z & 7;
    int t = threadIdx.x, tx = t & 31, ty = t >> 5;
    #pragma unroll
    for (int i = ty; i < 32; i += 8)
        tile[i*33 + tx] = g_vbf[((size_t)(b*Nn + m0 + i))*Cc + h*64 + d0 + tx];
    __syncthreads();
    #pragma unroll
    for (int i = ty; i < 32; i += 8)
        g_vthi[((size_t)z*64 + d0 + i)*1024 + m0 + tx] = tile[tx*33 + i];
}

// ====== kernel 5: FUSED QK^T + exact top-k + dual softmax -> coeff ===========
// CTA: 64 q-rows x full m=1024. mma in 8 m-chunks of 128 into smem fp16 logits,
// then per-row 16-bit radix select from smem, coeff written to g_chi.
#define QS_QT 0
#define QS_KT (64*PADB)                       // 9216
#define QS_LG (QS_QT + 64*PADB + 2*128*PADB)  // 46080
#define QS_LROW 2064                          // logits row stride bytes (1032 halves)
#define QS_SMEM (QS_LG + 64*QS_LROW)          // 178176

__device__ __forceinline__ float key2h(unsigned k) {
    unsigned short b = (k & 0x8000u) ? (unsigned short)(k ^ 0x8000u)
                                     : (unsigned short)(~k & 0xFFFFu);
    return __half2float(__ushort_as_half(b));
}

__device__ __forceinline__ unsigned kth_key16(const unsigned* key, int k)
{
    unsigned prefix = 0;
    int kk = k;
    for (int bit = 15; bit >= 0; --bit) {
        unsigned bm = 1u << bit;
        unsigned msk = (bit == 15) ? bm : (((0xFFFFu << (bit+1)) & 0xFFFFu) | bm);
        unsigned want = prefix | bm;
        int c = 0;
        #pragma unroll
        for (int i = 0; i < 32; i++)
            c += ((key[i] & msk) == want) ? 1 : 0;
        c = __reduce_add_sync(0xffffffffu, c);
        if (c == kk) {
            unsigned mn = 0xFFFFu;
            #pragma unroll
            for (int i = 0; i < 32; i++)
                if ((key[i] & msk) == want) mn = min(mn, key[i]);
            return __reduce_min_sync(0xffffffffu, mn);
        } else if (c > kk) {
            prefix |= bm;
        } else {
            kk -= c;
        }
    }
    return prefix;
}

__global__ void __launch_bounds__(256, 1)
qkselect_kernel(const float* __restrict__ kr1, const float* __restrict__ kr2)
{
    extern __shared__ __align__(16) char sm[];
    uint32_t sb = smem_u32(sm);

    int t = threadIdx.x, warp = t >> 5, lane = t & 31;
    int n0 = blockIdx.x * 64, z = blockIdx.y;
    int b = z >> 3, h = z & 7;
    int wn = warp >> 2, wm = warp & 3;        // 2 n-halves x 4 m-quarters

    const char* qs = (const char*)(g_qbf + ((size_t)(b*Nn + n0)*Cc + h*64));
    const char* ks = (const char*)(g_kbf + ((size_t)(b*Nn)*Cc + h*64));

    // group 0: q tile (64 rows x 128B)
    for (int i = t; i < 512; i += 256) {
        int row = i >> 3, cb = (i & 7) * 16;
        CP_ASYNC16(sb + QS_QT + row*PADB + cb, qs + (size_t)row*1024 + cb);
    }
    CP_COMMIT();

    auto issueK = [&](int m0, int bi) {      // 128 k-rows x 128B
        uint32_t base = sb + QS_KT + bi*(128*PADB);
        for (int i = t; i < 1024; i += 256) {
            int row = i >> 3, cb = (i & 7) * 16;
            CP_ASYNC16(base + row*PADB + cb, ks + (size_t)(m0 + row)*1024 + cb);
        }
        CP_COMMIT();
    };
    issueK(0, 0);

    int lr16 = lane & 15, lh = lane >> 4;
    int l8 = lane & 7,  lq = (lane & 15) >> 3;

    uint32_t afr[4][2][4];                    // [k0i][mi][4], loaded once
    bool afr_loaded = false;

    for (int c8 = 0; c8 < 8; c8++) {
        if (c8 < 7) { issueK((c8+1)*128, (c8+1)&1); CP_WAIT(1); }
        else        { CP_WAIT(0); }
        __syncthreads();

        if (!afr_loaded) {
            uint32_t aAddr = sb + QS_QT + (wn*32 + lr16)*PADB + lh*16;
            #pragma unroll
            for (int k0i = 0; k0i < 4; k0i++)
                #pragma unroll
                for (int mi = 0; mi < 2; mi++)
                    ldsm_x4(afr[k0i][mi][0], afr[k0i][mi][1],
                            afr[k0i][mi][2], afr[k0i][mi][3],
                            aAddr + mi*16*PADB + k0i*32);
            afr_loaded = true;
        }

        float acc[2][4][4] = {};
        uint32_t bAddr = sb + QS_KT + (c8&1)*(128*PADB) + (wm*32 + l8)*PADB + lq*16;
        #pragma unroll
        for (int k0i = 0; k0i < 4; k0i++) {
            uint32_t bb[4][2];
            #pragma unroll
            for (int ni = 0; ni < 4; ni++)
                ldsm_x2(bb[ni][0], bb[ni][1], bAddr + ni*8*PADB + k0i*32);
            #pragma unroll
            for (int mi = 0; mi < 2; mi++)
                #pragma unroll
                for (int ni = 0; ni < 4; ni++)
                    mma_bf16(acc[mi][ni], afr[k0i][mi], bb[ni]);
        }

        // write logits to smem as fp16
        int rl = wn*32 + (lane >> 2);
        int cl = c8*128 + wm*32 + (lane & 3)*2;
        #pragma unroll
        for (int mi = 0; mi < 2; mi++)
            #pragma unroll
            for (int ni = 0; ni < 4; ni++) {
                float* c = acc[mi][ni];
                char* p = sm + QS_LG + (rl + mi*16)*QS_LROW + (cl + ni*8)*2;
                *(__half2*)p                = __floats2half2_rn(c[0], c[1]);
                *(__half2*)(p + 8*QS_LROW)  = __floats2half2_rn(c[2], c[3]);
            }
        __syncthreads();
    }

    // ---- select phase: each warp handles 8 rows ----
    float r1 = kr1[0], r2 = kr2[0];
    int k1 = (int)(1024.f * (1.f/(1.f+expf(-r1)))); k1 = min(max(k1,1),1024);
    int k2 = (int)(1024.f * (1.f/(1.f+expf(-r2)))); k2 = min(max(k2,1),1024);

    for (int rr = 0; rr < 8; rr++) {
        int r = warp*8 + rr;
        const char* rp = sm + QS_LG + r*QS_LROW;

        unsigned key[32];
        #pragma unroll
        for (int i = 0; i < 4; i++) {
            uint4 v = *(const uint4*)(rp + i*512 + lane*16);
            const unsigned short* hh = (const unsigned short*)&v;
            #pragma unroll
            for (int j = 0; j < 8; j++) {
                unsigned bb = hh[j];
                key[i*8 + j] = (bb & 0x8000u) ? ((~bb) & 0xFFFFu) : (bb | 0x8000u);
            }
        }

        unsigned mx = 0;
        #pragma unroll
        for (int i = 0; i < 32; i++) mx = max(mx, key[i]);
        mx = __reduce_max_sync(0xffffffffu, mx);
        float M = key2h(mx);

        unsigned T1 = kth_key16(key, k1);
        unsigned T2 = kth_key16(key, k2);

        float ev[32];
        float s1 = 0.f, s2 = 0.f;
        #pragma unroll
        for (int i = 0; i < 32; i++) {
            ev[i] = __expf(key2h(key[i]) - M);
            if (key[i] >= T1) s1 += ev[i];
            if (key[i] >= T2) s2 += ev[i];
        }
        #pragma unroll
        for (int o = 16; o; o >>= 1) {
            s1 += __shfl_xor_sync(0xffffffffu, s1, o);
            s2 += __shfl_xor_sync(0xffffffffu, s2, o);
        }
        float c1 = 0.6f / s1, c2 = 0.4f / s2;
        __nv_bfloat16* ch = g_chi + ((size_t)z*Nn + n0 + r)*Nn;
        #pragma unroll
        for (int i = 0; i < 4; i++) {
            __nv_bfloat16 ob[8];
            #pragma unroll
            for (int j = 0; j < 8; j++) {
                int e = i*8 + j;
                float w = (key[e] >= T1 ? c1 : 0.f) + (key[e] >= T2 ? c2 : 0.f);
                ob[j] = __float2bfloat16(ev[e] * w);
            }
            *(uint4*)(ch + i*256 + lane*8) = *(const uint4*)ob;
        }
    }
}

// ------- kernel 7: AV via mma.sync bf16, double-buffered, bf16 output --------
#define AV_SMEM (2*(192*PADB))
__global__ void __launch_bounds__(256, 2) av_mma_kernel()
{
    extern __shared__ __align__(16) char sm[];
    uint32_t sb = smem_u32(sm);

    int t = threadIdx.x, warp = t >> 5, lane = t & 31;
    int n0 = blockIdx.x * 128, z = blockIdx.y;
    int b = z >> 3, h = z & 7;
    int wn = warp >> 1, wd = warp & 1;

    const char* ch = (const char*)(g_chi  + ((size_t)z*Nn + n0)*Nn);
    const char* vh = (const char*)(g_vthi + (size_t)z*64*1024);

    auto issue = [&](int m0, int bi) {
        uint32_t base = sb + bi*(192*PADB);
        for (int i = t; i < 1024; i += 256) {
            int row = i >> 3, cb = (i & 7) * 16;
            CP_ASYNC16(base + row*PADB + cb, ch + (size_t)row*2048 + m0*2 + cb);
        }
        for (int i = t; i < 512; i += 256) {
            int row = i >> 3, cb = (i & 7) * 16;
            CP_ASYNC16(base + 128*PADB + row*PADB + cb, vh + (size_t)row*2048 + m0*2 + cb);
        }
        CP_COMMIT();
    };
    issue(0, 0);

    float acc[2][4][4] = {};
    int lr16 = lane & 15, lh = lane >> 4;
    int l8 = lane & 7,  lq = (lane & 15) >> 3;

    for (int c16 = 0; c16 < 16; c16++) {
        if (c16 < 15) { issue((c16+1)*64, (c16+1)&1); CP_WAIT(1); }
        else          { CP_WAIT(0); }
        __syncthreads();
        uint32_t base = sb + (c16&1)*(192*PADB);
        uint32_t aAddr = base + (wn*32 + lr16)*PADB + lh*16;
        uint32_t bAddr = base + 128*PADB + (wd*32 + l8)*PADB + lq*16;
        #pragma unroll
        for (int k0 = 0; k0 < 64; k0 += 16) {
            uint32_t a[2][4], bb[4][2];
            #pragma unroll
            for (int mi = 0; mi < 2; mi++)
                ldsm_x4(a[mi][0], a[mi][1], a[mi][2], a[mi][3],
                        aAddr + mi*16*PADB + k0*2);
            #pragma unroll
            for (int ni = 0; ni < 4; ni++)
                ldsm_x2(bb[ni][0], bb[ni][1], bAddr + ni*8*PADB + k0*2);
            #pragma unroll
            for (int mi = 0; mi < 2; mi++)
                #pragma unroll
                for (int ni = 0; ni < 4; ni++)
                    mma_bf16(acc[mi][ni], a[mi], bb[ni]);
        }
        __syncthreads();
    }

    int rbase = n0 + wn*32 + (lane >> 2);
    int cbase = h*64 + wd*32 + (lane & 3)*2;
    #pragma unroll
    for (int mi = 0; mi < 2; mi++)
        #pragma unroll
        for (int ni = 0; ni < 4; ni++) {
            float* c = acc[mi][ni];
            size_t o0 = ((size_t)(b*Nn) + rbase + mi*16)*Cc + cbase + ni*8;
            __nv_bfloat162 p0, p1;
            p0.x = __float2bfloat16(c[0]); p0.y = __float2bfloat16(c[1]);
            p1.x = __float2bfloat16(c[2]); p1.y = __float2bfloat16(c[3]);
            *(__nv_bfloat162*)&g_obf[o0]        = p0;
            *(__nv_bfloat162*)&g_obf[o0 + 8*Cc] = p1;
        }
}

// ------- kernel 8: proj via mma; out[b,c,n] = W.o + bias + x ------------------
#define PJ_SMEM (4*128*PADB)
__global__ void __launch_bounds__(256, 2)
proj_mma_kernel(const float* __restrict__ bias, const float* __restrict__ x,
                float* __restrict__ OUT)
{
    extern __shared__ __align__(16) char sm[];
    uint32_t sb = smem_u32(sm);

    int t = threadIdx.x, warp = t >> 5, lane = t & 31;
    int c0 = blockIdx.x * 128, n0 = blockIdx.y * 128, b = blockIdx.z;
    int wc = warp >> 2, wnn = warp & 3;

    const char* wsrc = (const char*)(g_pwb + (size_t)c0*Cc);
    const char* osrc = (const char*)(g_obf + ((size_t)(b*Nn + n0))*Cc);

    auto issue = [&](int kc, int bi) {
        uint32_t base = sb + bi*(2*128*PADB);
        for (int i = t; i < 1024; i += 256) {
            int row = i >> 3, cb = (i & 7) * 16;
            CP_ASYNC16(base + row*PADB + cb, wsrc + (size_t)row*1024 + kc*2 + cb);
            CP_ASYNC16(base + 128*PADB + row*PADB + cb, osrc + (size_t)row*1024 + kc*2 + cb);
        }
        CP_COMMIT();
    };
    issue(0, 0);

    float acc[4][4][4] = {};
    int lr16 = lane & 15, lh = lane >> 4;
    int l8 = lane & 7,  lq = (lane & 15) >> 3;

    for (int c8 = 0; c8 < 8; c8++) {
        if (c8 < 7) { issue((c8+1)*64, (c8+1)&1); CP_WAIT(1); }
        else        { CP_WAIT(0); }
        __syncthreads();
        uint32_t base = sb + (c8&1)*(2*128*PADB);
        uint32_t aAddr = base + (wc*64 + lr16)*PADB + lh*16;
        uint32_t bAddr = base + 128*PADB + (wnn*32 + l8)*PADB + lq*16;
        #pragma unroll
        for (int k0 = 0; k0 < 64; k0 += 16) {
            uint32_t a[4][4], bb[4][2];
            #pragma unroll
            for (int mi = 0; mi < 4; mi++)
                ldsm_x4(a[mi][0], a[mi][1], a[mi][2], a[mi][3],
                        aAddr + mi*16*PADB + k0*2);
            #pragma unroll
            for (int ni = 0; ni < 4; ni++)
                ldsm_x2(bb[ni][0], bb[ni][1], bAddr + ni*8*PADB + k0*2);
            #pragma unroll
            for (int mi = 0; mi < 4; mi++)
                #pragma unroll
                for (int ni = 0; ni < 4; ni++)
                    mma_bf16(acc[mi][ni], a[mi], bb[ni]);
        }
        __syncthreads();
    }

    int cb0 = c0 + wc*64 + (lane >> 2);
    int nb0 = n0 + wnn*32 + (lane & 3)*2;
    #pragma unroll
    for (int mi = 0; mi < 4; mi++) {
        int c = cb0 + mi*16;
        float bs0 = bias[c], bs8 = bias[c + 8];
        #pragma unroll
        for (int ni = 0; ni < 4; ni++) {
            float* a = acc[mi][ni];
            int n = nb0 + ni*8;
            size_t i0 = ((size_t)b*Cc + c)*Nn + n;
            float2 x0 = *(const float2*)&x[i0];
            *(float2*)&OUT[i0] = make_float2(a[0] + bs0 + x0.x, a[1] + bs0 + x0.y);
            size_t i8 = i0 + (size_t)8*Nn;
            float2 x8 = *(const float2*)&x[i8];
            *(float2*)&OUT[i8] = make_float2(a[2] + bs8 + x8.x, a[3] + bs8 + x8.y);
        }
    }
}

// -----------------------------------------------------------------------------
extern "C" void kernel_launch(void* const* d_in, const int* in_sizes, int n_in,
                              void* d_out, int out_size)
{
    const float* x       = (const float*)d_in[0];
    const float* y       = (const float*)d_in[1];
    const float* q_w     = (const float*)d_in[2];
    const float* kv_w    = (const float*)d_in[3];
    const float* proj_w  = (const float*)d_in[4];
    const float* proj_b  = (const float*)d_in[5];
    const float* conv1_w = (const float*)d_in[6];
    const float* conv1_b = (const float*)d_in[7];
    const float* conv2_w = (const float*)d_in[8];
    const float* conv2_b = (const float*)d_in[9];
    const float* conv3_w = (const float*)d_in[10];
    const float* conv3_b = (const float*)d_in[11];
    const float* ln_w    = (const float*)d_in[12];
    const float* ln_b    = (const float*)d_in[13];
    const float* kr1     = (const float*)d_in[14];
    const float* kr2     = (const float*)d_in[15];
    float* out = (float*)d_out;

    __nv_bfloat16 *xbf, *ynbf, *qwb, *kvwb, *qbf, *kbf, *vbf;
    cudaGetSymbolAddress((void**)&xbf,  g_xbf);
    cudaGetSymbolAddress((void**)&ynbf, g_ynbf);
    cudaGetSymbolAddress((void**)&qwb,  g_qwb);
    cudaGetSymbolAddress((void**)&kvwb, g_kvwb);
    cudaGetSymbolAddress((void**)&qbf,  g_qbf);
    cudaGetSymbolAddress((void**)&kbf,  g_kbf);
    cudaGetSymbolAddress((void**)&vbf,  g_vbf);

    cudaFuncSetAttribute(gemm_mma_kernel, cudaFuncAttributeMaxDynamicSharedMemorySize, GM_SMEM);
    cudaFuncSetAttribute(qkselect_kernel, cudaFuncAttributeMaxDynamicSharedMemorySize, QS_SMEM);
    cudaFuncSetAttribute(av_mma_kernel,   cudaFuncAttributeMaxDynamicSharedMemorySize, AV_SMEM);
    cudaFuncSetAttribute(proj_mma_kernel, cudaFuncAttributeMaxDynamicSharedMemorySize, PJ_SMEM);

    // K1: conv | weight-cvt | x transpose-cvt (all independent)
    k1_kernel<<<4096 + 1024 + 4096, 256, K1_SMEM>>>(
        y, conv1_w, conv1_b, conv2_w, conv2_b, conv3_w, conv3_b,
        x, q_w, kv_w, proj_w);

    ln_kernel<<<Bz*32, 256>>>(ln_w, ln_b);

    gemm_mma_kernel<<<dim3(4, 8, Bz), 256, GM_SMEM>>>(xbf, qwb, qbf, qbf);
    gemm_mma_kernel<<<dim3(8, 8, Bz), 256, GM_SMEM>>>(ynbf, kvwb, kbf, vbf);

    vt_kernel<<<4096, 256>>>();

    qkselect_kernel<<<dim3(16, 64), 256, QS_SMEM>>>(kr1, kr2);

    av_mma_kernel<<<dim3(Nn/128, Bz*8), 256, AV_SMEM>>>();
    proj_mma_kernel<<<dim3(Cc/128, Nn/128, Bz), 256, PJ_SMEM>>>(proj_b, x, out);
}

// round 12
// speedup vs baseline: 1.1073x; 1.1073x over previous
#include <cuda_runtime.h>
#include <cuda_bf16.h>
#include <cuda_fp16.h>
#include <cstdint>

#define Bz 8
#define Cc 512
#define Nn 1024

// ---------------- device scratch (no allocations allowed) --------------------
__device__ float g_yf[Bz*Cc*Nn];               // conv output [B,C,N]
__device__ __half g_attnh[(size_t)64*1024*1024]; // attn [64 z][1024 n][1024 m] fp16
// bf16 operand buffers
__device__ __nv_bfloat16 g_xbf [Bz*Nn*Cc];     // x^T  [b,n,512]
__device__ __nv_bfloat16 g_ynbf[Bz*Nn*Cc];     // yn^T [b,n,512]
__device__ __nv_bfloat16 g_qwb [Cc*Cc];        // 0.125*q_w  [co,512]
__device__ __nv_bfloat16 g_kvwb[2*Cc*Cc];      // kv_w [co,512]
__device__ __nv_bfloat16 g_pwb [Cc*Cc];        // proj_w [co,512]
__device__ __nv_bfloat16 g_qbf [Bz*Nn*Cc];     // q  [b,n,512]
__device__ __nv_bfloat16 g_kbf [Bz*Nn*Cc];     // k  [b,n,512]
__device__ __nv_bfloat16 g_vbf [Bz*Nn*Cc];     // v  [b,n,512]
__device__ __nv_bfloat16 g_obf [Bz*Nn*Cc];     // attn out [b,n,512]
__device__ __nv_bfloat16 g_vthi[(size_t)64*64*1024];   // v^T [z,d,m]
__device__ __nv_bfloat16 g_chi [(size_t)64*1024*1024]; // coeff [z,n,m]

// =================== warp-MMA helpers (plain sm_103-safe PTX) ================
__device__ __forceinline__ uint32_t smem_u32(const void* p) {
    uint32_t a;
    asm("{ .reg .u64 t; cvta.to.shared.u64 t, %1; cvt.u32.u64 %0, t; }"
        : "=r"(a) : "l"(p));
    return a;
}
__device__ __forceinline__ void ldsm_x4(uint32_t& r0, uint32_t& r1, uint32_t& r2,
                                        uint32_t& r3, uint32_t addr) {
    asm volatile("ldmatrix.sync.aligned.m8n8.x4.shared.b16 {%0,%1,%2,%3}, [%4];"
                 : "=r"(r0), "=r"(r1), "=r"(r2), "=r"(r3) : "r"(addr));
}
__device__ __forceinline__ void ldsm_x2(uint32_t& r0, uint32_t& r1, uint32_t addr) {
    asm volatile("ldmatrix.sync.aligned.m8n8.x2.shared.b16 {%0,%1}, [%2];"
                 : "=r"(r0), "=r"(r1) : "r"(addr));
}
__device__ __forceinline__ void mma_bf16(float* c, const uint32_t* a, const uint32_t* b) {
    asm volatile("mma.sync.aligned.m16n8k16.row.col.f32.bf16.bf16.f32 "
                 "{%0,%1,%2,%3}, {%4,%5,%6,%7}, {%8,%9}, {%0,%1,%2,%3};"
                 : "+f"(c[0]), "+f"(c[1]), "+f"(c[2]), "+f"(c[3])
                 : "r"(a[0]), "r"(a[1]), "r"(a[2]), "r"(a[3]), "r"(b[0]), "r"(b[1]));
}
#define CP_ASYNC16(dst, src) \
    asm volatile("cp.async.cg.shared.global [%0], [%1], 16;" :: "r"(dst), "l"(src))
#define CP_COMMIT() asm volatile("cp.async.commit_group;" ::: "memory")
#define CP_WAIT(n)  asm volatile("cp.async.wait_group %0;" :: "n"(n) : "memory")
#define PADB 144   // padded row stride (72 bf16): conflict-free ldmatrix, 16B-mult

// ================= K1: fused conv | weight-convert | x transpose =============
#define K1_SMEM (38*40*4 + 64*4)

__device__ void conv_body(int bc, int t,
                          const float* __restrict__ y,
                          const float* __restrict__ w3, const float* __restrict__ b3,
                          const float* __restrict__ w5, const float* __restrict__ b5,
                          const float* __restrict__ w7, const float* __restrict__ b7)
{
    extern __shared__ __align__(16) char k1sm[];
    float* tile  = (float*)k1sm;            // [38][40]
    float* wsum  = tile + 38*40;            // [49]
    float* biasp = wsum + 49;

    int c = bc & (Cc-1);
    if (t < 49) {
        int dy = t / 7, dx = t % 7;
        float w = w7[c*49 + t];
        if (dy >= 1 && dy <= 5 && dx >= 1 && dx <= 5) w += w5[c*25 + (dy-1)*5 + (dx-1)];
        if (dy >= 2 && dy <= 4 && dx >= 2 && dx <= 4) w += w3[c*9  + (dy-2)*3 + (dx-2)];
        wsum[t] = w;
    }
    if (t == 64) *biasp = b3[c] + b5[c] + b7[c];

    const float* yp = y + (size_t)bc * Nn;
    for (int i = t; i < 38*38; i += 256) {
        int rr = i / 38, cc = i % 38;
        int r = rr - 3, cl = cc - 3;
        float v = 0.f;
        if (r >= 0 && r < 32 && cl >= 0 && cl < 32) v = yp[r*32 + cl];
        tile[rr*40 + cc] = v;
    }
    __syncthreads();

    int r  = t >> 3;
    int cq = (t & 7) * 4;
    float bias = *biasp;
    float a0 = bias, a1 = bias, a2 = bias, a3 = bias;
    #pragma unroll
    for (int dy = 0; dy < 7; dy++) {
        float rv[12];
        const float* rp = &tile[(r+dy)*40 + cq];
        *(float4*)&rv[0] = *(const float4*)rp;
        *(float4*)&rv[4] = *(const float4*)(rp + 4);
        *(float4*)&rv[8] = *(const float4*)(rp + 8);
        #pragma unroll
        for (int dx = 0; dx < 7; dx++) {
            float w = wsum[dy*7 + dx];
            a0 += w*rv[dx];   a1 += w*rv[dx+1];
            a2 += w*rv[dx+2]; a3 += w*rv[dx+3];
        }
    }
    *(float4*)&g_yf[(size_t)bc*Nn + r*32 + cq] = make_float4(a0, a1, a2, a3);
}

__device__ void wcvt_body(int b2, int t,
                          const float* __restrict__ q_w,
                          const float* __restrict__ kv_w,
                          const float* __restrict__ proj_w)
{
    const float* S; __nv_bfloat16* D; float scale; int off;
    if (b2 < 256)      { S = q_w;    D = g_qwb;  scale = 0.125f; off = b2; }
    else if (b2 < 768) { S = kv_w;   D = g_kvwb; scale = 1.f;    off = b2 - 256; }
    else               { S = proj_w; D = g_pwb;  scale = 1.f;    off = b2 - 768; }
    int i4 = off * 256 + t;
    float4 v = *(const float4*)&S[(size_t)i4 * 4];
    __nv_bfloat16 o[4] = {__float2bfloat16(v.x*scale), __float2bfloat16(v.y*scale),
                          __float2bfloat16(v.z*scale), __float2bfloat16(v.w*scale)};
    *(uint2*)&D[(size_t)i4 * 4] = *(uint2*)o;
}

__device__ void tcvt_body(int idx, int t, const float* __restrict__ S,
                          __nv_bfloat16* __restrict__ D)
{
    extern __shared__ __align__(16) char k1sm[];
    float* tile = (float*)k1sm;             // [32][33]
    int n0 = (idx & 31) * 32;
    int c0 = ((idx >> 5) & 15) * 32;
    int b  = idx >> 9;
    int tx = t & 31, ty = t >> 5;
    #pragma unroll
    for (int i = ty; i < 32; i += 8)
        tile[i*33 + tx] = S[((size_t)b*Cc + c0 + i)*Nn + n0 + tx];
    __syncthreads();
    #pragma unroll
    for (int i = ty; i < 32; i += 8)
        D[((size_t)b*Nn + n0 + i)*Cc + c0 + tx] = __float2bfloat16(tile[tx*33 + i]);
}

__global__ void __launch_bounds__(256)
k1_kernel(const float* __restrict__ y,
          const float* __restrict__ w3, const float* __restrict__ b3,
          const float* __restrict__ w5, const float* __restrict__ b5,
          const float* __restrict__ w7, const float* __restrict__ b7,
          const float* __restrict__ x,
          const float* __restrict__ q_w, const float* __restrict__ kv_w,
          const float* __restrict__ proj_w)
{
    int blk = blockIdx.x, t = threadIdx.x;
    if (blk < 4096)       conv_body(blk, t, y, w3, b3, w5, b5, w7, b7);
    else if (blk < 5120)  wcvt_body(blk - 4096, t, q_w, kv_w, proj_w);
    else                  tcvt_body(blk - 5120, t, x, g_xbf);
}

// ------ kernel 2: layernorm over C per (b,n), writes yn^T bf16 directly ------
__global__ void __launch_bounds__(256) ln_kernel(const float* __restrict__ lnw,
                                                 const float* __restrict__ lnb)
{
    __shared__ __nv_bfloat16 tile[32*516];   // [n 32][c 512+4 pad]
    __shared__ float sh[2][8][32];

    int b    = blockIdx.x >> 5;
    int n0   = (blockIdx.x & 31) * 32;
    int t    = threadIdx.x;
    int lane = t & 31;
    int g    = t >> 5;
    int n    = n0 + lane;

    const float* base = g_yf + (size_t)b*Cc*Nn + n;
    float s = 0.f, s2 = 0.f;
    for (int c = g; c < Cc; c += 8) {
        float v = base[(size_t)c*Nn];
        s += v; s2 += v*v;
    }
    sh[0][g][lane] = s; sh[1][g][lane] = s2;
    __syncthreads();
    if (g == 0) {
        float a = 0.f, a2 = 0.f;
        #pragma unroll
        for (int i = 0; i < 8; i++) { a += sh[0][i][lane]; a2 += sh[1][i][lane]; }
        float mu  = a * (1.f/512.f);
        float var = a2 * (1.f/512.f) - mu*mu;
        sh[0][0][lane] = mu;
        sh[1][0][lane] = rsqrtf(var + 1e-5f);
    }
    __syncthreads();
    float mu = sh[0][0][lane], rs = sh[1][0][lane];
    for (int c = g; c < Cc; c += 8) {
        float v = base[(size_t)c*Nn];
        tile[lane*516 + c] = __float2bfloat16((v - mu) * rs * lnw[c] + lnb[c]);
    }
    __syncthreads();
    for (int i = t; i < 32*256; i += 256) {
        int row = i >> 8, w = i & 255;
        uint32_t val = *(const uint32_t*)&tile[row*516 + w*2];
        *(uint32_t*)&g_ynbf[((size_t)(b*Nn + n0 + row))*Cc + w*2] = val;
    }
}

// ------- kernels 3/4: bf16 mma projection GEMM, double-buffered cp.async -----
#define GM_SMEM (4*128*PADB)
__global__ void __launch_bounds__(256, 2)
gemm_mma_kernel(const __nv_bfloat16* __restrict__ A, const __nv_bfloat16* __restrict__ W,
                __nv_bfloat16* __restrict__ D0, __nv_bfloat16* __restrict__ D1)
{
    extern __shared__ __align__(16) char sm[];
    uint32_t sb = smem_u32(sm);

    int t = threadIdx.x, warp = t >> 5, lane = t & 31;
    int co0 = blockIdx.x * 128, n0 = blockIdx.y * 128, b = blockIdx.z;
    int wn = warp >> 2, wm = warp & 3;

    const char* asrc = (const char*)(A + ((size_t)(b*Nn + n0))*Cc);
    const char* wsrc = (const char*)(W + (size_t)co0*Cc);

    auto issue = [&](int kc, int bi) {
        uint32_t base = sb + bi*(2*128*PADB);
        for (int i = t; i < 1024; i += 256) {
            int row = i >> 3, cb = (i & 7) * 16;
            CP_ASYNC16(base + row*PADB + cb, asrc + (size_t)row*1024 + kc*2 + cb);
            CP_ASYNC16(base + 128*PADB + row*PADB + cb, wsrc + (size_t)row*1024 + kc*2 + cb);
        }
        CP_COMMIT();
    };
    issue(0, 0);

    float acc[4][4][4] = {};
    int lr16 = lane & 15, lh = lane >> 4;
    int l8 = lane & 7,  lq = (lane & 15) >> 3;

    for (int c8 = 0; c8 < 8; c8++) {
        if (c8 < 7) { issue((c8+1)*64, (c8+1)&1); CP_WAIT(1); }
        else        { CP_WAIT(0); }
        __syncthreads();
        uint32_t base = sb + (c8&1)*(2*128*PADB);
        uint32_t aAddr = base + (wn*64 + lr16)*PADB + lh*16;
        uint32_t bAddr = base + 128*PADB + (wm*32 + l8)*PADB + lq*16;
        #pragma unroll
        for (int k0 = 0; k0 < 64; k0 += 16) {
            uint32_t a[4][4], bb[4][2];
            #pragma unroll
            for (int mi = 0; mi < 4; mi++)
                ldsm_x4(a[mi][0], a[mi][1], a[mi][2], a[mi][3],
                        aAddr + mi*16*PADB + k0*2);
            #pragma unroll
            for (int ni = 0; ni < 4; ni++)
                ldsm_x2(bb[ni][0], bb[ni][1], bAddr + ni*8*PADB + k0*2);
            #pragma unroll
            for (int mi = 0; mi < 4; mi++)
                #pragma unroll
                for (int ni = 0; ni < 4; ni++)
                    mma_bf16(acc[mi][ni], a[mi], bb[ni]);
        }
        __syncthreads();
    }

    __nv_bfloat16* D = (co0 < Cc) ? D0 : D1;
    int cadj = (co0 < Cc) ? 0 : Cc;
    int rbase = n0 + wn*64 + (lane >> 2);
    int cbase = co0 - cadj + wm*32 + (lane & 3)*2;
    #pragma unroll
    for (int mi = 0; mi < 4; mi++)
        #pragma unroll
        for (int ni = 0; ni < 4; ni++) {
            float* c = acc[mi][ni];
            size_t r0i = ((size_t)(b*Nn) + rbase + mi*16)*Cc + cbase + ni*8;
            __nv_bfloat162 p0, p1;
            p0.x = __float2bfloat16(c[0]); p0.y = __float2bfloat16(c[1]);
            p1.x = __float2bfloat16(c[2]); p1.y = __float2bfloat16(c[3]);
            *(__nv_bfloat162*)&D[r0i]        = p0;
            *(__nv_bfloat162*)&D[r0i + 8*Cc] = p1;
        }
}

// ---------------- kernel 5: QK^T (z<64) fused with v-transpose (z>=64) -------
#define QK_SMEM (2*128*PADB)
__global__ void __launch_bounds__(256, 2) qksplit_kernel()
{
    extern __shared__ __align__(16) char sm[];
    int t = threadIdx.x;

    if (blockIdx.z >= 64) {
        int f = blockIdx.x + blockIdx.y*8 + (blockIdx.z - 64)*64;
        int d0 = (f & 1) * 32, m0 = ((f >> 1) & 31) * 32, z = f >> 6;
        int b = z >> 3, h = z & 7;
        __nv_bfloat16* tile = (__nv_bfloat16*)sm;    // [32][33]
        int tx = t & 31, ty = t >> 5;
        #pragma unroll
        for (int i = ty; i < 32; i += 8)
            tile[i*33 + tx] = g_vbf[((size_t)(b*Nn + m0 + i))*Cc + h*64 + d0 + tx];
        __syncthreads();
        #pragma unroll
        for (int i = ty; i < 32; i += 8)
            g_vthi[((size_t)z*64 + d0 + i)*1024 + m0 + tx] = tile[tx*33 + i];
        return;
    }

    const uint32_t QT = 0, KT = 128*PADB;
    uint32_t sb = smem_u32(sm);
    int warp = t >> 5, lane = t & 31;
    int m0 = blockIdx.x * 128, n0 = blockIdx.y * 128, z = blockIdx.z;
    int b = z >> 3, h = z & 7;
    int wn = warp >> 2, wm = warp & 3;

    {
        const char* srcs[2] = {
            (const char*)(g_qbf + ((size_t)(b*Nn + n0)*Cc + h*64)),
            (const char*)(g_kbf + ((size_t)(b*Nn + m0)*Cc + h*64))};
        const uint32_t offs[2] = {QT, KT};
        #pragma unroll
        for (int tl = 0; tl < 2; tl++) {
            uint32_t dst = sb + offs[tl];
            for (int i = t; i < 1024; i += 256) {
                int row = i >> 3, cb = (i & 7) * 16;
                CP_ASYNC16(dst + row*PADB + cb, srcs[tl] + (size_t)row*(Cc*2) + cb);
            }
        }
        CP_COMMIT();
        CP_WAIT(0);
    }
    __syncthreads();

    float acc[4][4][4] = {};
    int lr16 = lane & 15, lh = lane >> 4;
    int l8 = lane & 7,  lq = (lane & 15) >> 3;

    uint32_t aAddr = sb + QT + (wn*64 + lr16)*PADB + lh*16;
    uint32_t bAddr = sb + KT + (wm*32 + l8)*PADB + lq*16;
    #pragma unroll
    for (int k0 = 0; k0 < 64; k0 += 16) {
        uint32_t a[4][4], bb[4][2];
        #pragma unroll
        for (int mi = 0; mi < 4; mi++)
            ldsm_x4(a[mi][0], a[mi][1], a[mi][2], a[mi][3],
                    aAddr + mi*16*PADB + k0*2);
        #pragma unroll
        for (int ni = 0; ni < 4; ni++)
            ldsm_x2(bb[ni][0], bb[ni][1], bAddr + ni*8*PADB + k0*2);
        #pragma unroll
        for (int mi = 0; mi < 4; mi++)
            #pragma unroll
            for (int ni = 0; ni < 4; ni++)
                mma_bf16(acc[mi][ni], a[mi], bb[ni]);
    }

    int rbase = n0 + wn*64 + (lane >> 2);
    int cbase = m0 + wm*32 + (lane & 3)*2;
    #pragma unroll
    for (int mi = 0; mi < 4; mi++)
        #pragma unroll
        for (int ni = 0; ni < 4; ni++) {
            float* c = acc[mi][ni];
            __half* A = g_attnh + ((size_t)z*Nn + rbase + mi*16)*Nn + cbase + ni*8;
            *(__half2*)&A[0]            = __floats2half2_rn(c[0], c[1]);
            *(__half2*)&A[(size_t)8*Nn] = __floats2half2_rn(c[2], c[3]);
        }
}

// ---------------- kernel 6: exact top-k on 16-bit keys + dual softmax --------
__device__ __forceinline__ float key2h(unsigned k) {
    unsigned short b = (k & 0x8000u) ? (unsigned short)(k ^ 0x8000u)
                                     : (unsigned short)(~k & 0xFFFFu);
    return __half2float(__ushort_as_half(b));
}

__device__ __forceinline__ unsigned kth_key16(const unsigned* key, int k)
{
    unsigned prefix = 0;
    int kk = k;
    for (int bit = 15; bit >= 0; --bit) {
        unsigned bm = 1u << bit;
        unsigned msk = (bit == 15) ? bm : (((0xFFFFu << (bit+1)) & 0xFFFFu) | bm);
        unsigned want = prefix | bm;
        int c = 0;
        #pragma unroll
        for (int i = 0; i < 32; i++)
            c += ((key[i] & msk) == want) ? 1 : 0;
        c = __reduce_add_sync(0xffffffffu, c);
        if (c == kk) {
            unsigned mn = 0xFFFFu;
            #pragma unroll
            for (int i = 0; i < 32; i++)
                if ((key[i] & msk) == want) mn = min(mn, key[i]);
            return __reduce_min_sync(0xffffffffu, mn);
        } else if (c > kk) {
            prefix |= bm;
        } else {
            kk -= c;
        }
    }
    return prefix;
}

__global__ void select_kernel(const float* __restrict__ kr1, const float* __restrict__ kr2)
{
    int row  = blockIdx.x * 8 + (threadIdx.x >> 5);   // z*1024 + n
    int lane = threadIdx.x & 31;

    float r1 = kr1[0], r2 = kr2[0];
    int k1 = (int)(1024.f * (1.f/(1.f+expf(-r1)))); k1 = min(max(k1,1),1024);
    int k2 = (int)(1024.f * (1.f/(1.f+expf(-r2)))); k2 = min(max(k2,1),1024);

    const __half* rp = g_attnh + (size_t)row * Nn;
    unsigned key[32];
    #pragma unroll
    for (int i = 0; i < 4; i++) {
        uint4 v = *(const uint4*)(rp + i*256 + lane*8);
        const unsigned short* hh = (const unsigned short*)&v;
        #pragma unroll
        for (int j = 0; j < 8; j++) {
            unsigned b = hh[j];
            key[i*8 + j] = (b & 0x8000u) ? ((~b) & 0xFFFFu) : (b | 0x8000u);
        }
    }

    unsigned mx = 0;
    #pragma unroll
    for (int i = 0; i < 32; i++) mx = max(mx, key[i]);
    mx = __reduce_max_sync(0xffffffffu, mx);
    float M = key2h(mx);

    unsigned T1 = kth_key16(key, k1);
    unsigned T2 = kth_key16(key, k2);

    float ev[32];
    float s1 = 0.f, s2 = 0.f;
    #pragma unroll
    for (int i = 0; i < 32; i++) {
        ev[i] = __expf(key2h(key[i]) - M);
        if (key[i] >= T1) s1 += ev[i];
        if (key[i] >= T2) s2 += ev[i];
    }
    #pragma unroll
    for (int o = 16; o; o >>= 1) {
        s1 += __shfl_xor_sync(0xffffffffu, s1, o);
        s2 += __shfl_xor_sync(0xffffffffu, s2, o);
    }
    float c1 = 0.6f / s1, c2 = 0.4f / s2;
    __nv_bfloat16* ch = g_chi + (size_t)row * Nn;
    #pragma unroll
    for (int i = 0; i < 4; i++) {
        __nv_bfloat16 ob[8];
        #pragma unroll
        for (int j = 0; j < 8; j++) {
            int e = i*8 + j;
            float w = (key[e] >= T1 ? c1 : 0.f) + (key[e] >= T2 ? c2 : 0.f);
            ob[j] = __float2bfloat16(ev[e] * w);
        }
        *(uint4*)(ch + i*256 + lane*8) = *(const uint4*)ob;
    }
}

// ------- kernel 7: AV via mma.sync bf16, double-buffered, bf16 output --------
#define AV_SMEM (2*(192*PADB))
__global__ void __launch_bounds__(256, 2) av_mma_kernel()
{
    extern __shared__ __align__(16) char sm[];
    uint32_t sb = smem_u32(sm);

    int t = threadIdx.x, warp = t >> 5, lane = t & 31;
    int n0 = blockIdx.x * 128, z = blockIdx.y;
    int b = z >> 3, h = z & 7;
    int wn = warp >> 1, wd = warp & 1;

    const char* ch = (const char*)(g_chi  + ((size_t)z*Nn + n0)*Nn);
    const char* vh = (const char*)(g_vthi + (size_t)z*64*1024);

    auto issue = [&](int m0, int bi) {
        uint32_t base = sb + bi*(192*PADB);
        for (int i = t; i < 1024; i += 256) {
            int row = i >> 3, cb = (i & 7) * 16;
            CP_ASYNC16(base + row*PADB + cb, ch + (size_t)row*2048 + m0*2 + cb);
        }
        for (int i = t; i < 512; i += 256) {
            int row = i >> 3, cb = (i & 7) * 16;
            CP_ASYNC16(base + 128*PADB + row*PADB + cb, vh + (size_t)row*2048 + m0*2 + cb);
        }
        CP_COMMIT();
    };
    issue(0, 0);

    float acc[2][4][4] = {};
    int lr16 = lane & 15, lh = lane >> 4;
    int l8 = lane & 7,  lq = (lane & 15) >> 3;

    for (int c16 = 0; c16 < 16; c16++) {
        if (c16 < 15) { issue((c16+1)*64, (c16+1)&1); CP_WAIT(1); }
        else          { CP_WAIT(0); }
        __syncthreads();
        uint32_t base = sb + (c16&1)*(192*PADB);
        uint32_t aAddr = base + (wn*32 + lr16)*PADB + lh*16;
        uint32_t bAddr = base + 128*PADB + (wd*32 + l8)*PADB + lq*16;
        #pragma unroll
        for (int k0 = 0; k0 < 64; k0 += 16) {
            uint32_t a[2][4], bb[4][2];
            #pragma unroll
            for (int mi = 0; mi < 2; mi++)
                ldsm_x4(a[mi][0], a[mi][1], a[mi][2], a[mi][3],
                        aAddr + mi*16*PADB + k0*2);
            #pragma unroll
            for (int ni = 0; ni < 4; ni++)
                ldsm_x2(bb[ni][0], bb[ni][1], bAddr + ni*8*PADB + k0*2);
            #pragma unroll
            for (int mi = 0; mi < 2; mi++)
                #pragma unroll
                for (int ni = 0; ni < 4; ni++)
                    mma_bf16(acc[mi][ni], a[mi], bb[ni]);
        }
        __syncthreads();
    }

    int rbase = n0 + wn*32 + (lane >> 2);
    int cbase = h*64 + wd*32 + (lane & 3)*2;
    #pragma unroll
    for (int mi = 0; mi < 2; mi++)
        #pragma unroll
        for (int ni = 0; ni < 4; ni++) {
            float* c = acc[mi][ni];
            size_t o0 = ((size_t)(b*Nn) + rbase + mi*16)*Cc + cbase + ni*8;
            __nv_bfloat162 p0, p1;
            p0.x = __float2bfloat16(c[0]); p0.y = __float2bfloat16(c[1]);
            p1.x = __float2bfloat16(c[2]); p1.y = __float2bfloat16(c[3]);
            *(__nv_bfloat162*)&g_obf[o0]        = p0;
            *(__nv_bfloat162*)&g_obf[o0 + 8*Cc] = p1;
        }
}

// ------- kernel 8: proj via mma; out[b,c,n] = W.o + bias + x ------------------
#define PJ_SMEM (4*128*PADB)
__global__ void __launch_bounds__(256, 2)
proj_mma_kernel(const float* __restrict__ bias, const float* __restrict__ x,
                float* __restrict__ OUT)
{
    extern __shared__ __align__(16) char sm[];
    uint32_t sb = smem_u32(sm);

    int t = threadIdx.x, warp = t >> 5, lane = t & 31;
    int c0 = blockIdx.x * 128, n0 = blockIdx.y * 128, b = blockIdx.z;
    int wc = warp >> 2, wnn = warp & 3;

    const char* wsrc = (const char*)(g_pwb + (size_t)c0*Cc);
    const char* osrc = (const char*)(g_obf + ((size_t)(b*Nn + n0))*Cc);

    auto issue = [&](int kc, int bi) {
        uint32_t base = sb + bi*(2*128*PADB);
        for (int i = t; i < 1024; i += 256) {
            int row = i >> 3, cb = (i & 7) * 16;
            CP_ASYNC16(base + row*PADB + cb, wsrc + (size_t)row*1024 + kc*2 + cb);
            CP_ASYNC16(base + 128*PADB + row*PADB + cb, osrc + (size_t)row*1024 + kc*2 + cb);
        }
        CP_COMMIT();
    };
    issue(0, 0);

    float acc[4][4][4] = {};
    int lr16 = lane & 15, lh = lane >> 4;
    int l8 = lane & 7,  lq = (lane & 15) >> 3;

    for (int c8 = 0; c8 < 8; c8++) {
        if (c8 < 7) { issue((c8+1)*64, (c8+1)&1); CP_WAIT(1); }
        else        { CP_WAIT(0); }
        __syncthreads();
        uint32_t base = sb + (c8&1)*(2*128*PADB);
        uint32_t aAddr = base + (wc*64 + lr16)*PADB + lh*16;
        uint32_t bAddr = base + 128*PADB + (wnn*32 + l8)*PADB + lq*16;
        #pragma unroll
        for (int k0 = 0; k0 < 64; k0 += 16) {
            uint32_t a[4][4], bb[4][2];
            #pragma unroll
            for (int mi = 0; mi < 4; mi++)
                ldsm_x4(a[mi][0], a[mi][1], a[mi][2], a[mi][3],
                        aAddr + mi*16*PADB + k0*2);
            #pragma unroll
            for (int ni = 0; ni < 4; ni++)
                ldsm_x2(bb[ni][0], bb[ni][1], bAddr + ni*8*PADB + k0*2);
            #pragma unroll
            for (int mi = 0; mi < 4; mi++)
                #pragma unroll
                for (int ni = 0; ni < 4; ni++)
                    mma_bf16(acc[mi][ni], a[mi], bb[ni]);
        }
        __syncthreads();
    }

    int cb0 = c0 + wc*64 + (lane >> 2);
    int nb0 = n0 + wnn*32 + (lane & 3)*2;
    #pragma unroll
    for (int mi = 0; mi < 4; mi++) {
        int c = cb0 + mi*16;
        float bs0 = bias[c], bs8 = bias[c + 8];
        #pragma unroll
        for (int ni = 0; ni < 4; ni++) {
            float* a = acc[mi][ni];
            int n = nb0 + ni*8;
            size_t i0 = ((size_t)b*Cc + c)*Nn + n;
            float2 x0 = *(const float2*)&x[i0];
            *(float2*)&OUT[i0] = make_float2(a[0] + bs0 + x0.x, a[1] + bs0 + x0.y);
            size_t i8 = i0 + (size_t)8*Nn;
            float2 x8 = *(const float2*)&x[i8];
            *(float2*)&OUT[i8] = make_float2(a[2] + bs8 + x8.x, a[3] + bs8 + x8.y);
        }
    }
}

// -----------------------------------------------------------------------------
extern "C" void kernel_launch(void* const* d_in, const int* in_sizes, int n_in,
                              void* d_out, int out_size)
{
    const float* x       = (const float*)d_in[0];
    const float* y       = (const float*)d_in[1];
    const float* q_w     = (const float*)d_in[2];
    const float* kv_w    = (const float*)d_in[3];
    const float* proj_w  = (const float*)d_in[4];
    const float* proj_b  = (const float*)d_in[5];
    const float* conv1_w = (const float*)d_in[6];
    const float* conv1_b = (const float*)d_in[7];
    const float* conv2_w = (const float*)d_in[8];
    const float* conv2_b = (const float*)d_in[9];
    const float* conv3_w = (const float*)d_in[10];
    const float* conv3_b = (const float*)d_in[11];
    const float* ln_w    = (const float*)d_in[12];
    const float* ln_b    = (const float*)d_in[13];
    const float* kr1     = (const float*)d_in[14];
    const float* kr2     = (const float*)d_in[15];
    float* out = (float*)d_out;

    __nv_bfloat16 *xbf, *ynbf, *qwb, *kvwb, *qbf, *kbf, *vbf;
    cudaGetSymbolAddress((void**)&xbf,  g_xbf);
    cudaGetSymbolAddress((void**)&ynbf, g_ynbf);
    cudaGetSymbolAddress((void**)&qwb,  g_qwb);
    cudaGetSymbolAddress((void**)&kvwb, g_kvwb);
    cudaGetSymbolAddress((void**)&qbf,  g_qbf);
    cudaGetSymbolAddress((void**)&kbf,  g_kbf);
    cudaGetSymbolAddress((void**)&vbf,  g_vbf);

    cudaFuncSetAttribute(gemm_mma_kernel, cudaFuncAttributeMaxDynamicSharedMemorySize, GM_SMEM);
    cudaFuncSetAttribute(qksplit_kernel,  cudaFuncAttributeMaxDynamicSharedMemorySize, QK_SMEM);
    cudaFuncSetAttribute(av_mma_kernel,   cudaFuncAttributeMaxDynamicSharedMemorySize, AV_SMEM);
    cudaFuncSetAttribute(proj_mma_kernel, cudaFuncAttributeMaxDynamicSharedMemorySize, PJ_SMEM);

    // K1: conv | weight-cvt | x transpose-cvt (all independent)
    k1_kernel<<<4096 + 1024 + 4096, 256, K1_SMEM>>>(
        y, conv1_w, conv1_b, conv2_w, conv2_b, conv3_w, conv3_b,
        x, q_w, kv_w, proj_w);

    ln_kernel<<<Bz*32, 256>>>(ln_w, ln_b);

    gemm_mma_kernel<<<dim3(4, 8, Bz), 256, GM_SMEM>>>(xbf, qwb, qbf, qbf);
    gemm_mma_kernel<<<dim3(8, 8, Bz), 256, GM_SMEM>>>(ynbf, kvwb, kbf, vbf);

    // qk (z<64) fused with v-transpose (z>=64)
    qksplit_kernel<<<dim3(8, 8, 128), 256, QK_SMEM>>>();

    select_kernel<<<Bz*8*Nn/8, 256>>>(kr1, kr2);
    av_mma_kernel<<<dim3(Nn/128, Bz*8), 256, AV_SMEM>>>();
    proj_mma_kernel<<<dim3(Cc/128, Nn/128, Bz), 256, PJ_SMEM>>>(proj_b, x, out);
}

// round 13
// speedup vs baseline: 1.1728x; 1.0591x over previous
#include <cuda_runtime.h>
#include <cuda_bf16.h>
#include <cuda_fp16.h>
#include <cstdint>

#define Bz 8
#define Cc 512
#define Nn 1024

// ---------------- device scratch (no allocations allowed) --------------------
__device__ float g_yf[Bz*Cc*Nn];               // conv output [B,C,N]
__device__ float g_yn[Bz*Cc*Nn];               // layernorm output [B,C,N]
__device__ __half g_attnh[(size_t)64*1024*1024]; // attn [64 z][1024 n][1024 m] fp16
// bf16 operand buffers
__device__ __nv_bfloat16 g_xbf [Bz*Nn*Cc];     // x^T  [b,n,512]
__device__ __nv_bfloat16 g_ynbf[Bz*Nn*Cc];     // yn^T [b,n,512]
__device__ __nv_bfloat16 g_qwb [Cc*Cc];        // 0.125*q_w  [co,512]
__device__ __nv_bfloat16 g_kvwb[2*Cc*Cc];      // kv_w [co,512]
__device__ __nv_bfloat16 g_pwb [Cc*Cc];        // proj_w [co,512]
__device__ __nv_bfloat16 g_qbf [Bz*Nn*Cc];     // q  [b,n,512]
__device__ __nv_bfloat16 g_kbf [Bz*Nn*Cc];     // k  [b,n,512]
__device__ __nv_bfloat16 g_vbf [Bz*Nn*Cc];     // v  [b,n,512]
__device__ __nv_bfloat16 g_obf [Bz*Nn*Cc];     // attn out [b,n,512]
__device__ __nv_bfloat16 g_vthi[(size_t)64*64*1024];   // v^T [z,d,m]
__device__ __nv_bfloat16 g_chi [(size_t)64*1024*1024]; // coeff [z,n,m]

// =================== warp-MMA helpers (plain sm_103-safe PTX) ================
__device__ __forceinline__ uint32_t smem_u32(const void* p) {
    uint32_t a;
    asm("{ .reg .u64 t; cvta.to.shared.u64 t, %1; cvt.u32.u64 %0, t; }"
        : "=r"(a) : "l"(p));
    return a;
}
__device__ __forceinline__ void ldsm_x4(uint32_t& r0, uint32_t& r1, uint32_t& r2,
                                        uint32_t& r3, uint32_t addr) {
    asm volatile("ldmatrix.sync.aligned.m8n8.x4.shared.b16 {%0,%1,%2,%3}, [%4];"
                 : "=r"(r0), "=r"(r1), "=r"(r2), "=r"(r3) : "r"(addr));
}
__device__ __forceinline__ void ldsm_x2(uint32_t& r0, uint32_t& r1, uint32_t addr) {
    asm volatile("ldmatrix.sync.aligned.m8n8.x2.shared.b16 {%0,%1}, [%2];"
                 : "=r"(r0), "=r"(r1) : "r"(addr));
}
__device__ __forceinline__ void mma_bf16(float* c, const uint32_t* a, const uint32_t* b) {
    asm volatile("mma.sync.aligned.m16n8k16.row.col.f32.bf16.bf16.f32 "
                 "{%0,%1,%2,%3}, {%4,%5,%6,%7}, {%8,%9}, {%0,%1,%2,%3};"
                 : "+f"(c[0]), "+f"(c[1]), "+f"(c[2]), "+f"(c[3])
                 : "r"(a[0]), "r"(a[1]), "r"(a[2]), "r"(a[3]), "r"(b[0]), "r"(b[1]));
}
#define CP_ASYNC16(dst, src) \
    asm volatile("cp.async.cg.shared.global [%0], [%1], 16;" :: "r"(dst), "l"(src))
#define CP_COMMIT() asm volatile("cp.async.commit_group;" ::: "memory")
#define CP_WAIT(n)  asm volatile("cp.async.wait_group %0;" :: "n"(n) : "memory")
#define PADB 144   // padded row stride (72 bf16): conflict-free ldmatrix, 16B-mult

// ================= K1: fused conv | weight-convert | x transpose =============
#define K1_SMEM (38*40*4 + 64*4)

__device__ void conv_body(int bc, int t,
                          const float* __restrict__ y,
                          const float* __restrict__ w3, const float* __restrict__ b3,
                          const float* __restrict__ w5, const float* __restrict__ b5,
                          const float* __restrict__ w7, const float* __restrict__ b7)
{
    extern __shared__ __align__(16) char k1sm[];
    float* tile  = (float*)k1sm;            // [38][40]
    float* wsum  = tile + 38*40;            // [49]
    float* biasp = wsum + 49;

    int c = bc & (Cc-1);
    if (t < 49) {
        int dy = t / 7, dx = t % 7;
        float w = w7[c*49 + t];
        if (dy >= 1 && dy <= 5 && dx >= 1 && dx <= 5) w += w5[c*25 + (dy-1)*5 + (dx-1)];
        if (dy >= 2 && dy <= 4 && dx >= 2 && dx <= 4) w += w3[c*9  + (dy-2)*3 + (dx-2)];
        wsum[t] = w;
    }
    if (t == 64) *biasp = b3[c] + b5[c] + b7[c];

    const float* yp = y + (size_t)bc * Nn;
    for (int i = t; i < 38*38; i += 256) {
        int rr = i / 38, cc = i % 38;
        int r = rr - 3, cl = cc - 3;
        float v = 0.f;
        if (r >= 0 && r < 32 && cl >= 0 && cl < 32) v = yp[r*32 + cl];
        tile[rr*40 + cc] = v;
    }
    __syncthreads();

    int r  = t >> 3;
    int cq = (t & 7) * 4;
    float bias = *biasp;
    float a0 = bias, a1 = bias, a2 = bias, a3 = bias;
    #pragma unroll
    for (int dy = 0; dy < 7; dy++) {
        float rv[12];
        const float* rp = &tile[(r+dy)*40 + cq];
        *(float4*)&rv[0] = *(const float4*)rp;
        *(float4*)&rv[4] = *(const float4*)(rp + 4);
        *(float4*)&rv[8] = *(const float4*)(rp + 8);
        #pragma unroll
        for (int dx = 0; dx < 7; dx++) {
            float w = wsum[dy*7 + dx];
            a0 += w*rv[dx];   a1 += w*rv[dx+1];
            a2 += w*rv[dx+2]; a3 += w*rv[dx+3];
        }
    }
    *(float4*)&g_yf[(size_t)bc*Nn + r*32 + cq] = make_float4(a0, a1, a2, a3);
}

__device__ void wcvt_body(int b2, int t,
                          const float* __restrict__ q_w,
                          const float* __restrict__ kv_w,
                          const float* __restrict__ proj_w)
{
    const float* S; __nv_bfloat16* D; float scale; int off;
    if (b2 < 256)      { S = q_w;    D = g_qwb;  scale = 0.125f; off = b2; }
    else if (b2 < 768) { S = kv_w;   D = g_kvwb; scale = 1.f;    off = b2 - 256; }
    else               { S = proj_w; D = g_pwb;  scale = 1.f;    off = b2 - 768; }
    int i4 = off * 256 + t;
    float4 v = *(const float4*)&S[(size_t)i4 * 4];
    __nv_bfloat16 o[4] = {__float2bfloat16(v.x*scale), __float2bfloat16(v.y*scale),
                          __float2bfloat16(v.z*scale), __float2bfloat16(v.w*scale)};
    *(uint2*)&D[(size_t)i4 * 4] = *(uint2*)o;
}

__device__ void tcvt_body(int idx, int t, const float* __restrict__ S,
                          __nv_bfloat16* __restrict__ D)
{
    extern __shared__ __align__(16) char k1sm[];
    float* tile = (float*)k1sm;             // [32][33]
    int n0 = (idx & 31) * 32;
    int c0 = ((idx >> 5) & 15) * 32;
    int b  = idx >> 9;
    int tx = t & 31, ty = t >> 5;
    #pragma unroll
    for (int i = ty; i < 32; i += 8)
        tile[i*33 + tx] = S[((size_t)b*Cc + c0 + i)*Nn + n0 + tx];
    __syncthreads();
    #pragma unroll
    for (int i = ty; i < 32; i += 8)
        D[((size_t)b*Nn + n0 + i)*Cc + c0 + tx] = __float2bfloat16(tile[tx*33 + i]);
}

__global__ void __launch_bounds__(256)
k1_kernel(const float* __restrict__ y,
          const float* __restrict__ w3, const float* __restrict__ b3,
          const float* __restrict__ w5, const float* __restrict__ b5,
          const float* __restrict__ w7, const float* __restrict__ b7,
          const float* __restrict__ x,
          const float* __restrict__ q_w, const float* __restrict__ kv_w,
          const float* __restrict__ proj_w)
{
    int blk = blockIdx.x, t = threadIdx.x;
    if (blk < 4096)       conv_body(blk, t, y, w3, b3, w5, b5, w7, b7);
    else if (blk < 5120)  wcvt_body(blk - 4096, t, q_w, kv_w, proj_w);
    else                  tcvt_body(blk - 5120, t, x, g_xbf);
}

// ---------------- standalone yn transpose-convert ----------------------------
__global__ void tcvt_yn_kernel()
{
    extern __shared__ __align__(16) char k1sm[];
    tcvt_body(blockIdx.x, threadIdx.x, g_yn, g_ynbf);
}

// ---------------- kernel 2: layernorm over C per (b,n) -----------------------
__global__ void ln_kernel(const float* __restrict__ lnw, const float* __restrict__ lnb)
{
    int b    = blockIdx.x >> 5;
    int n0   = (blockIdx.x & 31) * 32;
    int lane = threadIdx.x & 31;
    int g    = threadIdx.x >> 5;
    int n    = n0 + lane;

    const float* base = g_yf + (size_t)b*Cc*Nn + n;
    float s = 0.f, s2 = 0.f;
    for (int c = g; c < Cc; c += 8) {
        float v = base[(size_t)c*Nn];
        s += v; s2 += v*v;
    }
    __shared__ float sh[2][8][32];
    sh[0][g][lane] = s; sh[1][g][lane] = s2;
    __syncthreads();
    if (g == 0) {
        float a = 0.f, a2 = 0.f;
        #pragma unroll
        for (int i = 0; i < 8; i++) { a += sh[0][i][lane]; a2 += sh[1][i][lane]; }
        float mu  = a * (1.f/512.f);
        float var = a2 * (1.f/512.f) - mu*mu;
        sh[0][0][lane] = mu;
        sh[1][0][lane] = rsqrtf(var + 1e-5f);
    }
    __syncthreads();
    float mu = sh[0][0][lane], rs = sh[1][0][lane];
    float* ob = g_yn + (size_t)b*Cc*Nn + n;
    for (int c = g; c < Cc; c += 8) {
        float v = base[(size_t)c*Nn];
        ob[(size_t)c*Nn] = (v - mu) * rs * lnw[c] + lnb[c];
    }
}

// ------- kernels 3/4: bf16 mma projection GEMM, double-buffered cp.async -----
#define GM_SMEM (4*128*PADB)
__global__ void __launch_bounds__(256, 2)
gemm_mma_kernel(const __nv_bfloat16* __restrict__ A, const __nv_bfloat16* __restrict__ W,
                __nv_bfloat16* __restrict__ D0, __nv_bfloat16* __restrict__ D1)
{
    extern __shared__ __align__(16) char sm[];
    uint32_t sb = smem_u32(sm);

    int t = threadIdx.x, warp = t >> 5, lane = t & 31;
    int co0 = blockIdx.x * 128, n0 = blockIdx.y * 128, b = blockIdx.z;
    int wn = warp >> 2, wm = warp & 3;

    const char* asrc = (const char*)(A + ((size_t)(b*Nn + n0))*Cc);
    const char* wsrc = (const char*)(W + (size_t)co0*Cc);

    auto issue = [&](int kc, int bi) {
        uint32_t base = sb + bi*(2*128*PADB);
        for (int i = t; i < 1024; i += 256) {
            int row = i >> 3, cb = (i & 7) * 16;
            CP_ASYNC16(base + row*PADB + cb, asrc + (size_t)row*1024 + kc*2 + cb);
            CP_ASYNC16(base + 128*PADB + row*PADB + cb, wsrc + (size_t)row*1024 + kc*2 + cb);
        }
        CP_COMMIT();
    };
    issue(0, 0);

    float acc[4][4][4] = {};
    int lr16 = lane & 15, lh = lane >> 4;
    int l8 = lane & 7,  lq = (lane & 15) >> 3;

    for (int c8 = 0; c8 < 8; c8++) {
        if (c8 < 7) { issue((c8+1)*64, (c8+1)&1); CP_WAIT(1); }
        else        { CP_WAIT(0); }
        __syncthreads();
        uint32_t base = sb + (c8&1)*(2*128*PADB);
        uint32_t aAddr = base + (wn*64 + lr16)*PADB + lh*16;
        uint32_t bAddr = base + 128*PADB + (wm*32 + l8)*PADB + lq*16;
        #pragma unroll
        for (int k0 = 0; k0 < 64; k0 += 16) {
            uint32_t a[4][4], bb[4][2];
            #pragma unroll
            for (int mi = 0; mi < 4; mi++)
                ldsm_x4(a[mi][0], a[mi][1], a[mi][2], a[mi][3],
                        aAddr + mi*16*PADB + k0*2);
            #pragma unroll
            for (int ni = 0; ni < 4; ni++)
                ldsm_x2(bb[ni][0], bb[ni][1], bAddr + ni*8*PADB + k0*2);
            #pragma unroll
            for (int mi = 0; mi < 4; mi++)
                #pragma unroll
                for (int ni = 0; ni < 4; ni++)
                    mma_bf16(acc[mi][ni], a[mi], bb[ni]);
        }
        __syncthreads();
    }

    __nv_bfloat16* D = (co0 < Cc) ? D0 : D1;
    int cadj = (co0 < Cc) ? 0 : Cc;
    int rbase = n0 + wn*64 + (lane >> 2);
    int cbase = co0 - cadj + wm*32 + (lane & 3)*2;
    #pragma unroll
    for (int mi = 0; mi < 4; mi++)
        #pragma unroll
        for (int ni = 0; ni < 4; ni++) {
            float* c = acc[mi][ni];
            size_t r0i = ((size_t)(b*Nn) + rbase + mi*16)*Cc + cbase + ni*8;
            __nv_bfloat162 p0, p1;
            p0.x = __float2bfloat16(c[0]); p0.y = __float2bfloat16(c[1]);
            p1.x = __float2bfloat16(c[2]); p1.y = __float2bfloat16(c[3]);
            *(__nv_bfloat162*)&D[r0i]        = p0;
            *(__nv_bfloat162*)&D[r0i + 8*Cc] = p1;
        }
}

// ---------- v (bf16) -> transposed bf16 [z][d][m], flat grid 4096 -------------
__global__ void __launch_bounds__(256) vt_kernel()
{
    __shared__ __nv_bfloat16 tile[32*33];
    int f = blockIdx.x;
    int d0 = (f & 1) * 32, m0 = ((f >> 1) & 31) * 32, z = f >> 6;
    int b = z >> 3, h = z & 7;
    int t = threadIdx.x, tx = t & 31, ty = t >> 5;
    #pragma unroll
    for (int i = ty; i < 32; i += 8)
        tile[i*33 + tx] = g_vbf[((size_t)(b*Nn + m0 + i))*Cc + h*64 + d0 + tx];
    __syncthreads();
    #pragma unroll
    for (int i = ty; i < 32; i += 8)
        g_vthi[((size_t)z*64 + d0 + i)*1024 + m0 + tx] = tile[tx*33 + i];
}

// ------- kernel 5: QK^T, q resident / k streamed (double-buffered) -----------
// CTA: 128 q-rows x full m=1024 in 8 chunks of 128. smem: q + 2 k-buffers.
#define QK_SMEM (3*128*PADB)
__global__ void __launch_bounds__(256, 2) qk_mma_kernel()
{
    extern __shared__ __align__(16) char sm[];
    uint32_t sb = smem_u32(sm);
    const uint32_t QT = 0, KT = 128*PADB;    // k buffers at KT + bi*128*PADB

    int t = threadIdx.x, warp = t >> 5, lane = t & 31;
    int n0 = blockIdx.x * 128, z = blockIdx.y;
    int b = z >> 3, h = z & 7;
    int wn = warp >> 2, wm = warp & 3;

    const char* qs = (const char*)(g_qbf + ((size_t)(b*Nn + n0)*Cc + h*64));
    const char* ks = (const char*)(g_kbf + ((size_t)(b*Nn)*Cc + h*64));

    // group 0: q tile + k chunk 0
    for (int i = t; i < 1024; i += 256) {
        int row = i >> 3, cb = (i & 7) * 16;
        CP_ASYNC16(sb + QT + row*PADB + cb, qs + (size_t)row*1024 + cb);
    }
    auto issueK = [&](int m0, int bi) {
        uint32_t base = sb + KT + bi*(128*PADB);
        for (int i = t; i < 1024; i += 256) {
            int row = i >> 3, cb = (i & 7) * 16;
            CP_ASYNC16(base + row*PADB + cb, ks + (size_t)(m0 + row)*1024 + cb);
        }
        CP_COMMIT();
    };
    issueK(0, 0);   // commits q + k0 together

    int lr16 = lane & 15, lh = lane >> 4;
    int l8 = lane & 7,  lq = (lane & 15) >> 3;

    for (int c8 = 0; c8 < 8; c8++) {
        if (c8 < 7) { issueK((c8+1)*128, (c8+1)&1); CP_WAIT(1); }
        else        { CP_WAIT(0); }
        __syncthreads();

        float acc[4][4][4] = {};
        uint32_t aAddr = sb + QT + (wn*64 + lr16)*PADB + lh*16;
        uint32_t bAddr = sb + KT + (c8&1)*(128*PADB) + (wm*32 + l8)*PADB + lq*16;
        #pragma unroll
        for (int k0 = 0; k0 < 64; k0 += 16) {
            uint32_t a[4][4], bb[4][2];
            #pragma unroll
            for (int mi = 0; mi < 4; mi++)
                ldsm_x4(a[mi][0], a[mi][1], a[mi][2], a[mi][3],
                        aAddr + mi*16*PADB + k0*2);
            #pragma unroll
            for (int ni = 0; ni < 4; ni++)
                ldsm_x2(bb[ni][0], bb[ni][1], bAddr + ni*8*PADB + k0*2);
            #pragma unroll
            for (int mi = 0; mi < 4; mi++)
                #pragma unroll
                for (int ni = 0; ni < 4; ni++)
                    mma_bf16(acc[mi][ni], a[mi], bb[ni]);
        }

        int rbase = n0 + wn*64 + (lane >> 2);
        int cbase = c8*128 + wm*32 + (lane & 3)*2;
        #pragma unroll
        for (int mi = 0; mi < 4; mi++)
            #pragma unroll
            for (int ni = 0; ni < 4; ni++) {
                float* c = acc[mi][ni];
                __half* A = g_attnh + ((size_t)z*Nn + rbase + mi*16)*Nn + cbase + ni*8;
                *(__half2*)&A[0]            = __floats2half2_rn(c[0], c[1]);
                *(__half2*)&A[(size_t)8*Nn] = __floats2half2_rn(c[2], c[3]);
            }
        __syncthreads();
    }
}

// ---------------- kernel 6: exact top-k on 16-bit keys + dual softmax --------
__device__ __forceinline__ float key2h(unsigned k) {
    unsigned short b = (k & 0x8000u) ? (unsigned short)(k ^ 0x8000u)
                                     : (unsigned short)(~k & 0xFFFFu);
    return __half2float(__ushort_as_half(b));
}

__device__ __forceinline__ unsigned kth_key16(const unsigned* key, int k)
{
    unsigned prefix = 0;
    int kk = k;
    for (int bit = 15; bit >= 0; --bit) {
        unsigned bm = 1u << bit;
        unsigned msk = (bit == 15) ? bm : (((0xFFFFu << (bit+1)) & 0xFFFFu) | bm);
        unsigned want = prefix | bm;
        int c = 0;
        #pragma unroll
        for (int i = 0; i < 32; i++)
            c += ((key[i] & msk) == want) ? 1 : 0;
        c = __reduce_add_sync(0xffffffffu, c);
        if (c == kk) {
            unsigned mn = 0xFFFFu;
            #pragma unroll
            for (int i = 0; i < 32; i++)
                if ((key[i] & msk) == want) mn = min(mn, key[i]);
            return __reduce_min_sync(0xffffffffu, mn);
        } else if (c > kk) {
            prefix |= bm;
        } else {
            kk -= c;
        }
    }
    return prefix;
}

__global__ void select_kernel(const float* __restrict__ kr1, const float* __restrict__ kr2)
{
    int row  = blockIdx.x * 8 + (threadIdx.x >> 5);   // z*1024 + n
    int lane = threadIdx.x & 31;

    float r1 = kr1[0], r2 = kr2[0];
    int k1 = (int)(1024.f * (1.f/(1.f+expf(-r1)))); k1 = min(max(k1,1),1024);
    int k2 = (int)(1024.f * (1.f/(1.f+expf(-r2)))); k2 = min(max(k2,1),1024);

    const __half* rp = g_attnh + (size_t)row * Nn;
    unsigned key[32];
    #pragma unroll
    for (int i = 0; i < 4; i++) {
        uint4 v = *(const uint4*)(rp + i*256 + lane*8);
        const unsigned short* hh = (const unsigned short*)&v;
        #pragma unroll
        for (int j = 0; j < 8; j++) {
            unsigned b = hh[j];
            key[i*8 + j] = (b & 0x8000u) ? ((~b) & 0xFFFFu) : (b | 0x8000u);
        }
    }

    unsigned mx = 0;
    #pragma unroll
    for (int i = 0; i < 32; i++) mx = max(mx, key[i]);
    mx = __reduce_max_sync(0xffffffffu, mx);
    float M = key2h(mx);

    unsigned T1 = kth_key16(key, k1);
    unsigned T2 = kth_key16(key, k2);

    float ev[32];
    float s1 = 0.f, s2 = 0.f;
    #pragma unroll
    for (int i = 0; i < 32; i++) {
        ev[i] = __expf(key2h(key[i]) - M);
        if (key[i] >= T1) s1 += ev[i];
        if (key[i] >= T2) s2 += ev[i];
    }
    #pragma unroll
    for (int o = 16; o; o >>= 1) {
        s1 += __shfl_xor_sync(0xffffffffu, s1, o);
        s2 += __shfl_xor_sync(0xffffffffu, s2, o);
    }
    float c1 = 0.6f / s1, c2 = 0.4f / s2;
    __nv_bfloat16* ch = g_chi + (size_t)row * Nn;
    #pragma unroll
    for (int i = 0; i < 4; i++) {
        __nv_bfloat16 ob[8];
        #pragma unroll
        for (int j = 0; j < 8; j++) {
            int e = i*8 + j;
            float w = (key[e] >= T1 ? c1 : 0.f) + (key[e] >= T2 ? c2 : 0.f);
            ob[j] = __float2bfloat16(ev[e] * w);
        }
        *(uint4*)(ch + i*256 + lane*8) = *(const uint4*)ob;
    }
}

// ------- kernel 7: AV via mma.sync bf16, double-buffered, bf16 output --------
#define AV_SMEM (2*(192*PADB))
__global__ void __launch_bounds__(256, 2) av_mma_kernel()
{
    extern __shared__ __align__(16) char sm[];
    uint32_t sb = smem_u32(sm);

    int t = threadIdx.x, warp = t >> 5, lane = t & 31;
    int n0 = blockIdx.x * 128, z = blockIdx.y;
    int b = z >> 3, h = z & 7;
    int wn = warp >> 1, wd = warp & 1;

    const char* ch = (const char*)(g_chi  + ((size_t)z*Nn + n0)*Nn);
    const char* vh = (const char*)(g_vthi + (size_t)z*64*1024);

    auto issue = [&](int m0, int bi) {
        uint32_t base = sb + bi*(192*PADB);
        for (int i = t; i < 1024; i += 256) {
            int row = i >> 3, cb = (i & 7) * 16;
            CP_ASYNC16(base + row*PADB + cb, ch + (size_t)row*2048 + m0*2 + cb);
        }
        for (int i = t; i < 512; i += 256) {
            int row = i >> 3, cb = (i & 7) * 16;
            CP_ASYNC16(base + 128*PADB + row*PADB + cb, vh + (size_t)row*2048 + m0*2 + cb);
        }
        CP_COMMIT();
    };
    issue(0, 0);

    float acc[2][4][4] = {};
    int lr16 = lane & 15, lh = lane >> 4;
    int l8 = lane & 7,  lq = (lane & 15) >> 3;

    for (int c16 = 0; c16 < 16; c16++) {
        if (c16 < 15) { issue((c16+1)*64, (c16+1)&1); CP_WAIT(1); }
        else          { CP_WAIT(0); }
        __syncthreads();
        uint32_t base = sb + (c16&1)*(192*PADB);
        uint32_t aAddr = base + (wn*32 + lr16)*PADB + lh*16;
        uint32_t bAddr = base + 128*PADB + (wd*32 + l8)*PADB + lq*16;
        #pragma unroll
        for (int k0 = 0; k0 < 64; k0 += 16) {
            uint32_t a[2][4], bb[4][2];
            #pragma unroll
            for (int mi = 0; mi < 2; mi++)
                ldsm_x4(a[mi][0], a[mi][1], a[mi][2], a[mi][3],
                        aAddr + mi*16*PADB + k0*2);
            #pragma unroll
            for (int ni = 0; ni < 4; ni++)
                ldsm_x2(bb[ni][0], bb[ni][1], bAddr + ni*8*PADB + k0*2);
            #pragma unroll
            for (int mi = 0; mi < 2; mi++)
                #pragma unroll
                for (int ni = 0; ni < 4; ni++)
                    mma_bf16(acc[mi][ni], a[mi], bb[ni]);
        }
        __syncthreads();
    }

    int rbase = n0 + wn*32 + (lane >> 2);
    int cbase = h*64 + wd*32 + (lane & 3)*2;
    #pragma unroll
    for (int mi = 0; mi < 2; mi++)
        #pragma unroll
        for (int ni = 0; ni < 4; ni++) {
            float* c = acc[mi][ni];
            size_t o0 = ((size_t)(b*Nn) + rbase + mi*16)*Cc + cbase + ni*8;
            __nv_bfloat162 p0, p1;
            p0.x = __float2bfloat16(c[0]); p0.y = __float2bfloat16(c[1]);
            p1.x = __float2bfloat16(c[2]); p1.y = __float2bfloat16(c[3]);
            *(__nv_bfloat162*)&g_obf[o0]        = p0;
            *(__nv_bfloat162*)&g_obf[o0 + 8*Cc] = p1;
        }
}

// ------- kernel 8: proj via mma; out[b,c,n] = W.o + bias + x ------------------
#define PJ_SMEM (4*128*PADB)
__global__ void __launch_bounds__(256, 2)
proj_mma_kernel(const float* __restrict__ bias, const float* __restrict__ x,
                float* __restrict__ OUT)
{
    extern __shared__ __align__(16) char sm[];
    uint32_t sb = smem_u32(sm);

    int t = threadIdx.x, warp = t >> 5, lane = t & 31;
    int c0 = blockIdx.x * 128, n0 = blockIdx.y * 128, b = blockIdx.z;
    int wc = warp >> 2, wnn = warp & 3;

    const char* wsrc = (const char*)(g_pwb + (size_t)c0*Cc);
    const char* osrc = (const char*)(g_obf + ((size_t)(b*Nn + n0))*Cc);

    auto issue = [&](int kc, int bi) {
        uint32_t base = sb + bi*(2*128*PADB);
        for (int i = t; i < 1024; i += 256) {
            int row = i >> 3, cb = (i & 7) * 16;
            CP_ASYNC16(base + row*PADB + cb, wsrc + (size_t)row*1024 + kc*2 + cb);
            CP_ASYNC16(base + 128*PADB + row*PADB + cb, osrc + (size_t)row*1024 + kc*2 + cb);
        }
        CP_COMMIT();
    };
    issue(0, 0);

    float acc[4][4][4] = {};
    int lr16 = lane & 15, lh = lane >> 4;
    int l8 = lane & 7,  lq = (lane & 15) >> 3;

    for (int c8 = 0; c8 < 8; c8++) {
        if (c8 < 7) { issue((c8+1)*64, (c8+1)&1); CP_WAIT(1); }
        else        { CP_WAIT(0); }
        __syncthreads();
        uint32_t base = sb + (c8&1)*(2*128*PADB);
        uint32_t aAddr = base + (wc*64 + lr16)*PADB + lh*16;
        uint32_t bAddr = base + 128*PADB + (wnn*32 + l8)*PADB + lq*16;
        #pragma unroll
        for (int k0 = 0; k0 < 64; k0 += 16) {
            uint32_t a[4][4], bb[4][2];
            #pragma unroll
            for (int mi = 0; mi < 4; mi++)
                ldsm_x4(a[mi][0], a[mi][1], a[mi][2], a[mi][3],
                        aAddr + mi*16*PADB + k0*2);
            #pragma unroll
            for (int ni = 0; ni < 4; ni++)
                ldsm_x2(bb[ni][0], bb[ni][1], bAddr + ni*8*PADB + k0*2);
            #pragma unroll
            for (int mi = 0; mi < 4; mi++)
                #pragma unroll
                for (int ni = 0; ni < 4; ni++)
                    mma_bf16(acc[mi][ni], a[mi], bb[ni]);
        }
        __syncthreads();
    }

    int cb0 = c0 + wc*64 + (lane >> 2);
    int nb0 = n0 + wnn*32 + (lane & 3)*2;
    #pragma unroll
    for (int mi = 0; mi < 4; mi++) {
        int c = cb0 + mi*16;
        float bs0 = bias[c], bs8 = bias[c + 8];
        #pragma unroll
        for (int ni = 0; ni < 4; ni++) {
            float* a = acc[mi][ni];
            int n = nb0 + ni*8;
            size_t i0 = ((size_t)b*Cc + c)*Nn + n;
            float2 x0 = *(const float2*)&x[i0];
            *(float2*)&OUT[i0] = make_float2(a[0] + bs0 + x0.x, a[1] + bs0 + x0.y);
            size_t i8 = i0 + (size_t)8*Nn;
            float2 x8 = *(const float2*)&x[i8];
            *(float2*)&OUT[i8] = make_float2(a[2] + bs8 + x8.x, a[3] + bs8 + x8.y);
        }
    }
}

// -----------------------------------------------------------------------------
extern "C" void kernel_launch(void* const* d_in, const int* in_sizes, int n_in,
                              void* d_out, int out_size)
{
    const float* x       = (const float*)d_in[0];
    const float* y       = (const float*)d_in[1];
    const float* q_w     = (const float*)d_in[2];
    const float* kv_w    = (const float*)d_in[3];
    const float* proj_w  = (const float*)d_in[4];
    const float* proj_b  = (const float*)d_in[5];
    const float* conv1_w = (const float*)d_in[6];
    const float* conv1_b = (const float*)d_in[7];
    const float* conv2_w = (const float*)d_in[8];
    const float* conv2_b = (const float*)d_in[9];
    const float* conv3_w = (const float*)d_in[10];
    const float* conv3_b = (const float*)d_in[11];
    const float* ln_w    = (const float*)d_in[12];
    const float* ln_b    = (const float*)d_in[13];
    const float* kr1     = (const float*)d_in[14];
    const float* kr2     = (const float*)d_in[15];
    float* out = (float*)d_out;

    __nv_bfloat16 *xbf, *ynbf, *qwb, *kvwb, *qbf, *kbf, *vbf;
    cudaGetSymbolAddress((void**)&xbf,  g_xbf);
    cudaGetSymbolAddress((void**)&ynbf, g_ynbf);
    cudaGetSymbolAddress((void**)&qwb,  g_qwb);
    cudaGetSymbolAddress((void**)&kvwb, g_kvwb);
    cudaGetSymbolAddress((void**)&qbf,  g_qbf);
    cudaGetSymbolAddress((void**)&kbf,  g_kbf);
    cudaGetSymbolAddress((void**)&vbf,  g_vbf);

    cudaFuncSetAttribute(gemm_mma_kernel, cudaFuncAttributeMaxDynamicSharedMemorySize, GM_SMEM);
    cudaFuncSetAttribute(qk_mma_kernel,   cudaFuncAttributeMaxDynamicSharedMemorySize, QK_SMEM);
    cudaFuncSetAttribute(av_mma_kernel,   cudaFuncAttributeMaxDynamicSharedMemorySize, AV_SMEM);
    cudaFuncSetAttribute(proj_mma_kernel, cudaFuncAttributeMaxDynamicSharedMemorySize, PJ_SMEM);

    // K1: conv | weight-cvt | x transpose-cvt (all independent)
    k1_kernel<<<4096 + 1024 + 4096, 256, K1_SMEM>>>(
        y, conv1_w, conv1_b, conv2_w, conv2_b, conv3_w, conv3_b,
        x, q_w, kv_w, proj_w);

    ln_kernel<<<Bz*32, 256>>>(ln_w, ln_b);

    gemm_mma_kernel<<<dim3(4, 8, Bz), 256, GM_SMEM>>>(xbf, qwb, qbf, qbf);

    tcvt_yn_kernel<<<4096, 256, K1_SMEM>>>();

    gemm_mma_kernel<<<dim3(8, 8, Bz), 256, GM_SMEM>>>(ynbf, kvwb, kbf, vbf);

    vt_kernel<<<4096, 256>>>();

    qk_mma_kernel<<<dim3(8, 64), 256, QK_SMEM>>>();

    select_kernel<<<Bz*8*Nn/8, 256>>>(kr1, kr2);
    av_mma_kernel<<<dim3(Nn/128, Bz*8), 256, AV_SMEM>>>();
    proj_mma_kernel<<<dim3(Cc/128, Nn/128, Bz), 256, PJ_SMEM>>>(proj_b, x, out);
}

// round 14
// speedup vs baseline: 1.4923x; 1.2725x over previous
#include <cuda_runtime.h>
#include <cuda_bf16.h>
#include <cuda_fp16.h>
#include <cstdint>

#define Bz 8
#define Cc 512
#define Nn 1024

// ---------------- device scratch (no allocations allowed) --------------------
__device__ float g_yf[Bz*Cc*Nn];               // conv output [B,C,N]
__device__ float g_yn[Bz*Cc*Nn];               // layernorm output [B,C,N]
__device__ __half g_attnh[(size_t)64*1024*1024]; // attn [64 z][1024 n][1024 m] fp16
// bf16 operand buffers
__device__ __nv_bfloat16 g_xbf [Bz*Nn*Cc];     // x^T  [b,n,512]
__device__ __nv_bfloat16 g_ynbf[Bz*Nn*Cc];     // yn^T [b,n,512]
__device__ __nv_bfloat16 g_qwb [Cc*Cc];        // 0.125*q_w  [co,512]
__device__ __nv_bfloat16 g_kvwb[2*Cc*Cc];      // kv_w [co,512]
__device__ __nv_bfloat16 g_pwb [Cc*Cc];        // proj_w [co,512]
__device__ __nv_bfloat16 g_qbf [Bz*Nn*Cc];     // q  [b,n,512]
__device__ __nv_bfloat16 g_kbf [Bz*Nn*Cc];     // k  [b,n,512]
__device__ __nv_bfloat16 g_vbf [Bz*Nn*Cc];     // v  [b,n,512]
__device__ __nv_bfloat16 g_obf [Bz*Nn*Cc];     // attn out [b,n,512]
__device__ __nv_bfloat16 g_vthi[(size_t)64*64*1024];   // v^T [z,d,m]
__device__ __nv_bfloat16 g_chi [(size_t)64*1024*1024]; // coeff [z,n,m]

// =================== warp-MMA helpers (plain sm_103-safe PTX) ================
__device__ __forceinline__ uint32_t smem_u32(const void* p) {
    uint32_t a;
    asm("{ .reg .u64 t; cvta.to.shared.u64 t, %1; cvt.u32.u64 %0, t; }"
        : "=r"(a) : "l"(p));
    return a;
}
__device__ __forceinline__ void ldsm_x4(uint32_t& r0, uint32_t& r1, uint32_t& r2,
                                        uint32_t& r3, uint32_t addr) {
    asm volatile("ldmatrix.sync.aligned.m8n8.x4.shared.b16 {%0,%1,%2,%3}, [%4];"
                 : "=r"(r0), "=r"(r1), "=r"(r2), "=r"(r3) : "r"(addr));
}
__device__ __forceinline__ void ldsm_x2(uint32_t& r0, uint32_t& r1, uint32_t addr) {
    asm volatile("ldmatrix.sync.aligned.m8n8.x2.shared.b16 {%0,%1}, [%2];"
                 : "=r"(r0), "=r"(r1) : "r"(addr));
}
__device__ __forceinline__ void mma_bf16(float* c, const uint32_t* a, const uint32_t* b) {
    asm volatile("mma.sync.aligned.m16n8k16.row.col.f32.bf16.bf16.f32 "
                 "{%0,%1,%2,%3}, {%4,%5,%6,%7}, {%8,%9}, {%0,%1,%2,%3};"
                 : "+f"(c[0]), "+f"(c[1]), "+f"(c[2]), "+f"(c[3])
                 : "r"(a[0]), "r"(a[1]), "r"(a[2]), "r"(a[3]), "r"(b[0]), "r"(b[1]));
}
#define CP_ASYNC16(dst, src) \
    asm volatile("cp.async.cg.shared.global [%0], [%1], 16;" :: "r"(dst), "l"(src))
#define CP_COMMIT() asm volatile("cp.async.commit_group;" ::: "memory")
#define CP_WAIT(n)  asm volatile("cp.async.wait_group %0;" :: "n"(n) : "memory")
#define PADB 144   // padded row stride (72 bf16): conflict-free ldmatrix, 16B-mult

// ================= K1: fused conv | weight-convert | x transpose =============
#define K1_SMEM (38*40*4 + 64*4)

__device__ void conv_body(int bc, int t,
                          const float* __restrict__ y,
                          const float* __restrict__ w3, const float* __restrict__ b3,
                          const float* __restrict__ w5, const float* __restrict__ b5,
                          const float* __restrict__ w7, const float* __restrict__ b7)
{
    extern __shared__ __align__(16) char k1sm[];
    float* tile  = (float*)k1sm;            // [38][40]
    float* wsum  = tile + 38*40;            // [49]
    float* biasp = wsum + 49;

    int c = bc & (Cc-1);
    if (t < 49) {
        int dy = t / 7, dx = t % 7;
        float w = w7[c*49 + t];
        if (dy >= 1 && dy <= 5 && dx >= 1 && dx <= 5) w += w5[c*25 + (dy-1)*5 + (dx-1)];
        if (dy >= 2 && dy <= 4 && dx >= 2 && dx <= 4) w += w3[c*9  + (dy-2)*3 + (dx-2)];
        wsum[t] = w;
    }
    if (t == 64) *biasp = b3[c] + b5[c] + b7[c];

    const float* yp = y + (size_t)bc * Nn;
    for (int i = t; i < 38*38; i += 256) {
        int rr = i / 38, cc = i % 38;
        int r = rr - 3, cl = cc - 3;
        float v = 0.f;
        if (r >= 0 && r < 32 && cl >= 0 && cl < 32) v = yp[r*32 + cl];
        tile[rr*40 + cc] = v;
    }
    __syncthreads();

    int r  = t >> 3;
    int cq = (t & 7) * 4;
    float bias = *biasp;
    float a0 = bias, a1 = bias, a2 = bias, a3 = bias;
    #pragma unroll
    for (int dy = 0; dy < 7; dy++) {
        float rv[12];
        const float* rp = &tile[(r+dy)*40 + cq];
        *(float4*)&rv[0] = *(const float4*)rp;
        *(float4*)&rv[4] = *(const float4*)(rp + 4);
        *(float4*)&rv[8] = *(const float4*)(rp + 8);
        #pragma unroll
        for (int dx = 0; dx < 7; dx++) {
            float w = wsum[dy*7 + dx];
            a0 += w*rv[dx];   a1 += w*rv[dx+1];
            a2 += w*rv[dx+2]; a3 += w*rv[dx+3];
        }
    }
    *(float4*)&g_yf[(size_t)bc*Nn + r*32 + cq] = make_float4(a0, a1, a2, a3);
}

__device__ void wcvt_body(int b2, int t,
                          const float* __restrict__ q_w,
                          const float* __restrict__ kv_w,
                          const float* __restrict__ proj_w)
{
    const float* S; __nv_bfloat16* D; float scale; int off;
    if (b2 < 256)      { S = q_w;    D = g_qwb;  scale = 0.125f; off = b2; }
    else if (b2 < 768) { S = kv_w;   D = g_kvwb; scale = 1.f;    off = b2 - 256; }
    else               { S = proj_w; D = g_pwb;  scale = 1.f;    off = b2 - 768; }
    int i4 = off * 256 + t;
    float4 v = *(const float4*)&S[(size_t)i4 * 4];
    __nv_bfloat16 o[4] = {__float2bfloat16(v.x*scale), __float2bfloat16(v.y*scale),
                          __float2bfloat16(v.z*scale), __float2bfloat16(v.w*scale)};
    *(uint2*)&D[(size_t)i4 * 4] = *(uint2*)o;
}

__device__ void tcvt_body(int idx, int t, const float* __restrict__ S,
                          __nv_bfloat16* __restrict__ D)
{
    extern __shared__ __align__(16) char k1sm[];
    float* tile = (float*)k1sm;             // [32][33]
    int n0 = (idx & 31) * 32;
    int c0 = ((idx >> 5) & 15) * 32;
    int b  = idx >> 9;
    int tx = t & 31, ty = t >> 5;
    #pragma unroll
    for (int i = ty; i < 32; i += 8)
        tile[i*33 + tx] = S[((size_t)b*Cc + c0 + i)*Nn + n0 + tx];
    __syncthreads();
    #pragma unroll
    for (int i = ty; i < 32; i += 8)
        D[((size_t)b*Nn + n0 + i)*Cc + c0 + tx] = __float2bfloat16(tile[tx*33 + i]);
}

__global__ void __launch_bounds__(256)
k1_kernel(const float* __restrict__ y,
          const float* __restrict__ w3, const float* __restrict__ b3,
          const float* __restrict__ w5, const float* __restrict__ b5,
          const float* __restrict__ w7, const float* __restrict__ b7,
          const float* __restrict__ x,
          const float* __restrict__ q_w, const float* __restrict__ kv_w,
          const float* __restrict__ proj_w)
{
    int blk = blockIdx.x, t = threadIdx.x;
    if (blk < 4096)       conv_body(blk, t, y, w3, b3, w5, b5, w7, b7);
    else if (blk < 5120)  wcvt_body(blk - 4096, t, q_w, kv_w, proj_w);
    else                  tcvt_body(blk - 5120, t, x, g_xbf);
}

// ---------------- standalone yn transpose-convert ----------------------------
__global__ void tcvt_yn_kernel()
{
    extern __shared__ __align__(16) char k1sm[];
    tcvt_body(blockIdx.x, threadIdx.x, g_yn, g_ynbf);
}

// ---------------- kernel 2: layernorm over C per (b,n) -----------------------
__global__ void ln_kernel(const float* __restrict__ lnw, const float* __restrict__ lnb)
{
    int b    = blockIdx.x >> 5;
    int n0   = (blockIdx.x & 31) * 32;
    int lane = threadIdx.x & 31;
    int g    = threadIdx.x >> 5;
    int n    = n0 + lane;

    const float* base = g_yf + (size_t)b*Cc*Nn + n;
    float s = 0.f, s2 = 0.f;
    for (int c = g; c < Cc; c += 8) {
        float v = base[(size_t)c*Nn];
        s += v; s2 += v*v;
    }
    __shared__ float sh[2][8][32];
    sh[0][g][lane] = s; sh[1][g][lane] = s2;
    __syncthreads();
    if (g == 0) {
        float a = 0.f, a2 = 0.f;
        #pragma unroll
        for (int i = 0; i < 8; i++) { a += sh[0][i][lane]; a2 += sh[1][i][lane]; }
        float mu  = a * (1.f/512.f);
        float var = a2 * (1.f/512.f) - mu*mu;
        sh[0][0][lane] = mu;
        sh[1][0][lane] = rsqrtf(var + 1e-5f);
    }
    __syncthreads();
    float mu = sh[0][0][lane], rs = sh[1][0][lane];
    float* ob = g_yn + (size_t)b*Cc*Nn + n;
    for (int c = g; c < Cc; c += 8) {
        float v = base[(size_t)c*Nn];
        ob[(size_t)c*Nn] = (v - mu) * rs * lnw[c] + lnb[c];
    }
}

// ------- kernels 3/4: bf16 mma projection GEMM, double-buffered cp.async -----
#define GM_SMEM (4*128*PADB)
__global__ void __launch_bounds__(256, 2)
gemm_mma_kernel(const __nv_bfloat16* __restrict__ A, const __nv_bfloat16* __restrict__ W,
                __nv_bfloat16* __restrict__ D0, __nv_bfloat16* __restrict__ D1)
{
    extern __shared__ __align__(16) char sm[];
    uint32_t sb = smem_u32(sm);

    int t = threadIdx.x, warp = t >> 5, lane = t & 31;
    int co0 = blockIdx.x * 128, n0 = blockIdx.y * 128, b = blockIdx.z;
    int wn = warp >> 2, wm = warp & 3;

    const char* asrc = (const char*)(A + ((size_t)(b*Nn + n0))*Cc);
    const char* wsrc = (const char*)(W + (size_t)co0*Cc);

    auto issue = [&](int kc, int bi) {
        uint32_t base = sb + bi*(2*128*PADB);
        for (int i = t; i < 1024; i += 256) {
            int row = i >> 3, cb = (i & 7) * 16;
            CP_ASYNC16(base + row*PADB + cb, asrc + (size_t)row*1024 + kc*2 + cb);
            CP_ASYNC16(base + 128*PADB + row*PADB + cb, wsrc + (size_t)row*1024 + kc*2 + cb);
        }
        CP_COMMIT();
    };
    issue(0, 0);

    float acc[4][4][4] = {};
    int lr16 = lane & 15, lh = lane >> 4;
    int l8 = lane & 7,  lq = (lane & 15) >> 3;

    for (int c8 = 0; c8 < 8; c8++) {
        if (c8 < 7) { issue((c8+1)*64, (c8+1)&1); CP_WAIT(1); }
        else        { CP_WAIT(0); }
        __syncthreads();
        uint32_t base = sb + (c8&1)*(2*128*PADB);
        uint32_t aAddr = base + (wn*64 + lr16)*PADB + lh*16;
        uint32_t bAddr = base + 128*PADB + (wm*32 + l8)*PADB + lq*16;
        #pragma unroll
        for (int k0 = 0; k0 < 64; k0 += 16) {
            uint32_t a[4][4], bb[4][2];
            #pragma unroll
            for (int mi = 0; mi < 4; mi++)
                ldsm_x4(a[mi][0], a[mi][1], a[mi][2], a[mi][3],
                        aAddr + mi*16*PADB + k0*2);
            #pragma unroll
            for (int ni = 0; ni < 4; ni++)
                ldsm_x2(bb[ni][0], bb[ni][1], bAddr + ni*8*PADB + k0*2);
            #pragma unroll
            for (int mi = 0; mi < 4; mi++)
                #pragma unroll
                for (int ni = 0; ni < 4; ni++)
                    mma_bf16(acc[mi][ni], a[mi], bb[ni]);
        }
        __syncthreads();
    }

    __nv_bfloat16* D = (co0 < Cc) ? D0 : D1;
    int cadj = (co0 < Cc) ? 0 : Cc;
    int rbase = n0 + wn*64 + (lane >> 2);
    int cbase = co0 - cadj + wm*32 + (lane & 3)*2;
    #pragma unroll
    for (int mi = 0; mi < 4; mi++)
        #pragma unroll
        for (int ni = 0; ni < 4; ni++) {
            float* c = acc[mi][ni];
            size_t r0i = ((size_t)(b*Nn) + rbase + mi*16)*Cc + cbase + ni*8;
            __nv_bfloat162 p0, p1;
            p0.x = __float2bfloat16(c[0]); p0.y = __float2bfloat16(c[1]);
            p1.x = __float2bfloat16(c[2]); p1.y = __float2bfloat16(c[3]);
            *(__nv_bfloat162*)&D[r0i]        = p0;
            *(__nv_bfloat162*)&D[r0i + 8*Cc] = p1;
        }
}

// ---------- v (bf16) -> transposed bf16 [z][d][m], flat grid 4096 -------------
__global__ void __launch_bounds__(256) vt_kernel()
{
    __shared__ __nv_bfloat16 tile[32*33];
    int f = blockIdx.x;
    int d0 = (f & 1) * 32, m0 = ((f >> 1) & 31) * 32, z = f >> 6;
    int b = z >> 3, h = z & 7;
    int t = threadIdx.x, tx = t & 31, ty = t >> 5;
    #pragma unroll
    for (int i = ty; i < 32; i += 8)
        tile[i*33 + tx] = g_vbf[((size_t)(b*Nn + m0 + i))*Cc + h*64 + d0 + tx];
    __syncthreads();
    #pragma unroll
    for (int i = ty; i < 32; i += 8)
        g_vthi[((size_t)z*64 + d0 + i)*1024 + m0 + tx] = tile[tx*33 + i];
}

// ------- kernel 5: QK^T, q resident / k streamed (double-buffered) -----------
#define QK_SMEM (3*128*PADB)
__global__ void __launch_bounds__(256, 2) qk_mma_kernel()
{
    extern __shared__ __align__(16) char sm[];
    uint32_t sb = smem_u32(sm);
    const uint32_t QT = 0, KT = 128*PADB;

    int t = threadIdx.x, warp = t >> 5, lane = t & 31;
    int n0 = blockIdx.x * 128, z = blockIdx.y;
    int b = z >> 3, h = z & 7;
    int wn = warp >> 2, wm = warp & 3;

    const char* qs = (const char*)(g_qbf + ((size_t)(b*Nn + n0)*Cc + h*64));
    const char* ks = (const char*)(g_kbf + ((size_t)(b*Nn)*Cc + h*64));

    for (int i = t; i < 1024; i += 256) {
        int row = i >> 3, cb = (i & 7) * 16;
        CP_ASYNC16(sb + QT + row*PADB + cb, qs + (size_t)row*1024 + cb);
    }
    auto issueK = [&](int m0, int bi) {
        uint32_t base = sb + KT + bi*(128*PADB);
        for (int i = t; i < 1024; i += 256) {
            int row = i >> 3, cb = (i & 7) * 16;
            CP_ASYNC16(base + row*PADB + cb, ks + (size_t)(m0 + row)*1024 + cb);
        }
        CP_COMMIT();
    };
    issueK(0, 0);

    int lr16 = lane & 15, lh = lane >> 4;
    int l8 = lane & 7,  lq = (lane & 15) >> 3;

    for (int c8 = 0; c8 < 8; c8++) {
        if (c8 < 7) { issueK((c8+1)*128, (c8+1)&1); CP_WAIT(1); }
        else        { CP_WAIT(0); }
        __syncthreads();

        float acc[4][4][4] = {};
        uint32_t aAddr = sb + QT + (wn*64 + lr16)*PADB + lh*16;
        uint32_t bAddr = sb + KT + (c8&1)*(128*PADB) + (wm*32 + l8)*PADB + lq*16;
        #pragma unroll
        for (int k0 = 0; k0 < 64; k0 += 16) {
            uint32_t a[4][4], bb[4][2];
            #pragma unroll
            for (int mi = 0; mi < 4; mi++)
                ldsm_x4(a[mi][0], a[mi][1], a[mi][2], a[mi][3],
                        aAddr + mi*16*PADB + k0*2);
            #pragma unroll
            for (int ni = 0; ni < 4; ni++)
                ldsm_x2(bb[ni][0], bb[ni][1], bAddr + ni*8*PADB + k0*2);
            #pragma unroll
            for (int mi = 0; mi < 4; mi++)
                #pragma unroll
                for (int ni = 0; ni < 4; ni++)
                    mma_bf16(acc[mi][ni], a[mi], bb[ni]);
        }

        int rbase = n0 + wn*64 + (lane >> 2);
        int cbase = c8*128 + wm*32 + (lane & 3)*2;
        #pragma unroll
        for (int mi = 0; mi < 4; mi++)
            #pragma unroll
            for (int ni = 0; ni < 4; ni++) {
                float* c = acc[mi][ni];
                __half* A = g_attnh + ((size_t)z*Nn + rbase + mi*16)*Nn + cbase + ni*8;
                *(__half2*)&A[0]            = __floats2half2_rn(c[0], c[1]);
                *(__half2*)&A[(size_t)8*Nn] = __floats2half2_rn(c[2], c[3]);
            }
        __syncthreads();
    }
}

// ------- kernel 6: exact top-k via >=-count bisection (dual walk) ------------
__device__ __forceinline__ float key2h(unsigned k) {
    unsigned short b = (k & 0x8000u) ? (unsigned short)(k ^ 0x8000u)
                                     : (unsigned short)(~k & 0xFFFFu);
    return __half2float(__ushort_as_half(b));
}

// returns (T1, T2): exact k1-th / k2-th largest 16-bit keys of the row.
__device__ __forceinline__ uint2 kth2_key16(const unsigned* key, int k1, int k2,
                                            unsigned mx)
{
    unsigned T1 = 0, T2 = 0;
    bool d1 = false, d2 = false;
    for (int bit = 15; bit >= 0; --bit) {
        if (d1 && d2) break;
        unsigned bm  = 1u << bit;
        unsigned Tp1 = T1 | bm, Tp2 = T2 | bm;
        bool a1 = !d1 && (Tp1 <= mx);
        bool a2 = !d2 && (Tp2 <= mx);
        if (!a1 && !a2) continue;
        unsigned cc = 0;
        #pragma unroll
        for (int i = 0; i < 32; i++) {
            cc += (key[i] >= Tp1) ? 1u : 0u;
            cc += (key[i] >= Tp2) ? 0x10000u : 0u;
        }
        cc = __reduce_add_sync(0xffffffffu, cc);
        int c1 = (int)(cc & 0xffffu), c2 = (int)(cc >> 16);
        if (a1 && c1 >= k1) { T1 = Tp1; d1 = (c1 == k1); }
        if (a2 && c2 >= k2) { T2 = Tp2; d2 = (c2 == k2); }
    }
    if (d1) {   // exact-count early exit: threshold = min of survivors
        unsigned mn = 0xFFFFFFFFu;
        #pragma unroll
        for (int i = 0; i < 32; i++)
            if (key[i] >= T1) mn = min(mn, key[i]);
        T1 = __reduce_min_sync(0xffffffffu, mn);
    }
    if (d2) {
        unsigned mn = 0xFFFFFFFFu;
        #pragma unroll
        for (int i = 0; i < 32; i++)
            if (key[i] >= T2) mn = min(mn, key[i]);
        T2 = __reduce_min_sync(0xffffffffu, mn);
    }
    return make_uint2(T1, T2);
}

__global__ void select_kernel(const float* __restrict__ kr1, const float* __restrict__ kr2)
{
    int row  = blockIdx.x * 8 + (threadIdx.x >> 5);   // z*1024 + n
    int lane = threadIdx.x & 31;

    float r1 = kr1[0], r2 = kr2[0];
    int k1 = (int)(1024.f * (1.f/(1.f+expf(-r1)))); k1 = min(max(k1,1),1024);
    int k2 = (int)(1024.f * (1.f/(1.f+expf(-r2)))); k2 = min(max(k2,1),1024);

    const __half* rp = g_attnh + (size_t)row * Nn;
    unsigned key[32];
    #pragma unroll
    for (int i = 0; i < 4; i++) {
        uint4 v = *(const uint4*)(rp + i*256 + lane*8);
        const unsigned short* hh = (const unsigned short*)&v;
        #pragma unroll
        for (int j = 0; j < 8; j++) {
            unsigned b = hh[j];
            key[i*8 + j] = (b & 0x8000u) ? ((~b) & 0xFFFFu) : (b | 0x8000u);
        }
    }

    unsigned mx = 0;
    #pragma unroll
    for (int i = 0; i < 32; i++) mx = max(mx, key[i]);
    mx = __reduce_max_sync(0xffffffffu, mx);
    float M = key2h(mx);

    uint2 T = kth2_key16(key, k1, k2, mx);
    unsigned T1 = T.x, T2 = T.y;

    float ev[32];
    float s1 = 0.f, s2 = 0.f;
    #pragma unroll
    for (int i = 0; i < 32; i++) {
        ev[i] = __expf(key2h(key[i]) - M);
        if (key[i] >= T1) s1 += ev[i];
        if (key[i] >= T2) s2 += ev[i];
    }
    #pragma unroll
    for (int o = 16; o; o >>= 1) {
        s1 += __shfl_xor_sync(0xffffffffu, s1, o);
        s2 += __shfl_xor_sync(0xffffffffu, s2, o);
    }
    float c1 = 0.6f / s1, c2 = 0.4f / s2;
    __nv_bfloat16* ch = g_chi + (size_t)row * Nn;
    #pragma unroll
    for (int i = 0; i < 4; i++) {
        __nv_bfloat16 ob[8];
        #pragma unroll
        for (int j = 0; j < 8; j++) {
            int e = i*8 + j;
            float w = (key[e] >= T1 ? c1 : 0.f) + (key[e] >= T2 ? c2 : 0.f);
            ob[j] = __float2bfloat16(ev[e] * w);
        }
        *(uint4*)(ch + i*256 + lane*8) = *(const uint4*)ob;
    }
}

// ------- kernel 7: AV via mma.sync bf16, double-buffered, bf16 output --------
#define AV_SMEM (2*(192*PADB))
__global__ void __launch_bounds__(256, 2) av_mma_kernel()
{
    extern __shared__ __align__(16) char sm[];
    uint32_t sb = smem_u32(sm);

    int t = threadIdx.x, warp = t >> 5, lane = t & 31;
    int n0 = blockIdx.x * 128, z = blockIdx.y;
    int b = z >> 3, h = z & 7;
    int wn = warp >> 1, wd = warp & 1;

    const char* ch = (const char*)(g_chi  + ((size_t)z*Nn + n0)*Nn);
    const char* vh = (const char*)(g_vthi + (size_t)z*64*1024);

    auto issue = [&](int m0, int bi) {
        uint32_t base = sb + bi*(192*PADB);
        for (int i = t; i < 1024; i += 256) {
            int row = i >> 3, cb = (i & 7) * 16;
            CP_ASYNC16(base + row*PADB + cb, ch + (size_t)row*2048 + m0*2 + cb);
        }
        for (int i = t; i < 512; i += 256) {
            int row = i >> 3, cb = (i & 7) * 16;
            CP_ASYNC16(base + 128*PADB + row*PADB + cb, vh + (size_t)row*2048 + m0*2 + cb);
        }
        CP_COMMIT();
    };
    issue(0, 0);

    float acc[2][4][4] = {};
    int lr16 = lane & 15, lh = lane >> 4;
    int l8 = lane & 7,  lq = (lane & 15) >> 3;

    for (int c16 = 0; c16 < 16; c16++) {
        if (c16 < 15) { issue((c16+1)*64, (c16+1)&1); CP_WAIT(1); }
        else          { CP_WAIT(0); }
        __syncthreads();
        uint32_t base = sb + (c16&1)*(192*PADB);
        uint32_t aAddr = base + (wn*32 + lr16)*PADB + lh*16;
        uint32_t bAddr = base + 128*PADB + (wd*32 + l8)*PADB + lq*16;
        #pragma unroll
        for (int k0 = 0; k0 < 64; k0 += 16) {
            uint32_t a[2][4], bb[4][2];
            #pragma unroll
            for (int mi = 0; mi < 2; mi++)
                ldsm_x4(a[mi][0], a[mi][1], a[mi][2], a[mi][3],
                        aAddr + mi*16*PADB + k0*2);
            #pragma unroll
            for (int ni = 0; ni < 4; ni++)
                ldsm_x2(bb[ni][0], bb[ni][1], bAddr + ni*8*PADB + k0*2);
            #pragma unroll
            for (int mi = 0; mi < 2; mi++)
                #pragma unroll
                for (int ni = 0; ni < 4; ni++)
                    mma_bf16(acc[mi][ni], a[mi], bb[ni]);
        }
        __syncthreads();
    }

    int rbase = n0 + wn*32 + (lane >> 2);
    int cbase = h*64 + wd*32 + (lane & 3)*2;
    #pragma unroll
    for (int mi = 0; mi < 2; mi++)
        #pragma unroll
        for (int ni = 0; ni < 4; ni++) {
            float* c = acc[mi][ni];
            size_t o0 = ((size_t)(b*Nn) + rbase + mi*16)*Cc + cbase + ni*8;
            __nv_bfloat162 p0, p1;
            p0.x = __float2bfloat16(c[0]); p0.y = __float2bfloat16(c[1]);
            p1.x = __float2bfloat16(c[2]); p1.y = __float2bfloat16(c[3]);
            *(__nv_bfloat162*)&g_obf[o0]        = p0;
            *(__nv_bfloat162*)&g_obf[o0 + 8*Cc] = p1;
        }
}

// ------- kernel 8: proj via mma; out[b,c,n] = W.o + bias + x ------------------
#define PJ_SMEM (4*128*PADB)
__global__ void __launch_bounds__(256, 2)
proj_mma_kernel(const float* __restrict__ bias, const float* __restrict__ x,
                float* __restrict__ OUT)
{
    extern __shared__ __align__(16) char sm[];
    uint32_t sb = smem_u32(sm);

    int t = threadIdx.x, warp = t >> 5, lane = t & 31;
    int c0 = blockIdx.x * 128, n0 = blockIdx.y * 128, b = blockIdx.z;
    int wc = warp >> 2, wnn = warp & 3;

    const char* wsrc = (const char*)(g_pwb + (size_t)c0*Cc);
    const char* osrc = (const char*)(g_obf + ((size_t)(b*Nn + n0))*Cc);

    auto issue = [&](int kc, int bi) {
        uint32_t base = sb + bi*(2*128*PADB);
        for (int i = t; i < 1024; i += 256) {
            int row = i >> 3, cb = (i & 7) * 16;
            CP_ASYNC16(base + row*PADB + cb, wsrc + (size_t)row*1024 + kc*2 + cb);
            CP_ASYNC16(base + 128*PADB + row*PADB + cb, osrc + (size_t)row*1024 + kc*2 + cb);
        }
        CP_COMMIT();
    };
    issue(0, 0);

    float acc[4][4][4] = {};
    int lr16 = lane & 15, lh = lane >> 4;
    int l8 = lane & 7,  lq = (lane & 15) >> 3;

    for (int c8 = 0; c8 < 8; c8++) {
        if (c8 < 7) { issue((c8+1)*64, (c8+1)&1); CP_WAIT(1); }
        else        { CP_WAIT(0); }
        __syncthreads();
        uint32_t base = sb + (c8&1)*(2*128*PADB);
        uint32_t aAddr = base + (wc*64 + lr16)*PADB + lh*16;
        uint32_t bAddr = base + 128*PADB + (wnn*32 + l8)*PADB + lq*16;
        #pragma unroll
        for (int k0 = 0; k0 < 64; k0 += 16) {
            uint32_t a[4][4], bb[4][2];
            #pragma unroll
            for (int mi = 0; mi < 4; mi++)
                ldsm_x4(a[mi][0], a[mi][1], a[mi][2], a[mi][3],
                        aAddr + mi*16*PADB + k0*2);
            #pragma unroll
            for (int ni = 0; ni < 4; ni++)
                ldsm_x2(bb[ni][0], bb[ni][1], bAddr + ni*8*PADB + k0*2);
            #pragma unroll
            for (int mi = 0; mi < 4; mi++)
                #pragma unroll
                for (int ni = 0; ni < 4; ni++)
                    mma_bf16(acc[mi][ni], a[mi], bb[ni]);
        }
        __syncthreads();
    }

    int cb0 = c0 + wc*64 + (lane >> 2);
    int nb0 = n0 + wnn*32 + (lane & 3)*2;
    #pragma unroll
    for (int mi = 0; mi < 4; mi++) {
        int c = cb0 + mi*16;
        float bs0 = bias[c], bs8 = bias[c + 8];
        #pragma unroll
        for (int ni = 0; ni < 4; ni++) {
            float* a = acc[mi][ni];
            int n = nb0 + ni*8;
            size_t i0 = ((size_t)b*Cc + c)*Nn + n;
            float2 x0 = *(const float2*)&x[i0];
            *(float2*)&OUT[i0] = make_float2(a[0] + bs0 + x0.x, a[1] + bs0 + x0.y);
            size_t i8 = i0 + (size_t)8*Nn;
            float2 x8 = *(const float2*)&x[i8];
            *(float2*)&OUT[i8] = make_float2(a[2] + bs8 + x8.x, a[3] + bs8 + x8.y);
        }
    }
}

// -----------------------------------------------------------------------------
extern "C" void kernel_launch(void* const* d_in, const int* in_sizes, int n_in,
                              void* d_out, int out_size)
{
    const float* x       = (const float*)d_in[0];
    const float* y       = (const float*)d_in[1];
    const float* q_w     = (const float*)d_in[2];
    const float* kv_w    = (const float*)d_in[3];
    const float* proj_w  = (const float*)d_in[4];
    const float* proj_b  = (const float*)d_in[5];
    const float* conv1_w = (const float*)d_in[6];
    const float* conv1_b = (const float*)d_in[7];
    const float* conv2_w = (const float*)d_in[8];
    const float* conv2_b = (const float*)d_in[9];
    const float* conv3_w = (const float*)d_in[10];
    const float* conv3_b = (const float*)d_in[11];
    const float* ln_w    = (const float*)d_in[12];
    const float* ln_b    = (const float*)d_in[13];
    const float* kr1     = (const float*)d_in[14];
    const float* kr2     = (const float*)d_in[15];
    float* out = (float*)d_out;

    __nv_bfloat16 *xbf, *ynbf, *qwb, *kvwb, *qbf, *kbf, *vbf;
    cudaGetSymbolAddress((void**)&xbf,  g_xbf);
    cudaGetSymbolAddress((void**)&ynbf, g_ynbf);
    cudaGetSymbolAddress((void**)&qwb,  g_qwb);
    cudaGetSymbolAddress((void**)&kvwb, g_kvwb);
    cudaGetSymbolAddress((void**)&qbf,  g_qbf);
    cudaGetSymbolAddress((void**)&kbf,  g_kbf);
    cudaGetSymbolAddress((void**)&vbf,  g_vbf);

    cudaFuncSetAttribute(gemm_mma_kernel, cudaFuncAttributeMaxDynamicSharedMemorySize, GM_SMEM);
    cudaFuncSetAttribute(qk_mma_kernel,   cudaFuncAttributeMaxDynamicSharedMemorySize, QK_SMEM);
    cudaFuncSetAttribute(av_mma_kernel,   cudaFuncAttributeMaxDynamicSharedMemorySize, AV_SMEM);
    cudaFuncSetAttribute(proj_mma_kernel, cudaFuncAttributeMaxDynamicSharedMemorySize, PJ_SMEM);

    // K1: conv | weight-cvt | x transpose-cvt (all independent)
    k1_kernel<<<4096 + 1024 + 4096, 256, K1_SMEM>>>(
        y, conv1_w, conv1_b, conv2_w, conv2_b, conv3_w, conv3_b,
        x, q_w, kv_w, proj_w);

    ln_kernel<<<Bz*32, 256>>>(ln_w, ln_b);

    gemm_mma_kernel<<<dim3(4, 8, Bz), 256, GM_SMEM>>>(xbf, qwb, qbf, qbf);

    tcvt_yn_kernel<<<4096, 256, K1_SMEM>>>();

    gemm_mma_kernel<<<dim3(8, 8, Bz), 256, GM_SMEM>>>(ynbf, kvwb, kbf, vbf);

    vt_kernel<<<4096, 256>>>();

    qk_mma_kernel<<<dim3(8, 64), 256, QK_SMEM>>>();

    select_kernel<<<Bz*8*Nn/8, 256>>>(kr1, kr2);
    av_mma_kernel<<<dim3(Nn/128, Bz*8), 256, AV_SMEM>>>();
    proj_mma_kernel<<<dim3(Cc/128, Nn/128, Bz), 256, PJ_SMEM>>>(proj_b, x, out);
}

// round 15
// speedup vs baseline: 1.7940x; 1.2022x over previous
#include <cuda_runtime.h>
#include <cuda_bf16.h>
#include <cuda_fp16.h>
#include <cstdint>

#define Bz 8
#define Cc 512
#define Nn 1024

// ---------------- device scratch (no allocations allowed) --------------------
__device__ float g_yf[Bz*Cc*Nn];               // conv output [B,C,N]
__device__ float g_yn[Bz*Cc*Nn];               // layernorm output [B,C,N]
__device__ __half g_attnh[(size_t)64*1024*1024]; // attn [64 z][1024 n][1024 m] fp16
// bf16 operand buffers
__device__ __nv_bfloat16 g_xbf [Bz*Nn*Cc];     // x^T  [b,n,512]
__device__ __nv_bfloat16 g_ynbf[Bz*Nn*Cc];     // yn^T [b,n,512]
__device__ __nv_bfloat16 g_qwb [Cc*Cc];        // 0.125*q_w  [co,512]
__device__ __nv_bfloat16 g_kvwb[2*Cc*Cc];      // kv_w [co,512]
__device__ __nv_bfloat16 g_pwb [Cc*Cc];        // proj_w [co,512]
__device__ __nv_bfloat16 g_qbf [Bz*Nn*Cc];     // q  [b,n,512]
__device__ __nv_bfloat16 g_kbf [Bz*Nn*Cc];     // k  [b,n,512]
__device__ __nv_bfloat16 g_vbf [Bz*Nn*Cc];     // v  [b,n,512]
__device__ __nv_bfloat16 g_obf [Bz*Nn*Cc];     // attn out [b,n,512]
__device__ __nv_bfloat16 g_vthi[(size_t)64*64*1024];   // v^T [z,d,m]
__device__ __nv_bfloat16 g_chi [(size_t)64*1024*1024]; // coeff [z,n,m]

// =================== warp-MMA helpers (plain sm_103-safe PTX) ================
__device__ __forceinline__ uint32_t smem_u32(const void* p) {
    uint32_t a;
    asm("{ .reg .u64 t; cvta.to.shared.u64 t, %1; cvt.u32.u64 %0, t; }"
        : "=r"(a) : "l"(p));
    return a;
}
__device__ __forceinline__ void ldsm_x4(uint32_t& r0, uint32_t& r1, uint32_t& r2,
                                        uint32_t& r3, uint32_t addr) {
    asm volatile("ldmatrix.sync.aligned.m8n8.x4.shared.b16 {%0,%1,%2,%3}, [%4];"
                 : "=r"(r0), "=r"(r1), "=r"(r2), "=r"(r3) : "r"(addr));
}
__device__ __forceinline__ void ldsm_x2(uint32_t& r0, uint32_t& r1, uint32_t addr) {
    asm volatile("ldmatrix.sync.aligned.m8n8.x2.shared.b16 {%0,%1}, [%2];"
                 : "=r"(r0), "=r"(r1) : "r"(addr));
}
__device__ __forceinline__ void mma_bf16(float* c, const uint32_t* a, const uint32_t* b) {
    asm volatile("mma.sync.aligned.m16n8k16.row.col.f32.bf16.bf16.f32 "
                 "{%0,%1,%2,%3}, {%4,%5,%6,%7}, {%8,%9}, {%0,%1,%2,%3};"
                 : "+f"(c[0]), "+f"(c[1]), "+f"(c[2]), "+f"(c[3])
                 : "r"(a[0]), "r"(a[1]), "r"(a[2]), "r"(a[3]), "r"(b[0]), "r"(b[1]));
}
#define CP_ASYNC16(dst, src) \
    asm volatile("cp.async.cg.shared.global [%0], [%1], 16;" :: "r"(dst), "l"(src))
#define CP_COMMIT() asm volatile("cp.async.commit_group;" ::: "memory")
#define CP_WAIT(n)  asm volatile("cp.async.wait_group %0;" :: "n"(n) : "memory")
#define PADB 144   // padded row stride (72 bf16): conflict-free ldmatrix, 16B-mult

// ================= K1: fused conv | weight-convert | x transpose =============
#define K1_SMEM (38*40*4 + 64*4)

__device__ void conv_body(int bc, int t,
                          const float* __restrict__ y,
                          const float* __restrict__ w3, const float* __restrict__ b3,
                          const float* __restrict__ w5, const float* __restrict__ b5,
                          const float* __restrict__ w7, const float* __restrict__ b7)
{
    extern __shared__ __align__(16) char k1sm[];
    float* tile  = (float*)k1sm;            // [38][40]
    float* wsum  = tile + 38*40;            // [49]
    float* biasp = wsum + 49;

    int c = bc & (Cc-1);
    if (t < 49) {
        int dy = t / 7, dx = t % 7;
        float w = w7[c*49 + t];
        if (dy >= 1 && dy <= 5 && dx >= 1 && dx <= 5) w += w5[c*25 + (dy-1)*5 + (dx-1)];
        if (dy >= 2 && dy <= 4 && dx >= 2 && dx <= 4) w += w3[c*9  + (dy-2)*3 + (dx-2)];
        wsum[t] = w;
    }
    if (t == 64) *biasp = b3[c] + b5[c] + b7[c];

    const float* yp = y + (size_t)bc * Nn;
    for (int i = t; i < 38*38; i += 256) {
        int rr = i / 38, cc = i % 38;
        int r = rr - 3, cl = cc - 3;
        float v = 0.f;
        if (r >= 0 && r < 32 && cl >= 0 && cl < 32) v = yp[r*32 + cl];
        tile[rr*40 + cc] = v;
    }
    __syncthreads();

    int r  = t >> 3;
    int cq = (t & 7) * 4;
    float bias = *biasp;
    float a0 = bias, a1 = bias, a2 = bias, a3 = bias;
    #pragma unroll
    for (int dy = 0; dy < 7; dy++) {
        float rv[12];
        const float* rp = &tile[(r+dy)*40 + cq];
        *(float4*)&rv[0] = *(const float4*)rp;
        *(float4*)&rv[4] = *(const float4*)(rp + 4);
        *(float4*)&rv[8] = *(const float4*)(rp + 8);
        #pragma unroll
        for (int dx = 0; dx < 7; dx++) {
            float w = wsum[dy*7 + dx];
            a0 += w*rv[dx];   a1 += w*rv[dx+1];
            a2 += w*rv[dx+2]; a3 += w*rv[dx+3];
        }
    }
    *(float4*)&g_yf[(size_t)bc*Nn + r*32 + cq] = make_float4(a0, a1, a2, a3);
}

__device__ void wcvt_body(int b2, int t,
                          const float* __restrict__ q_w,
                          const float* __restrict__ kv_w,
                          const float* __restrict__ proj_w)
{
    const float* S; __nv_bfloat16* D; float scale; int off;
    if (b2 < 256)      { S = q_w;    D = g_qwb;  scale = 0.125f; off = b2; }
    else if (b2 < 768) { S = kv_w;   D = g_kvwb; scale = 1.f;    off = b2 - 256; }
    else               { S = proj_w; D = g_pwb;  scale = 1.f;    off = b2 - 768; }
    int i4 = off * 256 + t;
    float4 v = *(const float4*)&S[(size_t)i4 * 4];
    __nv_bfloat16 o[4] = {__float2bfloat16(v.x*scale), __float2bfloat16(v.y*scale),
                          __float2bfloat16(v.z*scale), __float2bfloat16(v.w*scale)};
    *(uint2*)&D[(size_t)i4 * 4] = *(uint2*)o;
}

__device__ void tcvt_body(int idx, int t, const float* __restrict__ S,
                          __nv_bfloat16* __restrict__ D)
{
    extern __shared__ __align__(16) char k1sm[];
    float* tile = (float*)k1sm;             // [32][33]
    int n0 = (idx & 31) * 32;
    int c0 = ((idx >> 5) & 15) * 32;
    int b  = idx >> 9;
    int tx = t & 31, ty = t >> 5;
    #pragma unroll
    for (int i = ty; i < 32; i += 8)
        tile[i*33 + tx] = S[((size_t)b*Cc + c0 + i)*Nn + n0 + tx];
    __syncthreads();
    #pragma unroll
    for (int i = ty; i < 32; i += 8)
        D[((size_t)b*Nn + n0 + i)*Cc + c0 + tx] = __float2bfloat16(tile[tx*33 + i]);
}

__global__ void __launch_bounds__(256)
k1_kernel(const float* __restrict__ y,
          const float* __restrict__ w3, const float* __restrict__ b3,
          const float* __restrict__ w5, const float* __restrict__ b5,
          const float* __restrict__ w7, const float* __restrict__ b7,
          const float* __restrict__ x,
          const float* __restrict__ q_w, const float* __restrict__ kv_w,
          const float* __restrict__ proj_w)
{
    int blk = blockIdx.x, t = threadIdx.x;
    if (blk < 4096)       conv_body(blk, t, y, w3, b3, w5, b5, w7, b7);
    else if (blk < 5120)  wcvt_body(blk - 4096, t, q_w, kv_w, proj_w);
    else                  tcvt_body(blk - 5120, t, x, g_xbf);
}

// ---------------- standalone yn transpose-convert ----------------------------
__global__ void tcvt_yn_kernel()
{
    extern __shared__ __align__(16) char k1sm[];
    tcvt_body(blockIdx.x, threadIdx.x, g_yn, g_ynbf);
}

// ---------------- kernel 2: layernorm over C per (b,n) -----------------------
__global__ void ln_kernel(const float* __restrict__ lnw, const float* __restrict__ lnb)
{
    int b    = blockIdx.x >> 5;
    int n0   = (blockIdx.x & 31) * 32;
    int lane = threadIdx.x & 31;
    int g    = threadIdx.x >> 5;
    int n    = n0 + lane;

    const float* base = g_yf + (size_t)b*Cc*Nn + n;
    float s = 0.f, s2 = 0.f;
    for (int c = g; c < Cc; c += 8) {
        float v = base[(size_t)c*Nn];
        s += v; s2 += v*v;
    }
    __shared__ float sh[2][8][32];
    sh[0][g][lane] = s; sh[1][g][lane] = s2;
    __syncthreads();
    if (g == 0) {
        float a = 0.f, a2 = 0.f;
        #pragma unroll
        for (int i = 0; i < 8; i++) { a += sh[0][i][lane]; a2 += sh[1][i][lane]; }
        float mu  = a * (1.f/512.f);
        float var = a2 * (1.f/512.f) - mu*mu;
        sh[0][0][lane] = mu;
        sh[1][0][lane] = rsqrtf(var + 1e-5f);
    }
    __syncthreads();
    float mu = sh[0][0][lane], rs = sh[1][0][lane];
    float* ob = g_yn + (size_t)b*Cc*Nn + n;
    for (int c = g; c < Cc; c += 8) {
        float v = base[(size_t)c*Nn];
        ob[(size_t)c*Nn] = (v - mu) * rs * lnw[c] + lnb[c];
    }
}

// ------- kernels 3/4: bf16 mma projection GEMM, double-buffered cp.async -----
#define GM_SMEM (4*128*PADB)
__global__ void __launch_bounds__(256, 2)
gemm_mma_kernel(const __nv_bfloat16* __restrict__ A, const __nv_bfloat16* __restrict__ W,
                __nv_bfloat16* __restrict__ D0, __nv_bfloat16* __restrict__ D1)
{
    extern __shared__ __align__(16) char sm[];
    uint32_t sb = smem_u32(sm);

    int t = threadIdx.x, warp = t >> 5, lane = t & 31;
    int co0 = blockIdx.x * 128, n0 = blockIdx.y * 128, b = blockIdx.z;
    int wn = warp >> 2, wm = warp & 3;

    const char* asrc = (const char*)(A + ((size_t)(b*Nn + n0))*Cc);
    const char* wsrc = (const char*)(W + (size_t)co0*Cc);

    auto issue = [&](int kc, int bi) {
        uint32_t base = sb + bi*(2*128*PADB);
        for (int i = t; i < 1024; i += 256) {
            int row = i >> 3, cb = (i & 7) * 16;
            CP_ASYNC16(base + row*PADB + cb, asrc + (size_t)row*1024 + kc*2 + cb);
            CP_ASYNC16(base + 128*PADB + row*PADB + cb, wsrc + (size_t)row*1024 + kc*2 + cb);
        }
        CP_COMMIT();
    };
    issue(0, 0);

    float acc[4][4][4] = {};
    int lr16 = lane & 15, lh = lane >> 4;
    int l8 = lane & 7,  lq = (lane & 15) >> 3;

    for (int c8 = 0; c8 < 8; c8++) {
        if (c8 < 7) { issue((c8+1)*64, (c8+1)&1); CP_WAIT(1); }
        else        { CP_WAIT(0); }
        __syncthreads();
        uint32_t base = sb + (c8&1)*(2*128*PADB);
        uint32_t aAddr = base + (wn*64 + lr16)*PADB + lh*16;
        uint32_t bAddr = base + 128*PADB + (wm*32 + l8)*PADB + lq*16;
        #pragma unroll
        for (int k0 = 0; k0 < 64; k0 += 16) {
            uint32_t a[4][4], bb[4][2];
            #pragma unroll
            for (int mi = 0; mi < 4; mi++)
                ldsm_x4(a[mi][0], a[mi][1], a[mi][2], a[mi][3],
                        aAddr + mi*16*PADB + k0*2);
            #pragma unroll
            for (int ni = 0; ni < 4; ni++)
                ldsm_x2(bb[ni][0], bb[ni][1], bAddr + ni*8*PADB + k0*2);
            #pragma unroll
            for (int mi = 0; mi < 4; mi++)
                #pragma unroll
                for (int ni = 0; ni < 4; ni++)
                    mma_bf16(acc[mi][ni], a[mi], bb[ni]);
        }
        __syncthreads();
    }

    __nv_bfloat16* D = (co0 < Cc) ? D0 : D1;
    int cadj = (co0 < Cc) ? 0 : Cc;
    int rbase = n0 + wn*64 + (lane >> 2);
    int cbase = co0 - cadj + wm*32 + (lane & 3)*2;
    #pragma unroll
    for (int mi = 0; mi < 4; mi++)
        #pragma unroll
        for (int ni = 0; ni < 4; ni++) {
            float* c = acc[mi][ni];
            size_t r0i = ((size_t)(b*Nn) + rbase + mi*16)*Cc + cbase + ni*8;
            __nv_bfloat162 p0, p1;
            p0.x = __float2bfloat16(c[0]); p0.y = __float2bfloat16(c[1]);
            p1.x = __float2bfloat16(c[2]); p1.y = __float2bfloat16(c[3]);
            *(__nv_bfloat162*)&D[r0i]        = p0;
            *(__nv_bfloat162*)&D[r0i + 8*Cc] = p1;
        }
}

// ---------- v (bf16) -> transposed bf16 [z][d][m], flat grid 4096 -------------
__global__ void __launch_bounds__(256) vt_kernel()
{
    __shared__ __nv_bfloat16 tile[32*33];
    int f = blockIdx.x;
    int d0 = (f & 1) * 32, m0 = ((f >> 1) & 31) * 32, z = f >> 6;
    int b = z >> 3, h = z & 7;
    int t = threadIdx.x, tx = t & 31, ty = t >> 5;
    #pragma unroll
    for (int i = ty; i < 32; i += 8)
        tile[i*33 + tx] = g_vbf[((size_t)(b*Nn + m0 + i))*Cc + h*64 + d0 + tx];
    __syncthreads();
    #pragma unroll
    for (int i = ty; i < 32; i += 8)
        g_vthi[((size_t)z*64 + d0 + i)*1024 + m0 + tx] = tile[tx*33 + i];
}

// ------- kernel 5: QK^T, q resident / k streamed (double-buffered) -----------
#define QK_SMEM (3*128*PADB)
__global__ void __launch_bounds__(256, 2) qk_mma_kernel()
{
    extern __shared__ __align__(16) char sm[];
    uint32_t sb = smem_u32(sm);
    const uint32_t QT = 0, KT = 128*PADB;

    int t = threadIdx.x, warp = t >> 5, lane = t & 31;
    int n0 = blockIdx.x * 128, z = blockIdx.y;
    int b = z >> 3, h = z & 7;
    int wn = warp >> 2, wm = warp & 3;

    const char* qs = (const char*)(g_qbf + ((size_t)(b*Nn + n0)*Cc + h*64));
    const char* ks = (const char*)(g_kbf + ((size_t)(b*Nn)*Cc + h*64));

    for (int i = t; i < 1024; i += 256) {
        int row = i >> 3, cb = (i & 7) * 16;
        CP_ASYNC16(sb + QT + row*PADB + cb, qs + (size_t)row*1024 + cb);
    }
    auto issueK = [&](int m0, int bi) {
        uint32_t base = sb + KT + bi*(128*PADB);
        for (int i = t; i < 1024; i += 256) {
            int row = i >> 3, cb = (i & 7) * 16;
            CP_ASYNC16(base + row*PADB + cb, ks + (size_t)(m0 + row)*1024 + cb);
        }
        CP_COMMIT();
    };
    issueK(0, 0);

    int lr16 = lane & 15, lh = lane >> 4;
    int l8 = lane & 7,  lq = (lane & 15) >> 3;

    for (int c8 = 0; c8 < 8; c8++) {
        if (c8 < 7) { issueK((c8+1)*128, (c8+1)&1); CP_WAIT(1); }
        else        { CP_WAIT(0); }
        __syncthreads();

        float acc[4][4][4] = {};
        uint32_t aAddr = sb + QT + (wn*64 + lr16)*PADB + lh*16;
        uint32_t bAddr = sb + KT + (c8&1)*(128*PADB) + (wm*32 + l8)*PADB + lq*16;
        #pragma unroll
        for (int k0 = 0; k0 < 64; k0 += 16) {
            uint32_t a[4][4], bb[4][2];
            #pragma unroll
            for (int mi = 0; mi < 4; mi++)
                ldsm_x4(a[mi][0], a[mi][1], a[mi][2], a[mi][3],
                        aAddr + mi*16*PADB + k0*2);
            #pragma unroll
            for (int ni = 0; ni < 4; ni++)
                ldsm_x2(bb[ni][0], bb[ni][1], bAddr + ni*8*PADB + k0*2);
            #pragma unroll
            for (int mi = 0; mi < 4; mi++)
                #pragma unroll
                for (int ni = 0; ni < 4; ni++)
                    mma_bf16(acc[mi][ni], a[mi], bb[ni]);
        }

        int rbase = n0 + wn*64 + (lane >> 2);
        int cbase = c8*128 + wm*32 + (lane & 3)*2;
        #pragma unroll
        for (int mi = 0; mi < 4; mi++)
            #pragma unroll
            for (int ni = 0; ni < 4; ni++) {
                float* c = acc[mi][ni];
                __half* A = g_attnh + ((size_t)z*Nn + rbase + mi*16)*Nn + cbase + ni*8;
                *(__half2*)&A[0]            = __floats2half2_rn(c[0], c[1]);
                *(__half2*)&A[(size_t)8*Nn] = __floats2half2_rn(c[2], c[3]);
            }
        __syncthreads();
    }
}

// ------- kernel 6: exact top-k via fp16-domain >=-count bisection ------------
__device__ __forceinline__ __half u2h(unsigned k) {
    unsigned short b = (k & 0x8000u) ? (unsigned short)(k ^ 0x8000u)
                                     : (unsigned short)(~k & 0xFFFFu);
    return __ushort_as_half(b);
}

__global__ void select_kernel(const float* __restrict__ kr1, const float* __restrict__ kr2)
{
    int row  = blockIdx.x * 8 + (threadIdx.x >> 5);   // z*1024 + n
    int lane = threadIdx.x & 31;

    float r1 = kr1[0], r2 = kr2[0];
    int k1 = (int)(1024.f * (1.f/(1.f+expf(-r1)))); k1 = min(max(k1,1),1024);
    int k2 = (int)(1024.f * (1.f/(1.f+expf(-r2)))); k2 = min(max(k2,1),1024);

    const __half* rp = g_attnh + (size_t)row * Nn;
    __half2 kh[16];
    #pragma unroll
    for (int i = 0; i < 4; i++) {
        uint4 v = *(const uint4*)(rp + i*256 + lane*8);
        kh[i*4+0] = *(__half2*)&v.x;
        kh[i*4+1] = *(__half2*)&v.y;
        kh[i*4+2] = *(__half2*)&v.z;
        kh[i*4+3] = *(__half2*)&v.w;
    }

    // row max (fp32 shuffle reduce; exact since values are fp16)
    __half2 mx2 = kh[0];
    #pragma unroll
    for (int i = 1; i < 16; i++) mx2 = __hmax2(mx2, kh[i]);
    float M = fmaxf(__low2float(mx2), __high2float(mx2));
    #pragma unroll
    for (int o = 16; o; o >>= 1)
        M = fmaxf(M, __shfl_xor_sync(0xffffffffu, M, o));
    __half mxh = __float2half(M);   // exact: M is an fp16 value

    // dual bisection on uint16 key bits, counts in fp16 domain
    unsigned T1 = 0, T2 = 0;
    bool d1 = false, d2 = false;
    __half th1 = u2h(0), th2 = u2h(0);
    for (int bit = 15; bit >= 0; --bit) {
        if (d1 && d2) break;
        unsigned bm = 1u << bit;
        __half p1 = u2h(T1 | bm), p2 = u2h(T2 | bm);
        bool a1 = !d1 && __hle(p1, mxh);
        bool a2 = !d2 && __hle(p2, mxh);
        if (!a1 && !a2) continue;
        __half2 t1v = __half2half2(p1), t2v = __half2half2(p2);
        __half2 a1h = __float2half2_rn(0.f), a2h = a1h;
        #pragma unroll
        for (int i = 0; i < 16; i++) {
            a1h = __hadd2(a1h, __hge2(kh[i], t1v));
            a2h = __hadd2(a2h, __hge2(kh[i], t2v));
        }
        int c1 = (int)(__low2float(a1h) + __high2float(a1h));
        int c2 = (int)(__low2float(a2h) + __high2float(a2h));
        unsigned cc = (unsigned)c1 | ((unsigned)c2 << 16);
        cc = __reduce_add_sync(0xffffffffu, cc);
        c1 = (int)(cc & 0xffffu); c2 = (int)(cc >> 16);
        if (a1 && c1 >= k1) { T1 |= bm; th1 = p1; d1 = (c1 == k1); }
        if (a2 && c2 >= k2) { T2 |= bm; th2 = p2; d2 = (c2 == k2); }
    }
    if (!d1) th1 = u2h(T1);
    if (!d2) th2 = u2h(T2);
    if (d1) {   // exact count: threshold = min of survivors
        float mn = 1e30f;
        #pragma unroll
        for (int i = 0; i < 16; i++) {
            __half lo = __low2half(kh[i]), hi = __high2half(kh[i]);
            if (__hge(lo, th1)) mn = fminf(mn, __half2float(lo));
            if (__hge(hi, th1)) mn = fminf(mn, __half2float(hi));
        }
        #pragma unroll
        for (int o = 16; o; o >>= 1)
            mn = fminf(mn, __shfl_xor_sync(0xffffffffu, mn, o));
        th1 = __float2half(mn);
    }
    if (d2) {
        float mn = 1e30f;
        #pragma unroll
        for (int i = 0; i < 16; i++) {
            __half lo = __low2half(kh[i]), hi = __high2half(kh[i]);
            if (__hge(lo, th2)) mn = fminf(mn, __half2float(lo));
            if (__hge(hi, th2)) mn = fminf(mn, __half2float(hi));
        }
        #pragma unroll
        for (int o = 16; o; o >>= 1)
            mn = fminf(mn, __shfl_xor_sync(0xffffffffu, mn, o));
        th2 = __float2half(mn);
    }

    // fused dual softmax -> coeff
    float ev[32];
    float s1 = 0.f, s2 = 0.f;
    #pragma unroll
    for (int i = 0; i < 16; i++) {
        __half lo = __low2half(kh[i]), hi = __high2half(kh[i]);
        float fl = __half2float(lo), fh = __half2float(hi);
        ev[2*i]   = __expf(fl - M);
        ev[2*i+1] = __expf(fh - M);
        if (__hge(lo, th1)) s1 += ev[2*i];
        if (__hge(hi, th1)) s1 += ev[2*i+1];
        if (__hge(lo, th2)) s2 += ev[2*i];
        if (__hge(hi, th2)) s2 += ev[2*i+1];
    }
    #pragma unroll
    for (int o = 16; o; o >>= 1) {
        s1 += __shfl_xor_sync(0xffffffffu, s1, o);
        s2 += __shfl_xor_sync(0xffffffffu, s2, o);
    }
    float c1f = 0.6f / s1, c2f = 0.4f / s2;
    __nv_bfloat16* ch = g_chi + (size_t)row * Nn;
    #pragma unroll
    for (int i = 0; i < 4; i++) {
        __nv_bfloat16 ob[8];
        #pragma unroll
        for (int j = 0; j < 8; j++) {
            int e = i*8 + j;
            __half h = (e & 1) ? __high2half(kh[e >> 1]) : __low2half(kh[e >> 1]);
            float w = (__hge(h, th1) ? c1f : 0.f) + (__hge(h, th2) ? c2f : 0.f);
            ob[j] = __float2bfloat16(ev[e] * w);
        }
        *(uint4*)(ch + i*256 + lane*8) = *(const uint4*)ob;
    }
}

// ------- kernel 7: AV via mma.sync bf16, double-buffered, bf16 output --------
#define AV_SMEM (2*(192*PADB))
__global__ void __launch_bounds__(256, 2) av_mma_kernel()
{
    extern __shared__ __align__(16) char sm[];
    uint32_t sb = smem_u32(sm);

    int t = threadIdx.x, warp = t >> 5, lane = t & 31;
    int n0 = blockIdx.x * 128, z = blockIdx.y;
    int b = z >> 3, h = z & 7;
    int wn = warp >> 1, wd = warp & 1;

    const char* ch = (const char*)(g_chi  + ((size_t)z*Nn + n0)*Nn);
    const char* vh = (const char*)(g_vthi + (size_t)z*64*1024);

    auto issue = [&](int m0, int bi) {
        uint32_t base = sb + bi*(192*PADB);
        for (int i = t; i < 1024; i += 256) {
            int row = i >> 3, cb = (i & 7) * 16;
            CP_ASYNC16(base + row*PADB + cb, ch + (size_t)row*2048 + m0*2 + cb);
        }
        for (int i = t; i < 512; i += 256) {
            int row = i >> 3, cb = (i & 7) * 16;
            CP_ASYNC16(base + 128*PADB + row*PADB + cb, vh + (size_t)row*2048 + m0*2 + cb);
        }
        CP_COMMIT();
    };
    issue(0, 0);

    float acc[2][4][4] = {};
    int lr16 = lane & 15, lh = lane >> 4;
    int l8 = lane & 7,  lq = (lane & 15) >> 3;

    for (int c16 = 0; c16 < 16; c16++) {
        if (c16 < 15) { issue((c16+1)*64, (c16+1)&1); CP_WAIT(1); }
        else          { CP_WAIT(0); }
        __syncthreads();
        uint32_t base = sb + (c16&1)*(192*PADB);
        uint32_t aAddr = base + (wn*32 + lr16)*PADB + lh*16;
        uint32_t bAddr = base + 128*PADB + (wd*32 + l8)*PADB + lq*16;
        #pragma unroll
        for (int k0 = 0; k0 < 64; k0 += 16) {
            uint32_t a[2][4], bb[4][2];
            #pragma unroll
            for (int mi = 0; mi < 2; mi++)
                ldsm_x4(a[mi][0], a[mi][1], a[mi][2], a[mi][3],
                        aAddr + mi*16*PADB + k0*2);
            #pragma unroll
            for (int ni = 0; ni < 4; ni++)
                ldsm_x2(bb[ni][0], bb[ni][1], bAddr + ni*8*PADB + k0*2);
            #pragma unroll
            for (int mi = 0; mi < 2; mi++)
                #pragma unroll
                for (int ni = 0; ni < 4; ni++)
                    mma_bf16(acc[mi][ni], a[mi], bb[ni]);
        }
        __syncthreads();
    }

    int rbase = n0 + wn*32 + (lane >> 2);
    int cbase = h*64 + wd*32 + (lane & 3)*2;
    #pragma unroll
    for (int mi = 0; mi < 2; mi++)
        #pragma unroll
        for (int ni = 0; ni < 4; ni++) {
            float* c = acc[mi][ni];
            size_t o0 = ((size_t)(b*Nn) + rbase + mi*16)*Cc + cbase + ni*8;
            __nv_bfloat162 p0, p1;
            p0.x = __float2bfloat16(c[0]); p0.y = __float2bfloat16(c[1]);
            p1.x = __float2bfloat16(c[2]); p1.y = __float2bfloat16(c[3]);
            *(__nv_bfloat162*)&g_obf[o0]        = p0;
            *(__nv_bfloat162*)&g_obf[o0 + 8*Cc] = p1;
        }
}

// ------- kernel 8: proj via mma; out[b,c,n] = W.o + bias + x ------------------
#define PJ_SMEM (4*128*PADB)
__global__ void __launch_bounds__(256, 2)
proj_mma_kernel(const float* __restrict__ bias, const float* __restrict__ x,
                float* __restrict__ OUT)
{
    extern __shared__ __align__(16) char sm[];
    uint32_t sb = smem_u32(sm);

    int t = threadIdx.x, warp = t >> 5, lane = t & 31;
    int c0 = blockIdx.x * 128, n0 = blockIdx.y * 128, b = blockIdx.z;
    int wc = warp >> 2, wnn = warp & 3;

    const char* wsrc = (const char*)(g_pwb + (size_t)c0*Cc);
    const char* osrc = (const char*)(g_obf + ((size_t)(b*Nn + n0))*Cc);

    auto issue = [&](int kc, int bi) {
        uint32_t base = sb + bi*(2*128*PADB);
        for (int i = t; i < 1024; i += 256) {
            int row = i >> 3, cb = (i & 7) * 16;
            CP_ASYNC16(base + row*PADB + cb, wsrc + (size_t)row*1024 + kc*2 + cb);
            CP_ASYNC16(base + 128*PADB + row*PADB + cb, osrc + (size_t)row*1024 + kc*2 + cb);
        }
        CP_COMMIT();
    };
    issue(0, 0);

    float acc[4][4][4] = {};
    int lr16 = lane & 15, lh = lane >> 4;
    int l8 = lane & 7,  lq = (lane & 15) >> 3;

    for (int c8 = 0; c8 < 8; c8++) {
        if (c8 < 7) { issue((c8+1)*64, (c8+1)&1); CP_WAIT(1); }
        else        { CP_WAIT(0); }
        __syncthreads();
        uint32_t base = sb + (c8&1)*(2*128*PADB);
        uint32_t aAddr = base + (wc*64 + lr16)*PADB + lh*16;
        uint32_t bAddr = base + 128*PADB + (wnn*32 + l8)*PADB + lq*16;
        #pragma unroll
        for (int k0 = 0; k0 < 64; k0 += 16) {
            uint32_t a[4][4], bb[4][2];
            #pragma unroll
            for (int mi = 0; mi < 4; mi++)
                ldsm_x4(a[mi][0], a[mi][1], a[mi][2], a[mi][3],
                        aAddr + mi*16*PADB + k0*2);
            #pragma unroll
            for (int ni = 0; ni < 4; ni++)
                ldsm_x2(bb[ni][0], bb[ni][1], bAddr + ni*8*PADB + k0*2);
            #pragma unroll
            for (int mi = 0; mi < 4; mi++)
                #pragma unroll
                for (int ni = 0; ni < 4; ni++)
                    mma_bf16(acc[mi][ni], a[mi], bb[ni]);
        }
        __syncthreads();
    }

    int cb0 = c0 + wc*64 + (lane >> 2);
    int nb0 = n0 + wnn*32 + (lane & 3)*2;
    #pragma unroll
    for (int mi = 0; mi < 4; mi++) {
        int c = cb0 + mi*16;
        float bs0 = bias[c], bs8 = bias[c + 8];
        #pragma unroll
        for (int ni = 0; ni < 4; ni++) {
            float* a = acc[mi][ni];
            int n = nb0 + ni*8;
            size_t i0 = ((size_t)b*Cc + c)*Nn + n;
            float2 x0 = *(const float2*)&x[i0];
            *(float2*)&OUT[i0] = make_float2(a[0] + bs0 + x0.x, a[1] + bs0 + x0.y);
            size_t i8 = i0 + (size_t)8*Nn;
            float2 x8 = *(const float2*)&x[i8];
            *(float2*)&OUT[i8] = make_float2(a[2] + bs8 + x8.x, a[3] + bs8 + x8.y);
        }
    }
}

// -----------------------------------------------------------------------------
extern "C" void kernel_launch(void* const* d_in, const int* in_sizes, int n_in,
                              void* d_out, int out_size)
{
    const float* x       = (const float*)d_in[0];
    const float* y       = (const float*)d_in[1];
    const float* q_w     = (const float*)d_in[2];
    const float* kv_w    = (const float*)d_in[3];
    const float* proj_w  = (const float*)d_in[4];
    const float* proj_b  = (const float*)d_in[5];
    const float* conv1_w = (const float*)d_in[6];
    const float* conv1_b = (const float*)d_in[7];
    const float* conv2_w = (const float*)d_in[8];
    const float* conv2_b = (const float*)d_in[9];
    const float* conv3_w = (const float*)d_in[10];
    const float* conv3_b = (const float*)d_in[11];
    const float* ln_w    = (const float*)d_in[12];
    const float* ln_b    = (const float*)d_in[13];
    const float* kr1     = (const float*)d_in[14];
    const float* kr2     = (const float*)d_in[15];
    float* out = (float*)d_out;

    __nv_bfloat16 *xbf, *ynbf, *qwb, *kvwb, *qbf, *kbf, *vbf;
    cudaGetSymbolAddress((void**)&xbf,  g_xbf);
    cudaGetSymbolAddress((void**)&ynbf, g_ynbf);
    cudaGetSymbolAddress((void**)&qwb,  g_qwb);
    cudaGetSymbolAddress((void**)&kvwb, g_kvwb);
    cudaGetSymbolAddress((void**)&qbf,  g_qbf);
    cudaGetSymbolAddress((void**)&kbf,  g_kbf);
    cudaGetSymbolAddress((void**)&vbf,  g_vbf);

    cudaFuncSetAttribute(gemm_mma_kernel, cudaFuncAttributeMaxDynamicSharedMemorySize, GM_SMEM);
    cudaFuncSetAttribute(qk_mma_kernel,   cudaFuncAttributeMaxDynamicSharedMemorySize, QK_SMEM);
    cudaFuncSetAttribute(av_mma_kernel,   cudaFuncAttributeMaxDynamicSharedMemorySize, AV_SMEM);
    cudaFuncSetAttribute(proj_mma_kernel, cudaFuncAttributeMaxDynamicSharedMemorySize, PJ_SMEM);

    // K1: conv | weight-cvt | x transpose-cvt (all independent)
    k1_kernel<<<4096 + 1024 + 4096, 256, K1_SMEM>>>(
        y, conv1_w, conv1_b, conv2_w, conv2_b, conv3_w, conv3_b,
        x, q_w, kv_w, proj_w);

    ln_kernel<<<Bz*32, 256>>>(ln_w, ln_b);

    gemm_mma_kernel<<<dim3(4, 8, Bz), 256, GM_SMEM>>>(xbf, qwb, qbf, qbf);

    tcvt_yn_kernel<<<4096, 256, K1_SMEM>>>();

    gemm_mma_kernel<<<dim3(8, 8, Bz), 256, GM_SMEM>>>(ynbf, kvwb, kbf, vbf);

    vt_kernel<<<4096, 256>>>();

    qk_mma_kernel<<<dim3(8, 64), 256, QK_SMEM>>>();

    select_kernel<<<Bz*8*Nn/8, 256>>>(kr1, kr2);
    av_mma_kernel<<<dim3(Nn/128, Bz*8), 256, AV_SMEM>>>();
    proj_mma_kernel<<<dim3(Cc/128, Nn/128, Bz), 256, PJ_SMEM>>>(proj_b, x, out);
}

// round 16
// speedup vs baseline: 1.8282x; 1.0191x over previous
#include <cuda_runtime.h>
#include <cuda_bf16.h>
#include <cuda_fp16.h>
#include <cstdint>

#define Bz 8
#define Cc 512
#define Nn 1024

// ---------------- device scratch (no allocations allowed) --------------------
__device__ float g_yf[Bz*Cc*Nn];               // conv output [B,C,N]
__device__ float g_yn[Bz*Cc*Nn];               // layernorm output [B,C,N]
__device__ __half g_attnh[(size_t)64*1024*1024]; // attn [64 z][1024 n][1024 m] fp16
// bf16 operand buffers
__device__ __nv_bfloat16 g_xbf [Bz*Nn*Cc];     // x^T  [b,n,512]
__device__ __nv_bfloat16 g_ynbf[Bz*Nn*Cc];     // yn^T [b,n,512]
__device__ __nv_bfloat16 g_qwb [Cc*Cc];        // 0.125*q_w  [co,512]
__device__ __nv_bfloat16 g_kvwb[2*Cc*Cc];      // kv_w [co,512]
__device__ __nv_bfloat16 g_pwb [Cc*Cc];        // proj_w [co,512]
__device__ __nv_bfloat16 g_qbf [Bz*Nn*Cc];     // q  [b,n,512]
__device__ __nv_bfloat16 g_kbf [Bz*Nn*Cc];     // k  [b,n,512]
__device__ __nv_bfloat16 g_vbf [Bz*Nn*Cc];     // v  [b,n,512]
__device__ __nv_bfloat16 g_obf [Bz*Nn*Cc];     // attn out [b,n,512]
__device__ __nv_bfloat16 g_vthi[(size_t)64*64*1024];   // v^T [z,d,m]
__device__ __nv_bfloat16 g_chi [(size_t)64*1024*1024]; // coeff [z,n,m]

// =================== warp-MMA helpers (plain sm_103-safe PTX) ================
__device__ __forceinline__ uint32_t smem_u32(const void* p) {
    uint32_t a;
    asm("{ .reg .u64 t; cvta.to.shared.u64 t, %1; cvt.u32.u64 %0, t; }"
        : "=r"(a) : "l"(p));
    return a;
}
__device__ __forceinline__ void ldsm_x4(uint32_t& r0, uint32_t& r1, uint32_t& r2,
                                        uint32_t& r3, uint32_t addr) {
    asm volatile("ldmatrix.sync.aligned.m8n8.x4.shared.b16 {%0,%1,%2,%3}, [%4];"
                 : "=r"(r0), "=r"(r1), "=r"(r2), "=r"(r3) : "r"(addr));
}
__device__ __forceinline__ void ldsm_x2(uint32_t& r0, uint32_t& r1, uint32_t addr) {
    asm volatile("ldmatrix.sync.aligned.m8n8.x2.shared.b16 {%0,%1}, [%2];"
                 : "=r"(r0), "=r"(r1) : "r"(addr));
}
__device__ __forceinline__ void mma_bf16(float* c, const uint32_t* a, const uint32_t* b) {
    asm volatile("mma.sync.aligned.m16n8k16.row.col.f32.bf16.bf16.f32 "
                 "{%0,%1,%2,%3}, {%4,%5,%6,%7}, {%8,%9}, {%0,%1,%2,%3};"
                 : "+f"(c[0]), "+f"(c[1]), "+f"(c[2]), "+f"(c[3])
                 : "r"(a[0]), "r"(a[1]), "r"(a[2]), "r"(a[3]), "r"(b[0]), "r"(b[1]));
}
#define CP_ASYNC16(dst, src) \
    asm volatile("cp.async.cg.shared.global [%0], [%1], 16;" :: "r"(dst), "l"(src))
#define CP_COMMIT() asm volatile("cp.async.commit_group;" ::: "memory")
#define CP_WAIT(n)  asm volatile("cp.async.wait_group %0;" :: "n"(n) : "memory")
#define PADB 144   // padded row stride (72 bf16): conflict-free ldmatrix, 16B-mult

// ================= K1: fused conv | weight-convert | x transpose =============
#define K1_SMEM (38*40*4 + 64*4)

__device__ void conv_body(int bc, int t,
                          const float* __restrict__ y,
                          const float* __restrict__ w3, const float* __restrict__ b3,
                          const float* __restrict__ w5, const float* __restrict__ b5,
                          const float* __restrict__ w7, const float* __restrict__ b7)
{
    extern __shared__ __align__(16) char k1sm[];
    float* tile  = (float*)k1sm;            // [38][40]
    float* wsum  = tile + 38*40;            // [49]
    float* biasp = wsum + 49;

    int c = bc & (Cc-1);
    if (t < 49) {
        int dy = t / 7, dx = t % 7;
        float w = w7[c*49 + t];
        if (dy >= 1 && dy <= 5 && dx >= 1 && dx <= 5) w += w5[c*25 + (dy-1)*5 + (dx-1)];
        if (dy >= 2 && dy <= 4 && dx >= 2 && dx <= 4) w += w3[c*9  + (dy-2)*3 + (dx-2)];
        wsum[t] = w;
    }
    if (t == 64) *biasp = b3[c] + b5[c] + b7[c];

    const float* yp = y + (size_t)bc * Nn;
    for (int i = t; i < 38*38; i += 256) {
        int rr = i / 38, cc = i % 38;
        int r = rr - 3, cl = cc - 3;
        float v = 0.f;
        if (r >= 0 && r < 32 && cl >= 0 && cl < 32) v = yp[r*32 + cl];
        tile[rr*40 + cc] = v;
    }
    __syncthreads();

    int r  = t >> 3;
    int cq = (t & 7) * 4;
    float bias = *biasp;
    float a0 = bias, a1 = bias, a2 = bias, a3 = bias;
    #pragma unroll
    for (int dy = 0; dy < 7; dy++) {
        float rv[12];
        const float* rp = &tile[(r+dy)*40 + cq];
        *(float4*)&rv[0] = *(const float4*)rp;
        *(float4*)&rv[4] = *(const float4*)(rp + 4);
        *(float4*)&rv[8] = *(const float4*)(rp + 8);
        #pragma unroll
        for (int dx = 0; dx < 7; dx++) {
            float w = wsum[dy*7 + dx];
            a0 += w*rv[dx];   a1 += w*rv[dx+1];
            a2 += w*rv[dx+2]; a3 += w*rv[dx+3];
        }
    }
    *(float4*)&g_yf[(size_t)bc*Nn + r*32 + cq] = make_float4(a0, a1, a2, a3);
}

__device__ void wcvt_body(int b2, int t,
                          const float* __restrict__ q_w,
                          const float* __restrict__ kv_w,
                          const float* __restrict__ proj_w)
{
    const float* S; __nv_bfloat16* D; float scale; int off;
    if (b2 < 256)      { S = q_w;    D = g_qwb;  scale = 0.125f; off = b2; }
    else if (b2 < 768) { S = kv_w;   D = g_kvwb; scale = 1.f;    off = b2 - 256; }
    else               { S = proj_w; D = g_pwb;  scale = 1.f;    off = b2 - 768; }
    int i4 = off * 256 + t;
    float4 v = *(const float4*)&S[(size_t)i4 * 4];
    __nv_bfloat16 o[4] = {__float2bfloat16(v.x*scale), __float2bfloat16(v.y*scale),
                          __float2bfloat16(v.z*scale), __float2bfloat16(v.w*scale)};
    *(uint2*)&D[(size_t)i4 * 4] = *(uint2*)o;
}

__device__ void tcvt_body(int idx, int t, const float* __restrict__ S,
                          __nv_bfloat16* __restrict__ D)
{
    extern __shared__ __align__(16) char k1sm[];
    float* tile = (float*)k1sm;             // [32][33]
    int n0 = (idx & 31) * 32;
    int c0 = ((idx >> 5) & 15) * 32;
    int b  = idx >> 9;
    int tx = t & 31, ty = t >> 5;
    #pragma unroll
    for (int i = ty; i < 32; i += 8)
        tile[i*33 + tx] = S[((size_t)b*Cc + c0 + i)*Nn + n0 + tx];
    __syncthreads();
    #pragma unroll
    for (int i = ty; i < 32; i += 8)
        D[((size_t)b*Nn + n0 + i)*Cc + c0 + tx] = __float2bfloat16(tile[tx*33 + i]);
}

__global__ void __launch_bounds__(256)
k1_kernel(const float* __restrict__ y,
          const float* __restrict__ w3, const float* __restrict__ b3,
          const float* __restrict__ w5, const float* __restrict__ b5,
          const float* __restrict__ w7, const float* __restrict__ b7,
          const float* __restrict__ x,
          const float* __restrict__ q_w, const float* __restrict__ kv_w,
          const float* __restrict__ proj_w)
{
    int blk = blockIdx.x, t = threadIdx.x;
    if (blk < 4096)       conv_body(blk, t, y, w3, b3, w5, b5, w7, b7);
    else if (blk < 5120)  wcvt_body(blk - 4096, t, q_w, kv_w, proj_w);
    else                  tcvt_body(blk - 5120, t, x, g_xbf);
}

// ---------------- standalone yn transpose-convert ----------------------------
__global__ void tcvt_yn_kernel()
{
    extern __shared__ __align__(16) char k1sm[];
    tcvt_body(blockIdx.x, threadIdx.x, g_yn, g_ynbf);
}

// ---------------- layernorm body (dynamic smem) -------------------------------
__device__ void ln_body(int blk, int t, const float* __restrict__ lnw,
                        const float* __restrict__ lnb)
{
    extern __shared__ __align__(16) char dsm[];
    float* sh = (float*)dsm;                 // [2][8][32]

    int b    = blk >> 5;
    int n0   = (blk & 31) * 32;
    int lane = t & 31;
    int g    = t >> 5;
    int n    = n0 + lane;

    const float* base = g_yf + (size_t)b*Cc*Nn + n;
    float s = 0.f, s2 = 0.f;
    for (int c = g; c < Cc; c += 8) {
        float v = base[(size_t)c*Nn];
        s += v; s2 += v*v;
    }
    sh[(0*8 + g)*32 + lane] = s;
    sh[(1*8 + g)*32 + lane] = s2;
    __syncthreads();
    if (g == 0) {
        float a = 0.f, a2 = 0.f;
        #pragma unroll
        for (int i = 0; i < 8; i++) {
            a  += sh[(0*8 + i)*32 + lane];
            a2 += sh[(1*8 + i)*32 + lane];
        }
        float mu  = a * (1.f/512.f);
        float var = a2 * (1.f/512.f) - mu*mu;
        sh[0*32 + lane]       = mu;
        sh[(1*8)*32 + lane]   = rsqrtf(var + 1e-5f);
    }
    __syncthreads();
    float mu = sh[0*32 + lane], rs = sh[(1*8)*32 + lane];
    float* ob = g_yn + (size_t)b*Cc*Nn + n;
    for (int c = g; c < Cc; c += 8) {
        float v = base[(size_t)c*Nn];
        ob[(size_t)c*Nn] = (v - mu) * rs * lnw[c] + lnb[c];
    }
}

// ------- bf16 mma projection GEMM body, double-buffered cp.async --------------
#define GM_SMEM (4*128*PADB)
__device__ void gemm_body(int t, int co0, int n0, int b,
                          const __nv_bfloat16* __restrict__ A,
                          const __nv_bfloat16* __restrict__ W,
                          __nv_bfloat16* __restrict__ D0,
                          __nv_bfloat16* __restrict__ D1)
{
    extern __shared__ __align__(16) char sm[];
    uint32_t sb = smem_u32(sm);

    int warp = t >> 5, lane = t & 31;
    int wn = warp >> 2, wm = warp & 3;

    const char* asrc = (const char*)(A + ((size_t)(b*Nn + n0))*Cc);
    const char* wsrc = (const char*)(W + (size_t)co0*Cc);

    auto issue = [&](int kc, int bi) {
        uint32_t base = sb + bi*(2*128*PADB);
        for (int i = t; i < 1024; i += 256) {
            int row = i >> 3, cb = (i & 7) * 16;
            CP_ASYNC16(base + row*PADB + cb, asrc + (size_t)row*1024 + kc*2 + cb);
            CP_ASYNC16(base + 128*PADB + row*PADB + cb, wsrc + (size_t)row*1024 + kc*2 + cb);
        }
        CP_COMMIT();
    };
    issue(0, 0);

    float acc[4][4][4] = {};
    int lr16 = lane & 15, lh = lane >> 4;
    int l8 = lane & 7,  lq = (lane & 15) >> 3;

    for (int c8 = 0; c8 < 8; c8++) {
        if (c8 < 7) { issue((c8+1)*64, (c8+1)&1); CP_WAIT(1); }
        else        { CP_WAIT(0); }
        __syncthreads();
        uint32_t base = sb + (c8&1)*(2*128*PADB);
        uint32_t aAddr = base + (wn*64 + lr16)*PADB + lh*16;
        uint32_t bAddr = base + 128*PADB + (wm*32 + l8)*PADB + lq*16;
        #pragma unroll
        for (int k0 = 0; k0 < 64; k0 += 16) {
            uint32_t a[4][4], bb[4][2];
            #pragma unroll
            for (int mi = 0; mi < 4; mi++)
                ldsm_x4(a[mi][0], a[mi][1], a[mi][2], a[mi][3],
                        aAddr + mi*16*PADB + k0*2);
            #pragma unroll
            for (int ni = 0; ni < 4; ni++)
                ldsm_x2(bb[ni][0], bb[ni][1], bAddr + ni*8*PADB + k0*2);
            #pragma unroll
            for (int mi = 0; mi < 4; mi++)
                #pragma unroll
                for (int ni = 0; ni < 4; ni++)
                    mma_bf16(acc[mi][ni], a[mi], bb[ni]);
        }
        __syncthreads();
    }

    __nv_bfloat16* D = (co0 < Cc) ? D0 : D1;
    int cadj = (co0 < Cc) ? 0 : Cc;
    int rbase = n0 + wn*64 + (lane >> 2);
    int cbase = co0 - cadj + wm*32 + (lane & 3)*2;
    #pragma unroll
    for (int mi = 0; mi < 4; mi++)
        #pragma unroll
        for (int ni = 0; ni < 4; ni++) {
            float* c = acc[mi][ni];
            size_t r0i = ((size_t)(b*Nn) + rbase + mi*16)*Cc + cbase + ni*8;
            __nv_bfloat162 p0, p1;
            p0.x = __float2bfloat16(c[0]); p0.y = __float2bfloat16(c[1]);
            p1.x = __float2bfloat16(c[2]); p1.y = __float2bfloat16(c[3]);
            *(__nv_bfloat162*)&D[r0i]        = p0;
            *(__nv_bfloat162*)&D[r0i + 8*Cc] = p1;
        }
}

// ------- fused launch: gemm-q (blocks 0..255) | layernorm (blocks 256..511) ---
__global__ void __launch_bounds__(256, 2)
lnq_kernel(const float* __restrict__ lnw, const float* __restrict__ lnb)
{
    int blk = blockIdx.x, t = threadIdx.x;
    if (blk < 256) {
        int co0 = (blk & 3) * 128;
        int n0  = ((blk >> 2) & 7) * 128;
        int b   = blk >> 5;
        gemm_body(t, co0, n0, b, g_xbf, g_qwb, g_qbf, g_qbf);
    } else {
        ln_body(blk - 256, t, lnw, lnb);
    }
}

// ------- kv gemm (standard grid) ----------------------------------------------
__global__ void __launch_bounds__(256, 2)
gemm_kv_kernel()
{
    gemm_body(threadIdx.x, blockIdx.x * 128, blockIdx.y * 128, blockIdx.z,
              g_ynbf, g_kvwb, g_kbf, g_vbf);
}

// ---------- v transpose body ---------------------------------------------------
__device__ void vt_body(int f, int t)
{
    extern __shared__ __align__(16) char dsm[];
    __nv_bfloat16* tile = (__nv_bfloat16*)dsm;   // [32][33]
    int d0 = (f & 1) * 32, m0 = ((f >> 1) & 31) * 32, z = f >> 6;
    int b = z >> 3, h = z & 7;
    int tx = t & 31, ty = t >> 5;
    #pragma unroll
    for (int i = ty; i < 32; i += 8)
        tile[i*33 + tx] = g_vbf[((size_t)(b*Nn + m0 + i))*Cc + h*64 + d0 + tx];
    __syncthreads();
    #pragma unroll
    for (int i = ty; i < 32; i += 8)
        g_vthi[((size_t)z*64 + d0 + i)*1024 + m0 + tx] = tile[tx*33 + i];
}

// ------- fused launch: QK^T (blocks 0..511) | v-transpose (512..4607) ---------
#define QK_SMEM (3*128*PADB)
__global__ void __launch_bounds__(256, 2) qkvt_kernel()
{
    int blk = blockIdx.x, t = threadIdx.x;
    if (blk >= 512) { vt_body(blk - 512, t); return; }

    extern __shared__ __align__(16) char sm[];
    uint32_t sb = smem_u32(sm);
    const uint32_t QT = 0, KT = 128*PADB;

    int warp = t >> 5, lane = t & 31;
    int n0 = (blk & 7) * 128, z = blk >> 3;
    int b = z >> 3, h = z & 7;
    int wn = warp >> 2, wm = warp & 3;

    const char* qs = (const char*)(g_qbf + ((size_t)(b*Nn + n0)*Cc + h*64));
    const char* ks = (const char*)(g_kbf + ((size_t)(b*Nn)*Cc + h*64));

    for (int i = t; i < 1024; i += 256) {
        int row = i >> 3, cb = (i & 7) * 16;
        CP_ASYNC16(sb + QT + row*PADB + cb, qs + (size_t)row*1024 + cb);
    }
    auto issueK = [&](int m0, int bi) {
        uint32_t base = sb + KT + bi*(128*PADB);
        for (int i = t; i < 1024; i += 256) {
            int row = i >> 3, cb = (i & 7) * 16;
            CP_ASYNC16(base + row*PADB + cb, ks + (size_t)(m0 + row)*1024 + cb);
        }
        CP_COMMIT();
    };
    issueK(0, 0);

    int lr16 = lane & 15, lh = lane >> 4;
    int l8 = lane & 7,  lq = (lane & 15) >> 3;

    for (int c8 = 0; c8 < 8; c8++) {
        if (c8 < 7) { issueK((c8+1)*128, (c8+1)&1); CP_WAIT(1); }
        else        { CP_WAIT(0); }
        __syncthreads();

        float acc[4][4][4] = {};
        uint32_t aAddr = sb + QT + (wn*64 + lr16)*PADB + lh*16;
        uint32_t bAddr = sb + KT + (c8&1)*(128*PADB) + (wm*32 + l8)*PADB + lq*16;
        #pragma unroll
        for (int k0 = 0; k0 < 64; k0 += 16) {
            uint32_t a[4][4], bb[4][2];
            #pragma unroll
            for (int mi = 0; mi < 4; mi++)
                ldsm_x4(a[mi][0], a[mi][1], a[mi][2], a[mi][3],
                        aAddr + mi*16*PADB + k0*2);
            #pragma unroll
            for (int ni = 0; ni < 4; ni++)
                ldsm_x2(bb[ni][0], bb[ni][1], bAddr + ni*8*PADB + k0*2);
            #pragma unroll
            for (int mi = 0; mi < 4; mi++)
                #pragma unroll
                for (int ni = 0; ni < 4; ni++)
                    mma_bf16(acc[mi][ni], a[mi], bb[ni]);
        }

        int rbase = n0 + wn*64 + (lane >> 2);
        int cbase = c8*128 + wm*32 + (lane & 3)*2;
        #pragma unroll
        for (int mi = 0; mi < 4; mi++)
            #pragma unroll
            for (int ni = 0; ni < 4; ni++) {
                float* c = acc[mi][ni];
                __half* A = g_attnh + ((size_t)z*Nn + rbase + mi*16)*Nn + cbase + ni*8;
                *(__half2*)&A[0]            = __floats2half2_rn(c[0], c[1]);
                *(__half2*)&A[(size_t)8*Nn] = __floats2half2_rn(c[2], c[3]);
            }
        __syncthreads();
    }
}

// ------- kernel 6: exact top-k via fp16-domain >=-count bisection ------------
__device__ __forceinline__ __half u2h(unsigned k) {
    unsigned short b = (k & 0x8000u) ? (unsigned short)(k ^ 0x8000u)
                                     : (unsigned short)(~k & 0xFFFFu);
    return __ushort_as_half(b);
}

__global__ void select_kernel(const float* __restrict__ kr1, const float* __restrict__ kr2)
{
    int row  = blockIdx.x * 8 + (threadIdx.x >> 5);   // z*1024 + n
    int lane = threadIdx.x & 31;

    float r1 = kr1[0], r2 = kr2[0];
    int k1 = (int)(1024.f * (1.f/(1.f+expf(-r1)))); k1 = min(max(k1,1),1024);
    int k2 = (int)(1024.f * (1.f/(1.f+expf(-r2)))); k2 = min(max(k2,1),1024);

    const __half* rp = g_attnh + (size_t)row * Nn;
    __half2 kh[16];
    #pragma unroll
    for (int i = 0; i < 4; i++) {
        uint4 v = *(const uint4*)(rp + i*256 + lane*8);
        kh[i*4+0] = *(__half2*)&v.x;
        kh[i*4+1] = *(__half2*)&v.y;
        kh[i*4+2] = *(__half2*)&v.z;
        kh[i*4+3] = *(__half2*)&v.w;
    }

    __half2 mx2 = kh[0];
    #pragma unroll
    for (int i = 1; i < 16; i++) mx2 = __hmax2(mx2, kh[i]);
    float M = fmaxf(__low2float(mx2), __high2float(mx2));
    #pragma unroll
    for (int o = 16; o; o >>= 1)
        M = fmaxf(M, __shfl_xor_sync(0xffffffffu, M, o));
    __half mxh = __float2half(M);

    unsigned T1 = 0, T2 = 0;
    bool d1 = false, d2 = false;
    __half th1 = u2h(0), th2 = u2h(0);
    for (int bit = 15; bit >= 0; --bit) {
        if (d1 && d2) break;
        unsigned bm = 1u << bit;
        __half p1 = u2h(T1 | bm), p2 = u2h(T2 | bm);
        bool a1 = !d1 && __hle(p1, mxh);
        bool a2 = !d2 && __hle(p2, mxh);
        if (!a1 && !a2) continue;
        __half2 t1v = __half2half2(p1), t2v = __half2half2(p2);
        __half2 a1h = __float2half2_rn(0.f), a2h = a1h;
        #pragma unroll
        for (int i = 0; i < 16; i++) {
            a1h = __hadd2(a1h, __hge2(kh[i], t1v));
            a2h = __hadd2(a2h, __hge2(kh[i], t2v));
        }
        int c1 = (int)(__low2float(a1h) + __high2float(a1h));
        int c2 = (int)(__low2float(a2h) + __high2float(a2h));
        unsigned cc = (unsigned)c1 | ((unsigned)c2 << 16);
        cc = __reduce_add_sync(0xffffffffu, cc);
        c1 = (int)(cc & 0xffffu); c2 = (int)(cc >> 16);
        if (a1 && c1 >= k1) { T1 |= bm; th1 = p1; d1 = (c1 == k1); }
        if (a2 && c2 >= k2) { T2 |= bm; th2 = p2; d2 = (c2 == k2); }
    }
    if (!d1) th1 = u2h(T1);
    if (!d2) th2 = u2h(T2);
    if (d1) {
        float mn = 1e30f;
        #pragma unroll
        for (int i = 0; i < 16; i++) {
            __half lo = __low2half(kh[i]), hi = __high2half(kh[i]);
            if (__hge(lo, th1)) mn = fminf(mn, __half2float(lo));
            if (__hge(hi, th1)) mn = fminf(mn, __half2float(hi));
        }
        #pragma unroll
        for (int o = 16; o; o >>= 1)
            mn = fminf(mn, __shfl_xor_sync(0xffffffffu, mn, o));
        th1 = __float2half(mn);
    }
    if (d2) {
        float mn = 1e30f;
        #pragma unroll
        for (int i = 0; i < 16; i++) {
            __half lo = __low2half(kh[i]), hi = __high2half(kh[i]);
            if (__hge(lo, th2)) mn = fminf(mn, __half2float(lo));
            if (__hge(hi, th2)) mn = fminf(mn, __half2float(hi));
        }
        #pragma unroll
        for (int o = 16; o; o >>= 1)
            mn = fminf(mn, __shfl_xor_sync(0xffffffffu, mn, o));
        th2 = __float2half(mn);
    }

    float ev[32];
    float s1 = 0.f, s2 = 0.f;
    #pragma unroll
    for (int i = 0; i < 16; i++) {
        __half lo = __low2half(kh[i]), hi = __high2half(kh[i]);
        float fl = __half2float(lo), fh = __half2float(hi);
        ev[2*i]   = __expf(fl - M);
        ev[2*i+1] = __expf(fh - M);
        if (__hge(lo, th1)) s1 += ev[2*i];
        if (__hge(hi, th1)) s1 += ev[2*i+1];
        if (__hge(lo, th2)) s2 += ev[2*i];
        if (__hge(hi, th2)) s2 += ev[2*i+1];
    }
    #pragma unroll
    for (int o = 16; o; o >>= 1) {
        s1 += __shfl_xor_sync(0xffffffffu, s1, o);
        s2 += __shfl_xor_sync(0xffffffffu, s2, o);
    }
    float c1f = 0.6f / s1, c2f = 0.4f / s2;
    __nv_bfloat16* ch = g_chi + (size_t)row * Nn;
    #pragma unroll
    for (int i = 0; i < 4; i++) {
        __nv_bfloat16 ob[8];
        #pragma unroll
        for (int j = 0; j < 8; j++) {
            int e = i*8 + j;
            __half h = (e & 1) ? __high2half(kh[e >> 1]) : __low2half(kh[e >> 1]);
            float w = (__hge(h, th1) ? c1f : 0.f) + (__hge(h, th2) ? c2f : 0.f);
            ob[j] = __float2bfloat16(ev[e] * w);
        }
        *(uint4*)(ch + i*256 + lane*8) = *(const uint4*)ob;
    }
}

// ------- kernel 7: AV via mma.sync bf16, double-buffered, bf16 output --------
#define AV_SMEM (2*(192*PADB))
__global__ void __launch_bounds__(256, 2) av_mma_kernel()
{
    extern __shared__ __align__(16) char sm[];
    uint32_t sb = smem_u32(sm);

    int t = threadIdx.x, warp = t >> 5, lane = t & 31;
    int n0 = blockIdx.x * 128, z = blockIdx.y;
    int b = z >> 3, h = z & 7;
    int wn = warp >> 1, wd = warp & 1;

    const char* ch = (const char*)(g_chi  + ((size_t)z*Nn + n0)*Nn);
    const char* vh = (const char*)(g_vthi + (size_t)z*64*1024);

    auto issue = [&](int m0, int bi) {
        uint32_t base = sb + bi*(192*PADB);
        for (int i = t; i < 1024; i += 256) {
            int row = i >> 3, cb = (i & 7) * 16;
            CP_ASYNC16(base + row*PADB + cb, ch + (size_t)row*2048 + m0*2 + cb);
        }
        for (int i = t; i < 512; i += 256) {
            int row = i >> 3, cb = (i & 7) * 16;
            CP_ASYNC16(base + 128*PADB + row*PADB + cb, vh + (size_t)row*2048 + m0*2 + cb);
        }
        CP_COMMIT();
    };
    issue(0, 0);

    float acc[2][4][4] = {};
    int lr16 = lane & 15, lh = lane >> 4;
    int l8 = lane & 7,  lq = (lane & 15) >> 3;

    for (int c16 = 0; c16 < 16; c16++) {
        if (c16 < 15) { issue((c16+1)*64, (c16+1)&1); CP_WAIT(1); }
        else          { CP_WAIT(0); }
        __syncthreads();
        uint32_t base = sb + (c16&1)*(192*PADB);
        uint32_t aAddr = base + (wn*32 + lr16)*PADB + lh*16;
        uint32_t bAddr = base + 128*PADB + (wd*32 + l8)*PADB + lq*16;
        #pragma unroll
        for (int k0 = 0; k0 < 64; k0 += 16) {
            uint32_t a[2][4], bb[4][2];
            #pragma unroll
            for (int mi = 0; mi < 2; mi++)
                ldsm_x4(a[mi][0], a[mi][1], a[mi][2], a[mi][3],
                        aAddr + mi*16*PADB + k0*2);
            #pragma unroll
            for (int ni = 0; ni < 4; ni++)
                ldsm_x2(bb[ni][0], bb[ni][1], bAddr + ni*8*PADB + k0*2);
            #pragma unroll
            for (int mi = 0; mi < 2; mi++)
                #pragma unroll
                for (int ni = 0; ni < 4; ni++)
                    mma_bf16(acc[mi][ni], a[mi], bb[ni]);
        }
        __syncthreads();
    }

    int rbase = n0 + wn*32 + (lane >> 2);
    int cbase = h*64 + wd*32 + (lane & 3)*2;
    #pragma unroll
    for (int mi = 0; mi < 2; mi++)
        #pragma unroll
        for (int ni = 0; ni < 4; ni++) {
            float* c = acc[mi][ni];
            size_t o0 = ((size_t)(b*Nn) + rbase + mi*16)*Cc + cbase + ni*8;
            __nv_bfloat162 p0, p1;
            p0.x = __float2bfloat16(c[0]); p0.y = __float2bfloat16(c[1]);
            p1.x = __float2bfloat16(c[2]); p1.y = __float2bfloat16(c[3]);
            *(__nv_bfloat162*)&g_obf[o0]        = p0;
            *(__nv_bfloat162*)&g_obf[o0 + 8*Cc] = p1;
        }
}

// ------- kernel 8: proj via mma; out[b,c,n] = W.o + bias + x ------------------
#define PJ_SMEM (4*128*PADB)
__global__ void __launch_bounds__(256, 2)
proj_mma_kernel(const float* __restrict__ bias, const float* __restrict__ x,
                float* __restrict__ OUT)
{
    extern __shared__ __align__(16) char sm[];
    uint32_t sb = smem_u32(sm);

    int t = threadIdx.x, warp = t >> 5, lane = t & 31;
    int c0 = blockIdx.x * 128, n0 = blockIdx.y * 128, b = blockIdx.z;
    int wc = warp >> 2, wnn = warp & 3;

    const char* wsrc = (const char*)(g_pwb + (size_t)c0*Cc);
    const char* osrc = (const char*)(g_obf + ((size_t)(b*Nn + n0))*Cc);

    auto issue = [&](int kc, int bi) {
        uint32_t base = sb + bi*(2*128*PADB);
        for (int i = t; i < 1024; i += 256) {
            int row = i >> 3, cb = (i & 7) * 16;
            CP_ASYNC16(base + row*PADB + cb, wsrc + (size_t)row*1024 + kc*2 + cb);
            CP_ASYNC16(base + 128*PADB + row*PADB + cb, osrc + (size_t)row*1024 + kc*2 + cb);
        }
        CP_COMMIT();
    };
    issue(0, 0);

    float acc[4][4][4] = {};
    int lr16 = lane & 15, lh = lane >> 4;
    int l8 = lane & 7,  lq = (lane & 15) >> 3;

    for (int c8 = 0; c8 < 8; c8++) {
        if (c8 < 7) { issue((c8+1)*64, (c8+1)&1); CP_WAIT(1); }
        else        { CP_WAIT(0); }
        __syncthreads();
        uint32_t base = sb + (c8&1)*(2*128*PADB);
        uint32_t aAddr = base + (wc*64 + lr16)*PADB + lh*16;
        uint32_t bAddr = base + 128*PADB + (wnn*32 + l8)*PADB + lq*16;
        #pragma unroll
        for (int k0 = 0; k0 < 64; k0 += 16) {
            uint32_t a[4][4], bb[4][2];
            #pragma unroll
            for (int mi = 0; mi < 4; mi++)
                ldsm_x4(a[mi][0], a[mi][1], a[mi][2], a[mi][3],
                        aAddr + mi*16*PADB + k0*2);
            #pragma unroll
            for (int ni = 0; ni < 4; ni++)
                ldsm_x2(bb[ni][0], bb[ni][1], bAddr + ni*8*PADB + k0*2);
            #pragma unroll
            for (int mi = 0; mi < 4; mi++)
                #pragma unroll
                for (int ni = 0; ni < 4; ni++)
                    mma_bf16(acc[mi][ni], a[mi], bb[ni]);
        }
        __syncthreads();
    }

    int cb0 = c0 + wc*64 + (lane >> 2);
    int nb0 = n0 + wnn*32 + (lane & 3)*2;
    #pragma unroll
    for (int mi = 0; mi < 4; mi++) {
        int c = cb0 + mi*16;
        float bs0 = bias[c], bs8 = bias[c + 8];
        #pragma unroll
        for (int ni = 0; ni < 4; ni++) {
            float* a = acc[mi][ni];
            int n = nb0 + ni*8;
            size_t i0 = ((size_t)b*Cc + c)*Nn + n;
            float2 x0 = *(const float2*)&x[i0];
            *(float2*)&OUT[i0] = make_float2(a[0] + bs0 + x0.x, a[1] + bs0 + x0.y);
            size_t i8 = i0 + (size_t)8*Nn;
            float2 x8 = *(const float2*)&x[i8];
            *(float2*)&OUT[i8] = make_float2(a[2] + bs8 + x8.x, a[3] + bs8 + x8.y);
        }
    }
}

// -----------------------------------------------------------------------------
extern "C" void kernel_launch(void* const* d_in, const int* in_sizes, int n_in,
                              void* d_out, int out_size)
{
    const float* x       = (const float*)d_in[0];
    const float* y       = (const float*)d_in[1];
    const float* q_w     = (const float*)d_in[2];
    const float* kv_w    = (const float*)d_in[3];
    const float* proj_w  = (const float*)d_in[4];
    const float* proj_b  = (const float*)d_in[5];
    const float* conv1_w = (const float*)d_in[6];
    const float* conv1_b = (const float*)d_in[7];
    const float* conv2_w = (const float*)d_in[8];
    const float* conv2_b = (const float*)d_in[9];
    const float* conv3_w = (const float*)d_in[10];
    const float* conv3_b = (const float*)d_in[11];
    const float* ln_w    = (const float*)d_in[12];
    const float* ln_b    = (const float*)d_in[13];
    const float* kr1     = (const float*)d_in[14];
    const float* kr2     = (const float*)d_in[15];
    float* out = (float*)d_out;

    cudaFuncSetAttribute(lnq_kernel,      cudaFuncAttributeMaxDynamicSharedMemorySize, GM_SMEM);
    cudaFuncSetAttribute(gemm_kv_kernel,  cudaFuncAttributeMaxDynamicSharedMemorySize, GM_SMEM);
    cudaFuncSetAttribute(qkvt_kernel,     cudaFuncAttributeMaxDynamicSharedMemorySize, QK_SMEM);
    cudaFuncSetAttribute(av_mma_kernel,   cudaFuncAttributeMaxDynamicSharedMemorySize, AV_SMEM);
    cudaFuncSetAttribute(proj_mma_kernel, cudaFuncAttributeMaxDynamicSharedMemorySize, PJ_SMEM);

    // K1: conv | weight-cvt | x transpose-cvt (all independent)
    k1_kernel<<<4096 + 1024 + 4096, 256, K1_SMEM>>>(
        y, conv1_w, conv1_b, conv2_w, conv2_b, conv3_w, conv3_b,
        x, q_w, kv_w, proj_w);

    // gemm-q | layernorm (independent, fused launch)
    lnq_kernel<<<512, 256, GM_SMEM>>>(ln_w, ln_b);

    tcvt_yn_kernel<<<4096, 256, K1_SMEM>>>();

    gemm_kv_kernel<<<dim3(8, 8, Bz), 256, GM_SMEM>>>();

    // QK^T | v-transpose (independent, fused launch)
    qkvt_kernel<<<512 + 4096, 256, QK_SMEM>>>();

    select_kernel<<<Bz*8*Nn/8, 256>>>(kr1, kr2);
    av_mma_kernel<<<dim3(Nn/128, Bz*8), 256, AV_SMEM>>>();
    proj_mma_kernel<<<dim3(Cc/128, Nn/128, Bz), 256, PJ_SMEM>>>(proj_b, x, out);
}